// round 1
// baseline (speedup 1.0000x reference)
#include <cuda_runtime.h>

// Problem dims (fixed by setup_inputs)
#define BATCH 8
#define NPTS  8192
#define SPTS  2048
#define MTOT  65536      // BATCH*NPTS
#define CIN   384
#define C0    256
#define C1    128

// Scratch (static __device__ arrays per harness rules). Column-major [C][M].
__device__ float  d_X[(size_t)CIN * MTOT];   // concat(interp, points1)
__device__ float  d_Y[(size_t)C0 * MTOT];    // conv0 raw output
__device__ float  d_Z[(size_t)C1 * MTOT];    // conv1 raw output
__device__ int4   d_idx[MTOT];
__device__ float4 d_wt[MTOT];
__device__ float  d_stats[768];  // [0,256) sum0 [256,512) sq0 [512,640) sum1 [640,768) sq1
__device__ float  d_aff[768];    // [0,256) scale0 [256,512) shift0 [512,640) scale1 [640,768) shift1

// ---------------------------------------------------------------------------
// 1) 3-NN search. One thread per query point; dst points staged in smem as
//    (-2x,-2y,-2z,|p|^2) so key = |dst|^2 - 2*dot via 3 FMA. Top-3 in regs.
// ---------------------------------------------------------------------------
__global__ __launch_bounds__(256)
void knn_kernel(const float* __restrict__ xyz1, const float* __restrict__ xyz2)
{
    __shared__ float4 sp[SPTS];
    const int b = blockIdx.y;
    const int t = threadIdx.x;

    const float* x2 = xyz2 + (size_t)b * 3 * SPTS;
    for (int s = t; s < SPTS; s += 256) {
        float x = x2[s], y = x2[SPTS + s], z = x2[2 * SPTS + s];
        sp[s] = make_float4(-2.f * x, -2.f * y, -2.f * z, x * x + y * y + z * z);
    }
    __syncthreads();

    const int n = blockIdx.x * 256 + t;
    const float* x1 = xyz1 + (size_t)b * 3 * NPTS;
    const float qx = x1[n], qy = x1[NPTS + n], qz = x1[2 * NPTS + n];
    const float sn = qx * qx + qy * qy + qz * qz;

    float k0 = 3.402823466e38f, k1 = 3.402823466e38f, k2 = 3.402823466e38f;
    int i0 = 0, i1 = 0, i2 = 0;

#pragma unroll 4
    for (int s = 0; s < SPTS; ++s) {
        float4 p = sp[s];
        float key = fmaf(p.x, qx, fmaf(p.y, qy, fmaf(p.z, qz, p.w)));
        if (key < k2) {
            if (key < k1) {
                k2 = k1; i2 = i1;
                if (key < k0) { k1 = k0; i1 = i0; k0 = key; i0 = s; }
                else          { k1 = key; i1 = s; }
            } else { k2 = key; i2 = s; }
        }
    }

    const float r0 = 1.f / (k0 + sn + 1e-8f);
    const float r1 = 1.f / (k1 + sn + 1e-8f);
    const float r2 = 1.f / (k2 + sn + 1e-8f);
    const float ws = r0 + r1 + r2;

    const int m = b * NPTS + n;
    d_idx[m] = make_int4(i0, i1, i2, 0);
    d_wt[m]  = make_float4(r0 / ws, r1 / ws, r2 / ws, 0.f);
}

// ---------------------------------------------------------------------------
// 2) Interpolation: block = (4-channel chunk, batch). Stage the 4 channel rows
//    of points2[b] in smem (32 KB) as interleaved float4; gather from smem.
//    points2 is read from HBM exactly once. Writes to d_X are coalesced.
// ---------------------------------------------------------------------------
__global__ __launch_bounds__(256)
void interp_kernel(const float* __restrict__ points2)
{
    __shared__ float4 sp[SPTS];
    const int b  = blockIdx.y;
    const int d0 = blockIdx.x * 4;

    const float* src = points2 + ((size_t)b * C0 + d0) * SPTS;
    for (int s = threadIdx.x; s < SPTS; s += 256) {
        float4 v;
        v.x = src[s];
        v.y = src[SPTS + s];
        v.z = src[2 * SPTS + s];
        v.w = src[3 * SPTS + s];
        sp[s] = v;
    }
    __syncthreads();

    const int mb = b * NPTS;
    for (int n = threadIdx.x; n < NPTS; n += 256) {
        const int m = mb + n;
        const int4  id = d_idx[m];
        const float4 w = d_wt[m];
        const float4 a = sp[id.x];
        const float4 c = sp[id.y];
        const float4 e = sp[id.z];
        d_X[(d0 + 0) * MTOT + m] = fmaf(a.x, w.x, fmaf(c.x, w.y, e.x * w.z));
        d_X[(d0 + 1) * MTOT + m] = fmaf(a.y, w.x, fmaf(c.y, w.y, e.y * w.z));
        d_X[(d0 + 2) * MTOT + m] = fmaf(a.z, w.x, fmaf(c.z, w.y, e.z * w.z));
        d_X[(d0 + 3) * MTOT + m] = fmaf(a.w, w.x, fmaf(c.w, w.y, e.w * w.z));
    }
}

// ---------------------------------------------------------------------------
// 3) Copy points1 into channels [256,384) of d_X. Pure coalesced float4 copy.
// ---------------------------------------------------------------------------
__global__ __launch_bounds__(256)
void copy_p1_kernel(const float* __restrict__ points1)
{
    const int i = blockIdx.x * 256 + threadIdx.x;
    const int base = i * 4;
    const int dd = base >> 16;       // channel 0..127
    const int r  = base & 65535;     // m = b*8192+n
    const int b  = r >> 13;
    const int n  = r & 8191;
    float4 v = *(const float4*)(points1 + ((size_t)b * C1 + dd) * NPTS + n);
    *(float4*)(d_X + (size_t)(C0 + dd) * MTOT + r) = v;
}

// ---------------------------------------------------------------------------
// 4) SGEMM: C[o][m] = sum_k A[k][m] * W[o][k].  A column-major [K][M],
//    W row-major [Nout][K], C column-major [Nout][M].
//    128x128 block tile, BK=16, 256 threads, 8x8 microtile (4+4 split).
//    L2=true fuses BN0 affine + ReLU into the A-tile load.
// ---------------------------------------------------------------------------
template<bool L2>
__global__ __launch_bounds__(256)
void gemm_kernel(const float* __restrict__ W)
{
    constexpr int K = L2 ? C0 : CIN;
    const float* __restrict__ A = L2 ? d_Y : d_X;
    float* __restrict__ Cm      = L2 ? d_Z : d_Y;

    __shared__ float As[16 * 128];
    __shared__ float Bs[16 * 132];

    const int tid = threadIdx.x;
    const int m0 = blockIdx.x * 128;
    const int n0 = blockIdx.y * 128;

    const int ak  = tid >> 5;          // 0..7 (k-slot, +8 for second half)
    const int am  = (tid & 31) << 2;   // 0..124 (m within tile, float4)
    const int bn  = tid >> 2;          // 0..63 (n row, +64 second half)
    const int bk4 = (tid & 3) << 2;    // 0,4,8,12 (k within tile, float4)
    const int tx  = tid & 15;
    const int ry  = tid >> 4;
    const int ca  = ry << 2;           // row frag base (and +64)
    const int cb  = tx << 2;           // col frag base (and +64)

    float acc[8][8];
#pragma unroll
    for (int i = 0; i < 8; i++)
#pragma unroll
        for (int j = 0; j < 8; j++) acc[i][j] = 0.f;

    for (int k0 = 0; k0 < K; k0 += 16) {
#pragma unroll
        for (int h = 0; h < 2; h++) {
            const int k = ak + h * 8;
            float4 a = *(const float4*)(A + (size_t)(k0 + k) * MTOT + m0 + am);
            if (L2) {
                const float sc = d_aff[k0 + k];
                const float sh = d_aff[C0 + k0 + k];
                a.x = fmaxf(fmaf(a.x, sc, sh), 0.f);
                a.y = fmaxf(fmaf(a.y, sc, sh), 0.f);
                a.z = fmaxf(fmaf(a.z, sc, sh), 0.f);
                a.w = fmaxf(fmaf(a.w, sc, sh), 0.f);
            }
            *(float4*)(As + k * 128 + am) = a;
        }
#pragma unroll
        for (int h = 0; h < 2; h++) {
            const int nn = bn + h * 64;
            float4 bv = *(const float4*)(W + (size_t)(n0 + nn) * K + k0 + bk4);
            Bs[(bk4 + 0) * 132 + nn] = bv.x;
            Bs[(bk4 + 1) * 132 + nn] = bv.y;
            Bs[(bk4 + 2) * 132 + nn] = bv.z;
            Bs[(bk4 + 3) * 132 + nn] = bv.w;
        }
        __syncthreads();

#pragma unroll
        for (int kk = 0; kk < 16; kk++) {
            const float4 a0 = *(const float4*)(As + kk * 128 + ca);
            const float4 a1 = *(const float4*)(As + kk * 128 + ca + 64);
            const float4 b0 = *(const float4*)(Bs + kk * 132 + cb);
            const float4 b1 = *(const float4*)(Bs + kk * 132 + cb + 64);
            const float ar[8] = {a0.x, a0.y, a0.z, a0.w, a1.x, a1.y, a1.z, a1.w};
            const float br[8] = {b0.x, b0.y, b0.z, b0.w, b1.x, b1.y, b1.z, b1.w};
#pragma unroll
            for (int i = 0; i < 8; i++)
#pragma unroll
                for (int j = 0; j < 8; j++)
                    acc[i][j] = fmaf(ar[i], br[j], acc[i][j]);
        }
        __syncthreads();
    }

#pragma unroll
    for (int jh = 0; jh < 2; jh++) {
#pragma unroll
        for (int j = 0; j < 4; j++) {
            const int col = n0 + cb + jh * 64 + j;
            float* cp = Cm + (size_t)col * MTOT + m0;
            float4 v;
            v.x = acc[0][jh * 4 + j]; v.y = acc[1][jh * 4 + j];
            v.z = acc[2][jh * 4 + j]; v.w = acc[3][jh * 4 + j];
            *(float4*)(cp + ca) = v;
            v.x = acc[4][jh * 4 + j]; v.y = acc[5][jh * 4 + j];
            v.z = acc[6][jh * 4 + j]; v.w = acc[7][jh * 4 + j];
            *(float4*)(cp + ca + 64) = v;
        }
    }
}

// ---------------------------------------------------------------------------
// 5) Per-channel sum / sumsq. Column-major data => fully coalesced, no atomics.
// ---------------------------------------------------------------------------
template<int LAYER>
__global__ __launch_bounds__(256)
void stats_kernel()
{
    const float* src = LAYER ? d_Z : d_Y;
    const int c = blockIdx.x;
    const float4* p = (const float4*)(src + (size_t)c * MTOT);
    float s = 0.f, q = 0.f;
    for (int i = threadIdx.x; i < MTOT / 4; i += 256) {
        const float4 v = p[i];
        s += v.x + v.y + v.z + v.w;
        q += v.x * v.x + v.y * v.y + v.z * v.z + v.w * v.w;
    }
    __shared__ float rs[256], rq[256];
    rs[threadIdx.x] = s; rq[threadIdx.x] = q;
    __syncthreads();
    for (int off = 128; off > 0; off >>= 1) {
        if (threadIdx.x < off) {
            rs[threadIdx.x] += rs[threadIdx.x + off];
            rq[threadIdx.x] += rq[threadIdx.x + off];
        }
        __syncthreads();
    }
    if (threadIdx.x == 0) {
        const int o  = LAYER ? 512 : 0;
        const int cc = LAYER ? C1 : C0;
        d_stats[o + c]      = rs[0];
        d_stats[o + cc + c] = rq[0];
    }
}

// ---------------------------------------------------------------------------
// 6) Fold mean/var + gamma/beta into per-channel (scale, shift).
//    Note: conv biases b0/b1 cancel under training-mode BN and are skipped.
// ---------------------------------------------------------------------------
template<int LAYER>
__global__ void finalize_kernel(const float* __restrict__ g, const float* __restrict__ be)
{
    const int c  = threadIdx.x;
    const int o  = LAYER ? 512 : 0;
    const int cc = LAYER ? C1 : C0;
    const float mean = d_stats[o + c] * (1.f / MTOT);
    const float var  = d_stats[o + cc + c] * (1.f / MTOT) - mean * mean;
    const float sc   = g[c] * rsqrtf(var + 1e-5f);
    d_aff[o + c]      = sc;
    d_aff[o + cc + c] = be[c] - mean * sc;
}

// ---------------------------------------------------------------------------
// 7) BN1 affine + ReLU + write output [B,128,N]. Both sides n-contiguous.
// ---------------------------------------------------------------------------
__global__ __launch_bounds__(256)
void output_kernel(float* __restrict__ out)
{
    const int i = blockIdx.x * 256 + threadIdx.x;
    const int base = i * 4;
    const int o = base >> 16;
    const int m = base & 65535;
    const int b = m >> 13;
    const int n = m & 8191;
    float4 v = *(const float4*)(d_Z + (size_t)o * MTOT + m);
    const float sc = d_aff[512 + o];
    const float sh = d_aff[640 + o];
    v.x = fmaxf(fmaf(v.x, sc, sh), 0.f);
    v.y = fmaxf(fmaf(v.y, sc, sh), 0.f);
    v.z = fmaxf(fmaf(v.z, sc, sh), 0.f);
    v.w = fmaxf(fmaf(v.w, sc, sh), 0.f);
    *(float4*)(out + ((size_t)b * C1 + o) * NPTS + n) = v;
}

// ---------------------------------------------------------------------------
extern "C" void kernel_launch(void* const* d_in, const int* in_sizes, int n_in,
                              void* d_out, int out_size)
{
    const float* xyz1    = (const float*)d_in[0];
    const float* xyz2    = (const float*)d_in[1];
    const float* points1 = (const float*)d_in[2];
    const float* points2 = (const float*)d_in[3];
    const float* w0      = (const float*)d_in[4];
    // d_in[5] = b0: cancelled by training-mode BN
    const float* g0      = (const float*)d_in[6];
    const float* be0     = (const float*)d_in[7];
    const float* w1      = (const float*)d_in[8];
    // d_in[9] = b1: cancelled by training-mode BN
    const float* g1      = (const float*)d_in[10];
    const float* be1     = (const float*)d_in[11];
    float* out = (float*)d_out;

    knn_kernel<<<dim3(NPTS / 256, BATCH), 256>>>(xyz1, xyz2);
    interp_kernel<<<dim3(C0 / 4, BATCH), 256>>>(points2);
    copy_p1_kernel<<<(C1 * MTOT / 4) / 256, 256>>>(points1);

    gemm_kernel<false><<<dim3(MTOT / 128, C0 / 128), 256>>>(w0);
    stats_kernel<0><<<C0, 256>>>();
    finalize_kernel<0><<<1, C0>>>(g0, be0);

    gemm_kernel<true><<<dim3(MTOT / 128, C1 / 128), 256>>>(w1);
    stats_kernel<1><<<C1, 256>>>();
    finalize_kernel<1><<<1, C1>>>(g1, be1);

    output_kernel<<<(C1 * MTOT / 4) / 256, 256>>>(out);
}

// round 5
// speedup vs baseline: 1.0748x; 1.0748x over previous
#include <cuda_runtime.h>
#include <cuda_bf16.h>
#include <cstdint>

#define BATCH 8
#define NPTS  8192
#define SPTS  2048
#define MTOT  65536
#define CIN   384
#define C0    256
#define C1    128

// ------------------------- device scratch -------------------------
__device__ __nv_bfloat16 d_Xh[(size_t)MTOT * CIN];   // [m][384] k-contiguous
__device__ __nv_bfloat16 d_Xl[(size_t)MTOT * CIN];
__device__ float         d_Y[(size_t)MTOT * C0];     // [m][256] ch-contiguous
__device__ float         d_Z[(size_t)C1 * MTOT];     // [c][m]   m-contiguous
__device__ __nv_bfloat16 d_W0h[C0 * CIN], d_W0l[C0 * CIN];   // [256][384]
__device__ __nv_bfloat16 d_W1h[C1 * C0],  d_W1l[C1 * C0];    // [128][256]
__device__ uint4         d_nn[MTOT];
__device__ float         d_stats[768];               // sum0,sq0 | sum1,sq1
__device__ float         d_aff[768];                 // sc0,sh0  | sc1,sh1

// ------------------------- helpers -------------------------
__device__ __forceinline__ uint32_t smem_u32(const void* p) {
    uint32_t a;
    asm("{ .reg .u64 t; cvta.to.shared.u64 t, %1; cvt.u32.u64 %0, t; }" : "=r"(a) : "l"(p));
    return a;
}
#define SW128(o) ((o) ^ (((o) >> 3) & 0x70))
#define CP_COMMIT() asm volatile("cp.async.commit_group;" ::: "memory")

__device__ __forceinline__ void cp_async16(uint32_t dst, const void* src) {
    size_t g = __cvta_generic_to_global(src);
    asm volatile("cp.async.cg.shared.global [%0], [%1], 16;" :: "r"(dst), "l"(g));
}
__device__ __forceinline__ void ldsm_x4(uint32_t (&r)[4], uint32_t addr) {
    asm volatile("ldmatrix.sync.aligned.m8n8.x4.shared.b16 {%0,%1,%2,%3}, [%4];"
                 : "=r"(r[0]), "=r"(r[1]), "=r"(r[2]), "=r"(r[3]) : "r"(addr));
}
__device__ __forceinline__ void mma_bf16(float (&c)[4], const uint32_t (&a)[4],
                                         const uint32_t (&b)[2]) {
    asm volatile(
        "mma.sync.aligned.m16n8k16.row.col.f32.bf16.bf16.f32 "
        "{%0,%1,%2,%3}, {%4,%5,%6,%7}, {%8,%9}, {%0,%1,%2,%3};"
        : "+f"(c[0]), "+f"(c[1]), "+f"(c[2]), "+f"(c[3])
        : "r"(a[0]), "r"(a[1]), "r"(a[2]), "r"(a[3]), "r"(b[0]), "r"(b[1]));
}
__device__ __forceinline__ void split_pack(float v0, float v1, uint32_t& h, uint32_t& l) {
    __nv_bfloat16 h0 = __float2bfloat16_rn(v0), h1 = __float2bfloat16_rn(v1);
    __nv_bfloat16 l0 = __float2bfloat16_rn(v0 - __bfloat162float(h0));
    __nv_bfloat16 l1 = __float2bfloat16_rn(v1 - __bfloat162float(h1));
    h = (uint32_t)__bfloat16_as_ushort(h0) | ((uint32_t)__bfloat16_as_ushort(h1) << 16);
    l = (uint32_t)__bfloat16_as_ushort(l0) | ((uint32_t)__bfloat16_as_ushort(l1) << 16);
}

// ---------------------------------------------------------------------------
__global__ void zero_stats_kernel() { if (threadIdx.x < 768) d_stats[threadIdx.x] = 0.f; }

__global__ __launch_bounds__(256)
void split_w_kernel(const float* __restrict__ w0, const float* __restrict__ w1)
{
    int i = blockIdx.x * 256 + threadIdx.x;
    if (i < C0 * CIN) {
        float v = w0[i];
        __nv_bfloat16 h = __float2bfloat16_rn(v);
        d_W0h[i] = h;
        d_W0l[i] = __float2bfloat16_rn(v - __bfloat162float(h));
    }
    int j = i - C0 * CIN;
    if (j >= 0 && j < C1 * C0) {
        float v = w1[j];
        __nv_bfloat16 h = __float2bfloat16_rn(v);
        d_W1h[j] = h;
        d_W1l[j] = __float2bfloat16_rn(v - __bfloat162float(h));
    }
}

// ---------------------------------------------------------------------------
// 3-NN search, 2 query points per thread.
// ---------------------------------------------------------------------------
__global__ __launch_bounds__(256)
void knn_kernel(const float* __restrict__ xyz1, const float* __restrict__ xyz2)
{
    __shared__ float4 sp[SPTS];
    const int b = blockIdx.y;
    const int t = threadIdx.x;

    const float* x2 = xyz2 + (size_t)b * 3 * SPTS;
    for (int s = t; s < SPTS; s += 256) {
        float x = x2[s], y = x2[SPTS + s], z = x2[2 * SPTS + s];
        sp[s] = make_float4(-2.f * x, -2.f * y, -2.f * z, x * x + y * y + z * z);
    }
    __syncthreads();

    const int nA = blockIdx.x * 512 + t;
    const int nB = nA + 256;
    const float* x1 = xyz1 + (size_t)b * 3 * NPTS;
    const float ax = x1[nA], ay = x1[NPTS + nA], az = x1[2 * NPTS + nA];
    const float bx = x1[nB], by = x1[NPTS + nB], bz = x1[2 * NPTS + nB];

    float a0 = 3.4e38f, a1 = 3.4e38f, a2 = 3.4e38f;
    float b0 = 3.4e38f, b1 = 3.4e38f, b2 = 3.4e38f;
    int ai0 = 0, ai1 = 0, ai2 = 0, bi0 = 0, bi1 = 0, bi2 = 0;

#pragma unroll 4
    for (int s = 0; s < SPTS; ++s) {
        float4 p = sp[s];
        float ka = fmaf(p.x, ax, fmaf(p.y, ay, fmaf(p.z, az, p.w)));
        float kb = fmaf(p.x, bx, fmaf(p.y, by, fmaf(p.z, bz, p.w)));
        if (ka < a2) {
            if (ka < a1) {
                a2 = a1; ai2 = ai1;
                if (ka < a0) { a1 = a0; ai1 = ai0; a0 = ka; ai0 = s; }
                else         { a1 = ka; ai1 = s; }
            } else { a2 = ka; ai2 = s; }
        }
        if (kb < b2) {
            if (kb < b1) {
                b2 = b1; bi2 = bi1;
                if (kb < b0) { b1 = b0; bi1 = bi0; b0 = kb; bi0 = s; }
                else         { b1 = kb; bi1 = s; }
            } else { b2 = kb; bi2 = s; }
        }
    }

    {
        const float sn = ax * ax + ay * ay + az * az;
        float r0 = 1.f / (a0 + sn + 1e-8f), r1 = 1.f / (a1 + sn + 1e-8f),
              r2 = 1.f / (a2 + sn + 1e-8f);
        float ws = r0 + r1 + r2;
        uint4 o;
        o.x = (uint32_t)ai0 | ((uint32_t)ai1 << 16);
        o.y = (uint32_t)ai2;
        o.z = __float_as_uint(r0 / ws);
        o.w = __float_as_uint(r1 / ws);
        d_nn[b * NPTS + nA] = o;
    }
    {
        const float sn = bx * bx + by * by + bz * bz;
        float r0 = 1.f / (b0 + sn + 1e-8f), r1 = 1.f / (b1 + sn + 1e-8f),
              r2 = 1.f / (b2 + sn + 1e-8f);
        float ws = r0 + r1 + r2;
        uint4 o;
        o.x = (uint32_t)bi0 | ((uint32_t)bi1 << 16);
        o.y = (uint32_t)bi2;
        o.z = __float_as_uint(r0 / ws);
        o.w = __float_as_uint(r1 / ws);
        d_nn[b * NPTS + nB] = o;
    }
}

// ---------------------------------------------------------------------------
// Interp -> d_Xh/d_Xl [m][384] bf16 hi/lo.
// ---------------------------------------------------------------------------
__global__ __launch_bounds__(256)
void interp_kernel(const float* __restrict__ points2)
{
    __shared__ float4 sp[SPTS];
    const int b  = blockIdx.y;
    const int d0 = blockIdx.x * 4;

    const float* src = points2 + ((size_t)b * C0 + d0) * SPTS;
    for (int s = threadIdx.x; s < SPTS; s += 256) {
        float4 v;
        v.x = src[s];
        v.y = src[SPTS + s];
        v.z = src[2 * SPTS + s];
        v.w = src[3 * SPTS + s];
        sp[s] = v;
    }
    __syncthreads();

    const int mb = b * NPTS;
    for (int n = threadIdx.x; n < NPTS; n += 256) {
        const int m = mb + n;
        const uint4 nn = d_nn[m];
        const int i0 = nn.x & 0xFFFF, i1 = nn.x >> 16, i2 = nn.y;
        const float w0 = __uint_as_float(nn.z);
        const float w1 = __uint_as_float(nn.w);
        const float w2 = 1.f - w0 - w1;
        const float4 a = sp[i0];
        const float4 c = sp[i1];
        const float4 e = sp[i2];
        float v0 = fmaf(a.x, w0, fmaf(c.x, w1, e.x * w2));
        float v1 = fmaf(a.y, w0, fmaf(c.y, w1, e.y * w2));
        float v2 = fmaf(a.z, w0, fmaf(c.z, w1, e.z * w2));
        float v3 = fmaf(a.w, w0, fmaf(c.w, w1, e.w * w2));
        uint2 h, l;
        split_pack(v0, v1, h.x, l.x);
        split_pack(v2, v3, h.y, l.y);
        *(uint2*)(d_Xh + (size_t)m * CIN + d0) = h;
        *(uint2*)(d_Xl + (size_t)m * CIN + d0) = l;
    }
}

__global__ __launch_bounds__(256)
void copy_p1_kernel(const float* __restrict__ points1)
{
    const int b  = blockIdx.y;
    const int c0 = blockIdx.x * 4;
    const float* src = points1 + ((size_t)b * C1 + c0) * NPTS;
    const int mb = b * NPTS;
    for (int n = threadIdx.x; n < NPTS; n += 256) {
        float v0 = src[n];
        float v1 = src[NPTS + n];
        float v2 = src[2 * NPTS + n];
        float v3 = src[3 * NPTS + n];
        uint2 h, l;
        split_pack(v0, v1, h.x, l.x);
        split_pack(v2, v3, h.y, l.y);
        const int m = mb + n;
        *(uint2*)(d_Xh + (size_t)m * CIN + C0 + c0) = h;
        *(uint2*)(d_Xl + (size_t)m * CIN + C0 + c0) = l;
    }
}

// ---------------------------------------------------------------------------
// GEMM0 (mma.sync bf16 split): Y[m][o] = X[m][:].W0[o][:], K=384.
// CTA: 128 ch x 128 pts. BK=64, 3-stage cp.async. Warp grid 2(m) x 4(n).
// ---------------------------------------------------------------------------
#define G0_SMEM (3 * 65536)

__global__ __launch_bounds__(256)
void gemm0_kernel()
{
    extern __shared__ char smem[];
    const uint32_t sb = smem_u32(smem);
    const int tid = threadIdx.x;
    const int m0 = blockIdx.x * 128;
    const int ct = blockIdx.y;          // channel tile (0/1)
    const int w = tid >> 5, lane = tid & 31;
    const int wm = w >> 2, wn = w & 3;
    const int lrow = lane & 15, lch = lane >> 4;

    float acc[4][4][4];
#pragma unroll
    for (int i = 0; i < 4; i++)
#pragma unroll
        for (int j = 0; j < 4; j++)
#pragma unroll
            for (int q = 0; q < 4; q++) acc[i][j][q] = 0.f;

    auto load_chunk = [&](int c, int stage) {
        const int k0 = c * 64;
        const uint32_t stg = sb + stage * 65536;
#pragma unroll
        for (int it = 0; it < 16; it++) {
            int u = it * 256 + tid;
            int arr = u >> 10;
            int v = u & 1023;
            int row = v >> 3, un = v & 7;
            uint32_t dst = stg + arr * 16384 + SW128(row * 128 + un * 16);
            const __nv_bfloat16* src;
            if (arr == 0)      src = d_W0h + (size_t)(ct * 128 + row) * CIN + k0 + un * 8;
            else if (arr == 1) src = d_W0l + (size_t)(ct * 128 + row) * CIN + k0 + un * 8;
            else if (arr == 2) src = d_Xh  + (size_t)(m0 + row) * CIN + k0 + un * 8;
            else               src = d_Xl  + (size_t)(m0 + row) * CIN + k0 + un * 8;
            cp_async16(dst, src);
        }
        CP_COMMIT();
    };

    load_chunk(0, 0);
    load_chunk(1, 1);
    load_chunk(2, 2);

    for (int c = 0; c < 6; c++) {
        if (c <= 3)      asm volatile("cp.async.wait_group 2;" ::: "memory");
        else if (c == 4) asm volatile("cp.async.wait_group 1;" ::: "memory");
        else             asm volatile("cp.async.wait_group 0;" ::: "memory");
        __syncthreads();

        const uint32_t stg = sb + (c % 3) * 65536;
        const uint32_t aH = stg, aL = stg + 16384, bHb = stg + 32768, bLb = stg + 49152;
#pragma unroll
        for (int kk = 0; kk < 4; kk++) {
            uint32_t Ah[4][4], Al[4][4], Bh[4][2], Bl[4][2];
#pragma unroll
            for (int mf = 0; mf < 4; mf++) {
                uint32_t off = SW128((wm * 64 + mf * 16 + lrow) * 128 + (kk * 2 + lch) * 16);
                ldsm_x4(Ah[mf], aH + off);
                ldsm_x4(Al[mf], aL + off);
            }
#pragma unroll
            for (int p = 0; p < 2; p++) {
                uint32_t off = SW128((wn * 32 + p * 16 + lrow) * 128 + (kk * 2 + lch) * 16);
                uint32_t r[4];
                ldsm_x4(r, bHb + off);
                Bh[2 * p][0] = r[0]; Bh[2 * p][1] = r[2];
                Bh[2 * p + 1][0] = r[1]; Bh[2 * p + 1][1] = r[3];
                ldsm_x4(r, bLb + off);
                Bl[2 * p][0] = r[0]; Bl[2 * p][1] = r[2];
                Bl[2 * p + 1][0] = r[1]; Bl[2 * p + 1][1] = r[3];
            }
#pragma unroll
            for (int mf = 0; mf < 4; mf++)
#pragma unroll
                for (int nf = 0; nf < 4; nf++) {
                    mma_bf16(acc[mf][nf], Ah[mf], Bh[nf]);
                    mma_bf16(acc[mf][nf], Al[mf], Bh[nf]);
                    mma_bf16(acc[mf][nf], Ah[mf], Bl[nf]);
                }
        }
        __syncthreads();
        if (c + 3 < 6) load_chunk(c + 3, c % 3);
    }

    // ---- fused BN0 stats (sum, sumsq) via quad-shuffle + atomics ----
    float ssum[4][2] = {}, ssq[4][2] = {};
#pragma unroll
    for (int mf = 0; mf < 4; mf++)
#pragma unroll
        for (int nf = 0; nf < 4; nf++) {
            const float* a = acc[mf][nf];
            ssum[mf][0] += a[0] + a[1];
            ssum[mf][1] += a[2] + a[3];
            ssq[mf][0]  += a[0] * a[0] + a[1] * a[1];
            ssq[mf][1]  += a[2] * a[2] + a[3] * a[3];
        }
#pragma unroll
    for (int mf = 0; mf < 4; mf++)
#pragma unroll
        for (int h = 0; h < 2; h++) {
            float s = ssum[mf][h], q = ssq[mf][h];
            s += __shfl_xor_sync(0xffffffffu, s, 1);
            s += __shfl_xor_sync(0xffffffffu, s, 2);
            q += __shfl_xor_sync(0xffffffffu, q, 1);
            q += __shfl_xor_sync(0xffffffffu, q, 2);
            if ((lane & 3) == 0) {
                int ch = ct * 128 + wm * 64 + mf * 16 + (lane >> 2) + h * 8;
                atomicAdd(&d_stats[ch], s);
                atomicAdd(&d_stats[256 + ch], q);
            }
        }

    // ---- smem transpose -> coalesced d_Y [m][256] ----
    float* st = (float*)smem;
#pragma unroll
    for (int mf = 0; mf < 4; mf++)
#pragma unroll
        for (int nf = 0; nf < 4; nf++) {
            int ch = wm * 64 + mf * 16 + (lane >> 2);
            int pt = wn * 32 + nf * 8 + (lane & 3) * 2;
            st[pt * 132 + ch]           = acc[mf][nf][0];
            st[(pt + 1) * 132 + ch]     = acc[mf][nf][1];
            st[pt * 132 + ch + 8]       = acc[mf][nf][2];
            st[(pt + 1) * 132 + ch + 8] = acc[mf][nf][3];
        }
    __syncthreads();
    {
        const int row = tid >> 1, half = tid & 1;
        float4* dst = (float4*)(d_Y + (size_t)(m0 + row) * C0 + ct * 128 + half * 64);
        const float* sp = st + row * 132 + half * 64;
#pragma unroll
        for (int j = 0; j < 16; j++) dst[j] = *(const float4*)(sp + j * 4);
    }
}

// ---------------------------------------------------------------------------
// finalize BN constants (conv biases cancel under training-mode BN)
// ---------------------------------------------------------------------------
template<int LAYER>
__global__ void finalize_kernel(const float* __restrict__ g, const float* __restrict__ be)
{
    const int c  = threadIdx.x;
    const int o  = LAYER ? 512 : 0;
    const int cc = LAYER ? C1 : C0;
    const float mean = d_stats[o + c] * (1.f / MTOT);
    const float var  = d_stats[o + cc + c] * (1.f / MTOT) - mean * mean;
    const float sc   = g[c] * rsqrtf(var + 1e-5f);
    d_aff[o + c]      = sc;
    d_aff[o + cc + c] = be[c] - mean * sc;
}

// ---------------------------------------------------------------------------
// GEMM1: Z = relu(aff0(Y)) . W1^T, K=256. Entire W1 resident in smem;
// B produced in-register (affine+relu+split fused), double-buffered.
// ---------------------------------------------------------------------------
#define G1_SMEM (2048 + 131072 + 65536)

__global__ __launch_bounds__(256)
void gemm1_kernel()
{
    extern __shared__ char smem[];
    const uint32_t sb = smem_u32(smem);
    float* s_aff = (float*)smem;                 // 512 floats
    const uint32_t Wbase = sb + 2048;            // 8 tiles x 16KB (h: 0..64K, l: 64K..128K)
    const uint32_t Bbase = sb + 2048 + 131072;   // 2 x (Bh 16K + Bl 16K)
    const int tid = threadIdx.x;
    const int m0 = blockIdx.x * 128;
    const int w = tid >> 5, lane = tid & 31;
    const int wm = w >> 2, wn = w & 3;
    const int lrow = lane & 15, lch = lane >> 4;

    for (int i = tid; i < 512; i += 256) s_aff[i] = d_aff[i];

    // load entire W1 (h+l) via cp.async
#pragma unroll
    for (int it = 0; it < 32; it++) {
        int u = it * 256 + tid;
        int arr = u >> 12;            // 0=h 1=l
        int v = u & 4095;
        int chunk = v >> 10;
        int vv = v & 1023;
        int row = vv >> 3, un = vv & 7;
        uint32_t dst = Wbase + arr * 65536 + chunk * 16384 + SW128(row * 128 + un * 16);
        const __nv_bfloat16* src =
            (arr ? d_W1l : d_W1h) + (size_t)row * C0 + chunk * 64 + un * 8;
        cp_async16(dst, src);
    }
    CP_COMMIT();

    auto produce = [&](int c, int buf) {
        const uint32_t bH = Bbase + buf * 32768, bL = bH + 16384;
        const int yrow = tid >> 1;
        const int koff = (tid & 1) * 32;
        const float* yp  = d_Y + (size_t)(m0 + yrow) * C0 + c * 64 + koff;
        const float* af  = s_aff + c * 64 + koff;
        const float* af2 = s_aff + 256 + c * 64 + koff;
        uint32_t hi[16], lo[16];
#pragma unroll
        for (int i = 0; i < 32; i += 4) {
            float4 v = *(const float4*)(yp + i);
            float x0 = fmaxf(fmaf(v.x, af[i],     af2[i]),     0.f);
            float x1 = fmaxf(fmaf(v.y, af[i + 1], af2[i + 1]), 0.f);
            float x2 = fmaxf(fmaf(v.z, af[i + 2], af2[i + 2]), 0.f);
            float x3 = fmaxf(fmaf(v.w, af[i + 3], af2[i + 3]), 0.f);
            split_pack(x0, x1, hi[i >> 1], lo[i >> 1]);
            split_pack(x2, x3, hi[(i >> 1) + 1], lo[(i >> 1) + 1]);
        }
#pragma unroll
        for (int uu = 0; uu < 4; uu++) {
            uint32_t off = SW128(yrow * 128 + ((tid & 1) * 4 + uu) * 16);
            asm volatile("st.shared.v4.b32 [%0], {%1,%2,%3,%4};"
                         :: "r"(bH + off), "r"(hi[uu * 4]), "r"(hi[uu * 4 + 1]),
                            "r"(hi[uu * 4 + 2]), "r"(hi[uu * 4 + 3]) : "memory");
            asm volatile("st.shared.v4.b32 [%0], {%1,%2,%3,%4};"
                         :: "r"(bL + off), "r"(lo[uu * 4]), "r"(lo[uu * 4 + 1]),
                            "r"(lo[uu * 4 + 2]), "r"(lo[uu * 4 + 3]) : "memory");
        }
    };

    produce(0, 0);
    asm volatile("cp.async.wait_group 0;" ::: "memory");
    __syncthreads();

    float acc[4][4][4];
#pragma unroll
    for (int i = 0; i < 4; i++)
#pragma unroll
        for (int j = 0; j < 4; j++)
#pragma unroll
            for (int q = 0; q < 4; q++) acc[i][j][q] = 0.f;

    for (int c = 0; c < 4; c++) {
        if (c < 3) produce(c + 1, (c + 1) & 1);

        const uint32_t aH = Wbase + c * 16384, aL = Wbase + 65536 + c * 16384;
        const uint32_t bHb = Bbase + (c & 1) * 32768, bLb = bHb + 16384;
#pragma unroll
        for (int kk = 0; kk < 4; kk++) {
            uint32_t Ah[4][4], Al[4][4], Bh[4][2], Bl[4][2];
#pragma unroll
            for (int mf = 0; mf < 4; mf++) {
                uint32_t off = SW128((wm * 64 + mf * 16 + lrow) * 128 + (kk * 2 + lch) * 16);
                ldsm_x4(Ah[mf], aH + off);
                ldsm_x4(Al[mf], aL + off);
            }
#pragma unroll
            for (int p = 0; p < 2; p++) {
                uint32_t off = SW128((wn * 32 + p * 16 + lrow) * 128 + (kk * 2 + lch) * 16);
                uint32_t r[4];
                ldsm_x4(r, bHb + off);
                Bh[2 * p][0] = r[0]; Bh[2 * p][1] = r[2];
                Bh[2 * p + 1][0] = r[1]; Bh[2 * p + 1][1] = r[3];
                ldsm_x4(r, bLb + off);
                Bl[2 * p][0] = r[0]; Bl[2 * p][1] = r[2];
                Bl[2 * p + 1][0] = r[1]; Bl[2 * p + 1][1] = r[3];
            }
#pragma unroll
            for (int mf = 0; mf < 4; mf++)
#pragma unroll
                for (int nf = 0; nf < 4; nf++) {
                    mma_bf16(acc[mf][nf], Ah[mf], Bh[nf]);
                    mma_bf16(acc[mf][nf], Al[mf], Bh[nf]);
                    mma_bf16(acc[mf][nf], Ah[mf], Bl[nf]);
                }
        }
        __syncthreads();
    }

    // ---- fused BN1 stats ----
    float ssum[4][2] = {}, ssq[4][2] = {};
#pragma unroll
    for (int mf = 0; mf < 4; mf++)
#pragma unroll
        for (int nf = 0; nf < 4; nf++) {
            const float* a = acc[mf][nf];
            ssum[mf][0] += a[0] + a[1];
            ssum[mf][1] += a[2] + a[3];
            ssq[mf][0]  += a[0] * a[0] + a[1] * a[1];
            ssq[mf][1]  += a[2] * a[2] + a[3] * a[3];
        }
#pragma unroll
    for (int mf = 0; mf < 4; mf++)
#pragma unroll
        for (int h = 0; h < 2; h++) {
            float s = ssum[mf][h], q = ssq[mf][h];
            s += __shfl_xor_sync(0xffffffffu, s, 1);
            s += __shfl_xor_sync(0xffffffffu, s, 2);
            q += __shfl_xor_sync(0xffffffffu, q, 1);
            q += __shfl_xor_sync(0xffffffffu, q, 2);
            if ((lane & 3) == 0) {
                int ch = wm * 64 + mf * 16 + (lane >> 2) + h * 8;
                atomicAdd(&d_stats[512 + ch], s);
                atomicAdd(&d_stats[640 + ch], q);
            }
        }

    // ---- store d_Z [c][m] (pt-pairs contiguous => coalesced 32B sectors) ----
#pragma unroll
    for (int mf = 0; mf < 4; mf++)
#pragma unroll
        for (int nf = 0; nf < 4; nf++) {
            int ch = wm * 64 + mf * 16 + (lane >> 2);
            int pt = m0 + wn * 32 + nf * 8 + (lane & 3) * 2;
            *(float2*)(d_Z + (size_t)ch * MTOT + pt) =
                make_float2(acc[mf][nf][0], acc[mf][nf][1]);
            *(float2*)(d_Z + (size_t)(ch + 8) * MTOT + pt) =
                make_float2(acc[mf][nf][2], acc[mf][nf][3]);
        }
}

// ---------------------------------------------------------------------------
// BN1 affine + ReLU + output [B,128,N]; d_Z is [c][m] so both sides coalesced.
// ---------------------------------------------------------------------------
__global__ __launch_bounds__(256)
void output_kernel(float* __restrict__ out)
{
    const int i = blockIdx.x * 256 + threadIdx.x;
    const int base = i * 4;
    const int o = base >> 16;
    const int m = base & 65535;
    const int b = m >> 13;
    const int n = m & 8191;
    float4 v = *(const float4*)(d_Z + (size_t)o * MTOT + m);
    const float sc = d_aff[512 + o];
    const float sh = d_aff[640 + o];
    v.x = fmaxf(fmaf(v.x, sc, sh), 0.f);
    v.y = fmaxf(fmaf(v.y, sc, sh), 0.f);
    v.z = fmaxf(fmaf(v.z, sc, sh), 0.f);
    v.w = fmaxf(fmaf(v.w, sc, sh), 0.f);
    *(float4*)(out + ((size_t)b * C1 + o) * NPTS + n) = v;
}

// ---------------------------------------------------------------------------
extern "C" void kernel_launch(void* const* d_in, const int* in_sizes, int n_in,
                              void* d_out, int out_size)
{
    const float* xyz1    = (const float*)d_in[0];
    const float* xyz2    = (const float*)d_in[1];
    const float* points1 = (const float*)d_in[2];
    const float* points2 = (const float*)d_in[3];
    const float* w0      = (const float*)d_in[4];
    const float* g0      = (const float*)d_in[6];
    const float* be0     = (const float*)d_in[7];
    const float* w1      = (const float*)d_in[8];
    const float* g1      = (const float*)d_in[10];
    const float* be1     = (const float*)d_in[11];
    float* out = (float*)d_out;

    cudaFuncSetAttribute(gemm0_kernel, cudaFuncAttributeMaxDynamicSharedMemorySize, G0_SMEM);
    cudaFuncSetAttribute(gemm1_kernel, cudaFuncAttributeMaxDynamicSharedMemorySize, G1_SMEM);

    zero_stats_kernel<<<1, 768>>>();
    split_w_kernel<<<(C0 * CIN + C1 * C0 + 255) / 256, 256>>>(w0, w1);
    knn_kernel<<<dim3(NPTS / 512, BATCH), 256>>>(xyz1, xyz2);
    interp_kernel<<<dim3(C0 / 4, BATCH), 256>>>(points2);
    copy_p1_kernel<<<dim3(C1 / 4, BATCH), 256>>>(points1);

    gemm0_kernel<<<dim3(MTOT / 128, 2), 256, G0_SMEM>>>();
    finalize_kernel<0><<<1, C0>>>(g0, be0);

    gemm1_kernel<<<MTOT / 128, 256, G1_SMEM>>>();
    finalize_kernel<1><<<1, C1>>>(g1, be1);

    output_kernel<<<(C1 * MTOT / 4) / 256, 256>>>(out);
}

// round 6
// speedup vs baseline: 1.3358x; 1.2428x over previous
#include <cuda_runtime.h>
#include <cuda_bf16.h>
#include <cstdint>

#define BATCH 8
#define NPTS  8192
#define SPTS  2048
#define MTOT  65536
#define CIN   384
#define C0    256
#define C1    128

// ------------------------- device scratch -------------------------
__device__ __nv_bfloat16 d_Xh[(size_t)MTOT * CIN];   // [m][384] k-contiguous
__device__ __nv_bfloat16 d_Xl[(size_t)MTOT * CIN];
__device__ float         d_Y[(size_t)MTOT * C0];     // [m][256] ch-contiguous
__device__ float         d_Z[(size_t)C1 * MTOT];     // [c][m]   m-contiguous
__device__ float         d_P2T[(size_t)BATCH * SPTS * C0];   // [b][s][256]
__device__ __nv_bfloat16 d_W0h[C0 * CIN], d_W0l[C0 * CIN];   // [256][384]
__device__ __nv_bfloat16 d_W1h[C1 * C0],  d_W1l[C1 * C0];    // [128][256]
__device__ uint4         d_nn[MTOT];
__device__ float         d_stats[768];               // sum0,sq0 | sum1,sq1
__device__ float         d_aff[768];                 // sc0,sh0  | sc1,sh1

// ------------------------- helpers -------------------------
__device__ __forceinline__ uint32_t smem_u32(const void* p) {
    uint32_t a;
    asm("{ .reg .u64 t; cvta.to.shared.u64 t, %1; cvt.u32.u64 %0, t; }" : "=r"(a) : "l"(p));
    return a;
}
#define SW128(o) ((o) ^ (((o) >> 3) & 0x70))
#define CP_COMMIT() asm volatile("cp.async.commit_group;" ::: "memory")

__device__ __forceinline__ void cp_async16(uint32_t dst, const void* src) {
    size_t g = __cvta_generic_to_global(src);
    asm volatile("cp.async.cg.shared.global [%0], [%1], 16;" :: "r"(dst), "l"(g));
}
__device__ __forceinline__ void ldsm_x4(uint32_t (&r)[4], uint32_t addr) {
    asm volatile("ldmatrix.sync.aligned.m8n8.x4.shared.b16 {%0,%1,%2,%3}, [%4];"
                 : "=r"(r[0]), "=r"(r[1]), "=r"(r[2]), "=r"(r[3]) : "r"(addr));
}
__device__ __forceinline__ void mma_bf16(float (&c)[4], const uint32_t (&a)[4],
                                         const uint32_t (&b)[2]) {
    asm volatile(
        "mma.sync.aligned.m16n8k16.row.col.f32.bf16.bf16.f32 "
        "{%0,%1,%2,%3}, {%4,%5,%6,%7}, {%8,%9}, {%0,%1,%2,%3};"
        : "+f"(c[0]), "+f"(c[1]), "+f"(c[2]), "+f"(c[3])
        : "r"(a[0]), "r"(a[1]), "r"(a[2]), "r"(a[3]), "r"(b[0]), "r"(b[1]));
}
__device__ __forceinline__ void split_pack(float v0, float v1, uint32_t& h, uint32_t& l) {
    __nv_bfloat16 h0 = __float2bfloat16_rn(v0), h1 = __float2bfloat16_rn(v1);
    __nv_bfloat16 l0 = __float2bfloat16_rn(v0 - __bfloat162float(h0));
    __nv_bfloat16 l1 = __float2bfloat16_rn(v1 - __bfloat162float(h1));
    h = (uint32_t)__bfloat16_as_ushort(h0) | ((uint32_t)__bfloat16_as_ushort(h1) << 16);
    l = (uint32_t)__bfloat16_as_ushort(l0) | ((uint32_t)__bfloat16_as_ushort(l1) << 16);
}

// ---------------------------------------------------------------------------
__global__ void zero_stats_kernel() { if (threadIdx.x < 768) d_stats[threadIdx.x] = 0.f; }

__global__ __launch_bounds__(256)
void split_w_kernel(const float* __restrict__ w0, const float* __restrict__ w1)
{
    int i = blockIdx.x * 256 + threadIdx.x;
    if (i < C0 * CIN) {
        float v = w0[i];
        __nv_bfloat16 h = __float2bfloat16_rn(v);
        d_W0h[i] = h;
        d_W0l[i] = __float2bfloat16_rn(v - __bfloat162float(h));
    }
    int j = i - C0 * CIN;
    if (j >= 0 && j < C1 * C0) {
        float v = w1[j];
        __nv_bfloat16 h = __float2bfloat16_rn(v);
        d_W1h[j] = h;
        d_W1l[j] = __float2bfloat16_rn(v - __bfloat162float(h));
    }
}

// ---------------------------------------------------------------------------
// 3-NN search, 2 query points per thread.
// ---------------------------------------------------------------------------
__global__ __launch_bounds__(256)
void knn_kernel(const float* __restrict__ xyz1, const float* __restrict__ xyz2)
{
    __shared__ float4 sp[SPTS];
    const int b = blockIdx.y;
    const int t = threadIdx.x;

    const float* x2 = xyz2 + (size_t)b * 3 * SPTS;
    for (int s = t; s < SPTS; s += 256) {
        float x = x2[s], y = x2[SPTS + s], z = x2[2 * SPTS + s];
        sp[s] = make_float4(-2.f * x, -2.f * y, -2.f * z, x * x + y * y + z * z);
    }
    __syncthreads();

    const int nA = blockIdx.x * 512 + t;
    const int nB = nA + 256;
    const float* x1 = xyz1 + (size_t)b * 3 * NPTS;
    const float ax = x1[nA], ay = x1[NPTS + nA], az = x1[2 * NPTS + nA];
    const float bx = x1[nB], by = x1[NPTS + nB], bz = x1[2 * NPTS + nB];

    float a0 = 3.4e38f, a1 = 3.4e38f, a2 = 3.4e38f;
    float b0 = 3.4e38f, b1 = 3.4e38f, b2 = 3.4e38f;
    int ai0 = 0, ai1 = 0, ai2 = 0, bi0 = 0, bi1 = 0, bi2 = 0;

#pragma unroll 4
    for (int s = 0; s < SPTS; ++s) {
        float4 p = sp[s];
        float ka = fmaf(p.x, ax, fmaf(p.y, ay, fmaf(p.z, az, p.w)));
        float kb = fmaf(p.x, bx, fmaf(p.y, by, fmaf(p.z, bz, p.w)));
        if (ka < a2) {
            if (ka < a1) {
                a2 = a1; ai2 = ai1;
                if (ka < a0) { a1 = a0; ai1 = ai0; a0 = ka; ai0 = s; }
                else         { a1 = ka; ai1 = s; }
            } else { a2 = ka; ai2 = s; }
        }
        if (kb < b2) {
            if (kb < b1) {
                b2 = b1; bi2 = bi1;
                if (kb < b0) { b1 = b0; bi1 = bi0; b0 = kb; bi0 = s; }
                else         { b1 = kb; bi1 = s; }
            } else { b2 = kb; bi2 = s; }
        }
    }

    {
        const float sn = ax * ax + ay * ay + az * az;
        float r0 = 1.f / (a0 + sn + 1e-8f), r1 = 1.f / (a1 + sn + 1e-8f),
              r2 = 1.f / (a2 + sn + 1e-8f);
        float ws = r0 + r1 + r2;
        uint4 o;
        o.x = (uint32_t)ai0 | ((uint32_t)ai1 << 16);
        o.y = (uint32_t)ai2;
        o.z = __float_as_uint(r0 / ws);
        o.w = __float_as_uint(r1 / ws);
        d_nn[b * NPTS + nA] = o;
    }
    {
        const float sn = bx * bx + by * by + bz * bz;
        float r0 = 1.f / (b0 + sn + 1e-8f), r1 = 1.f / (b1 + sn + 1e-8f),
              r2 = 1.f / (b2 + sn + 1e-8f);
        float ws = r0 + r1 + r2;
        uint4 o;
        o.x = (uint32_t)bi0 | ((uint32_t)bi1 << 16);
        o.y = (uint32_t)bi2;
        o.z = __float_as_uint(r0 / ws);
        o.w = __float_as_uint(r1 / ws);
        d_nn[b * NPTS + nB] = o;
    }
}

// ---------------------------------------------------------------------------
// Transpose points2 [b][256][2048] -> d_P2T [b][s][256] fp32.
// Block: 32 s-columns x all 256 channels via smem tile; both sides coalesced.
// ---------------------------------------------------------------------------
__global__ __launch_bounds__(256)
void transpose_p2_kernel(const float* __restrict__ points2)
{
    __shared__ float tile[32][260];   // [s][ch], pad 260 to spread banks
    const int b  = blockIdx.y;
    const int s0 = blockIdx.x * 32;
    const int tx = threadIdx.x & 31;      // s offset
    const int ty = threadIdx.x >> 5;      // ch base (0..7)

    const float* src = points2 + (size_t)b * C0 * SPTS;
#pragma unroll
    for (int k = 0; k < 32; k++) {
        const int ch = ty + k * 8;
        tile[tx][ch] = src[(size_t)ch * SPTS + s0 + tx];
    }
    __syncthreads();

    // warp w writes s-rows w, w+8, w+16, w+24 : 256 ch = 2 float4 per lane
    const int w = threadIdx.x >> 5, lane = threadIdx.x & 31;
#pragma unroll
    for (int k = 0; k < 4; k++) {
        const int s = w + k * 8;
        float* dst = d_P2T + ((size_t)b * SPTS + s0 + s) * C0;
        *(float4*)(dst + lane * 8)     = *(const float4*)(&tile[s][lane * 8]);
        *(float4*)(dst + lane * 8 + 4) = *(const float4*)(&tile[s][lane * 8 + 4]);
    }
}

// ---------------------------------------------------------------------------
// Fused X-builder: warp-per-point. Block = 32 points, 8 warps (4 points/warp).
// Phase A: stage points1 [128ch][32pt] tile (transposed in smem).
// Phase B: per point -- gather 3 neighbor rows from d_P2T (coalesced 1KB
// bursts, L2-resident), weight-combine, bf16 hi/lo split, write X rows with
// fully coalesced 512B/256B warp stores. d_nn read once per point.
// ---------------------------------------------------------------------------
__global__ __launch_bounds__(256)
void fused_x_kernel(const float* __restrict__ points1)
{
    __shared__ float tile[32][132];   // [pt][ch]; 132*4B = 33*16B (float4-aligned rows)
    const int m0 = blockIdx.x * 32;
    const int b  = m0 >> 13;
    const int n0 = m0 & 8191;
    const int tx = threadIdx.x & 31;      // pt offset
    const int ty = threadIdx.x >> 5;      // ch base

    const float* p1 = points1 + (size_t)b * C1 * NPTS;
#pragma unroll
    for (int k = 0; k < 16; k++) {
        const int ch = ty + k * 8;
        tile[tx][ch] = p1[(size_t)ch * NPTS + n0 + tx];
    }
    __syncthreads();

    const int w = threadIdx.x >> 5, lane = threadIdx.x & 31;
    const float* p2t = d_P2T + (size_t)b * SPTS * C0;

#pragma unroll
    for (int k = 0; k < 4; k++) {
        const int pt = w * 4 + k;
        const int m  = m0 + pt;
        const uint4 nn = d_nn[m];                   // broadcast (same addr all lanes)
        const int i0 = nn.x & 0xFFFF, i1 = nn.x >> 16, i2 = nn.y;
        const float w0 = __uint_as_float(nn.z);
        const float w1 = __uint_as_float(nn.w);
        const float w2 = 1.f - w0 - w1;

        const float4* r0 = (const float4*)(p2t + (size_t)i0 * C0);
        const float4* r1 = (const float4*)(p2t + (size_t)i1 * C0);
        const float4* r2 = (const float4*)(p2t + (size_t)i2 * C0);

        uint4 H, L;
        {   // channels lane*8 .. lane*8+7 (two float4 per neighbor row)
            float4 a0 = r0[lane * 2],     c0 = r1[lane * 2],     e0 = r2[lane * 2];
            float4 a1 = r0[lane * 2 + 1], c1 = r1[lane * 2 + 1], e1 = r2[lane * 2 + 1];
            float v0 = fmaf(a0.x, w0, fmaf(c0.x, w1, e0.x * w2));
            float v1 = fmaf(a0.y, w0, fmaf(c0.y, w1, e0.y * w2));
            float v2 = fmaf(a0.z, w0, fmaf(c0.z, w1, e0.z * w2));
            float v3 = fmaf(a0.w, w0, fmaf(c0.w, w1, e0.w * w2));
            float v4 = fmaf(a1.x, w0, fmaf(c1.x, w1, e1.x * w2));
            float v5 = fmaf(a1.y, w0, fmaf(c1.y, w1, e1.y * w2));
            float v6 = fmaf(a1.z, w0, fmaf(c1.z, w1, e1.z * w2));
            float v7 = fmaf(a1.w, w0, fmaf(c1.w, w1, e1.w * w2));
            split_pack(v0, v1, H.x, L.x);
            split_pack(v2, v3, H.y, L.y);
            split_pack(v4, v5, H.z, L.z);
            split_pack(v6, v7, H.w, L.w);
        }
        __nv_bfloat16* xh = d_Xh + (size_t)m * CIN;
        __nv_bfloat16* xl = d_Xl + (size_t)m * CIN;
        *(uint4*)(xh + lane * 8) = H;               // warp: 512B contiguous
        *(uint4*)(xl + lane * 8) = L;

        {   // points1 channels: 4 per lane from smem tile (conflict-free float4)
            float4 v = *(const float4*)(&tile[pt][lane * 4]);
            uint2 h, l;
            split_pack(v.x, v.y, h.x, l.x);
            split_pack(v.z, v.w, h.y, l.y);
            *(uint2*)(xh + C0 + lane * 4) = h;      // warp: 256B contiguous
            *(uint2*)(xl + C0 + lane * 4) = l;
        }
    }
}

// ---------------------------------------------------------------------------
// GEMM0 (mma.sync bf16 split): Y[m][o] = X[m][:].W0[o][:], K=384.
// CTA: 128 ch x 128 pts. BK=64, 3-stage cp.async. Warp grid 2(m) x 4(n).
// ---------------------------------------------------------------------------
#define G0_SMEM (3 * 65536)

__global__ __launch_bounds__(256)
void gemm0_kernel()
{
    extern __shared__ char smem[];
    const uint32_t sb = smem_u32(smem);
    const int tid = threadIdx.x;
    const int m0 = blockIdx.x * 128;
    const int ct = blockIdx.y;          // channel tile (0/1)
    const int w = tid >> 5, lane = tid & 31;
    const int wm = w >> 2, wn = w & 3;
    const int lrow = lane & 15, lch = lane >> 4;

    float acc[4][4][4];
#pragma unroll
    for (int i = 0; i < 4; i++)
#pragma unroll
        for (int j = 0; j < 4; j++)
#pragma unroll
            for (int q = 0; q < 4; q++) acc[i][j][q] = 0.f;

    auto load_chunk = [&](int c, int stage) {
        const int k0 = c * 64;
        const uint32_t stg = sb + stage * 65536;
#pragma unroll
        for (int it = 0; it < 16; it++) {
            int u = it * 256 + tid;
            int arr = u >> 10;
            int v = u & 1023;
            int row = v >> 3, un = v & 7;
            uint32_t dst = stg + arr * 16384 + SW128(row * 128 + un * 16);
            const __nv_bfloat16* src;
            if (arr == 0)      src = d_W0h + (size_t)(ct * 128 + row) * CIN + k0 + un * 8;
            else if (arr == 1) src = d_W0l + (size_t)(ct * 128 + row) * CIN + k0 + un * 8;
            else if (arr == 2) src = d_Xh  + (size_t)(m0 + row) * CIN + k0 + un * 8;
            else               src = d_Xl  + (size_t)(m0 + row) * CIN + k0 + un * 8;
            cp_async16(dst, src);
        }
        CP_COMMIT();
    };

    load_chunk(0, 0);
    load_chunk(1, 1);
    load_chunk(2, 2);

    for (int c = 0; c < 6; c++) {
        if (c <= 3)      asm volatile("cp.async.wait_group 2;" ::: "memory");
        else if (c == 4) asm volatile("cp.async.wait_group 1;" ::: "memory");
        else             asm volatile("cp.async.wait_group 0;" ::: "memory");
        __syncthreads();

        const uint32_t stg = sb + (c % 3) * 65536;
        const uint32_t aH = stg, aL = stg + 16384, bHb = stg + 32768, bLb = stg + 49152;
#pragma unroll
        for (int kk = 0; kk < 4; kk++) {
            uint32_t Ah[4][4], Al[4][4], Bh[4][2], Bl[4][2];
#pragma unroll
            for (int mf = 0; mf < 4; mf++) {
                uint32_t off = SW128((wm * 64 + mf * 16 + lrow) * 128 + (kk * 2 + lch) * 16);
                ldsm_x4(Ah[mf], aH + off);
                ldsm_x4(Al[mf], aL + off);
            }
#pragma unroll
            for (int p = 0; p < 2; p++) {
                uint32_t off = SW128((wn * 32 + p * 16 + lrow) * 128 + (kk * 2 + lch) * 16);
                uint32_t r[4];
                ldsm_x4(r, bHb + off);
                Bh[2 * p][0] = r[0]; Bh[2 * p][1] = r[2];
                Bh[2 * p + 1][0] = r[1]; Bh[2 * p + 1][1] = r[3];
                ldsm_x4(r, bLb + off);
                Bl[2 * p][0] = r[0]; Bl[2 * p][1] = r[2];
                Bl[2 * p + 1][0] = r[1]; Bl[2 * p + 1][1] = r[3];
            }
#pragma unroll
            for (int mf = 0; mf < 4; mf++)
#pragma unroll
                for (int nf = 0; nf < 4; nf++) {
                    mma_bf16(acc[mf][nf], Ah[mf], Bh[nf]);
                    mma_bf16(acc[mf][nf], Al[mf], Bh[nf]);
                    mma_bf16(acc[mf][nf], Ah[mf], Bl[nf]);
                }
        }
        __syncthreads();
        if (c + 3 < 6) load_chunk(c + 3, c % 3);
    }

    // ---- fused BN0 stats (sum, sumsq) via quad-shuffle + atomics ----
    float ssum[4][2] = {}, ssq[4][2] = {};
#pragma unroll
    for (int mf = 0; mf < 4; mf++)
#pragma unroll
        for (int nf = 0; nf < 4; nf++) {
            const float* a = acc[mf][nf];
            ssum[mf][0] += a[0] + a[1];
            ssum[mf][1] += a[2] + a[3];
            ssq[mf][0]  += a[0] * a[0] + a[1] * a[1];
            ssq[mf][1]  += a[2] * a[2] + a[3] * a[3];
        }
#pragma unroll
    for (int mf = 0; mf < 4; mf++)
#pragma unroll
        for (int h = 0; h < 2; h++) {
            float s = ssum[mf][h], q = ssq[mf][h];
            s += __shfl_xor_sync(0xffffffffu, s, 1);
            s += __shfl_xor_sync(0xffffffffu, s, 2);
            q += __shfl_xor_sync(0xffffffffu, q, 1);
            q += __shfl_xor_sync(0xffffffffu, q, 2);
            if ((lane & 3) == 0) {
                int ch = ct * 128 + wm * 64 + mf * 16 + (lane >> 2) + h * 8;
                atomicAdd(&d_stats[ch], s);
                atomicAdd(&d_stats[256 + ch], q);
            }
        }

    // ---- smem transpose -> coalesced d_Y [m][256] ----
    float* st = (float*)smem;
#pragma unroll
    for (int mf = 0; mf < 4; mf++)
#pragma unroll
        for (int nf = 0; nf < 4; nf++) {
            int ch = wm * 64 + mf * 16 + (lane >> 2);
            int pt = wn * 32 + nf * 8 + (lane & 3) * 2;
            st[pt * 132 + ch]           = acc[mf][nf][0];
            st[(pt + 1) * 132 + ch]     = acc[mf][nf][1];
            st[pt * 132 + ch + 8]       = acc[mf][nf][2];
            st[(pt + 1) * 132 + ch + 8] = acc[mf][nf][3];
        }
    __syncthreads();
    {
        const int row = tid >> 1, half = tid & 1;
        float4* dst = (float4*)(d_Y + (size_t)(m0 + row) * C0 + ct * 128 + half * 64);
        const float* sp = st + row * 132 + half * 64;
#pragma unroll
        for (int j = 0; j < 16; j++) dst[j] = *(const float4*)(sp + j * 4);
    }
}

// ---------------------------------------------------------------------------
// finalize BN constants (conv biases cancel under training-mode BN)
// ---------------------------------------------------------------------------
template<int LAYER>
__global__ void finalize_kernel(const float* __restrict__ g, const float* __restrict__ be)
{
    const int c  = threadIdx.x;
    const int o  = LAYER ? 512 : 0;
    const int cc = LAYER ? C1 : C0;
    const float mean = d_stats[o + c] * (1.f / MTOT);
    const float var  = d_stats[o + cc + c] * (1.f / MTOT) - mean * mean;
    const float sc   = g[c] * rsqrtf(var + 1e-5f);
    d_aff[o + c]      = sc;
    d_aff[o + cc + c] = be[c] - mean * sc;
}

// ---------------------------------------------------------------------------
// GEMM1: Z = relu(aff0(Y)) . W1^T, K=256. Entire W1 resident in smem;
// B produced in-register (affine+relu+split fused), double-buffered.
// ---------------------------------------------------------------------------
#define G1_SMEM (2048 + 131072 + 65536)

__global__ __launch_bounds__(256)
void gemm1_kernel()
{
    extern __shared__ char smem[];
    const uint32_t sb = smem_u32(smem);
    float* s_aff = (float*)smem;                 // 512 floats
    const uint32_t Wbase = sb + 2048;            // 8 tiles x 16KB (h: 0..64K, l: 64K..128K)
    const uint32_t Bbase = sb + 2048 + 131072;   // 2 x (Bh 16K + Bl 16K)
    const int tid = threadIdx.x;
    const int m0 = blockIdx.x * 128;
    const int w = tid >> 5, lane = tid & 31;
    const int wm = w >> 2, wn = w & 3;
    const int lrow = lane & 15, lch = lane >> 4;

    for (int i = tid; i < 512; i += 256) s_aff[i] = d_aff[i];

    // load entire W1 (h+l) via cp.async
#pragma unroll
    for (int it = 0; it < 32; it++) {
        int u = it * 256 + tid;
        int arr = u >> 12;            // 0=h 1=l
        int v = u & 4095;
        int chunk = v >> 10;
        int vv = v & 1023;
        int row = vv >> 3, un = vv & 7;
        uint32_t dst = Wbase + arr * 65536 + chunk * 16384 + SW128(row * 128 + un * 16);
        const __nv_bfloat16* src =
            (arr ? d_W1l : d_W1h) + (size_t)row * C0 + chunk * 64 + un * 8;
        cp_async16(dst, src);
    }
    CP_COMMIT();

    auto produce = [&](int c, int buf) {
        const uint32_t bH = Bbase + buf * 32768, bL = bH + 16384;
        const int yrow = tid >> 1;
        const int koff = (tid & 1) * 32;
        const float* yp  = d_Y + (size_t)(m0 + yrow) * C0 + c * 64 + koff;
        const float* af  = s_aff + c * 64 + koff;
        const float* af2 = s_aff + 256 + c * 64 + koff;
        uint32_t hi[16], lo[16];
#pragma unroll
        for (int i = 0; i < 32; i += 4) {
            float4 v = *(const float4*)(yp + i);
            float x0 = fmaxf(fmaf(v.x, af[i],     af2[i]),     0.f);
            float x1 = fmaxf(fmaf(v.y, af[i + 1], af2[i + 1]), 0.f);
            float x2 = fmaxf(fmaf(v.z, af[i + 2], af2[i + 2]), 0.f);
            float x3 = fmaxf(fmaf(v.w, af[i + 3], af2[i + 3]), 0.f);
            split_pack(x0, x1, hi[i >> 1], lo[i >> 1]);
            split_pack(x2, x3, hi[(i >> 1) + 1], lo[(i >> 1) + 1]);
        }
#pragma unroll
        for (int uu = 0; uu < 4; uu++) {
            uint32_t off = SW128(yrow * 128 + ((tid & 1) * 4 + uu) * 16);
            asm volatile("st.shared.v4.b32 [%0], {%1,%2,%3,%4};"
                         :: "r"(bH + off), "r"(hi[uu * 4]), "r"(hi[uu * 4 + 1]),
                            "r"(hi[uu * 4 + 2]), "r"(hi[uu * 4 + 3]) : "memory");
            asm volatile("st.shared.v4.b32 [%0], {%1,%2,%3,%4};"
                         :: "r"(bL + off), "r"(lo[uu * 4]), "r"(lo[uu * 4 + 1]),
                            "r"(lo[uu * 4 + 2]), "r"(lo[uu * 4 + 3]) : "memory");
        }
    };

    produce(0, 0);
    asm volatile("cp.async.wait_group 0;" ::: "memory");
    __syncthreads();

    float acc[4][4][4];
#pragma unroll
    for (int i = 0; i < 4; i++)
#pragma unroll
        for (int j = 0; j < 4; j++)
#pragma unroll
            for (int q = 0; q < 4; q++) acc[i][j][q] = 0.f;

    for (int c = 0; c < 4; c++) {
        if (c < 3) produce(c + 1, (c + 1) & 1);

        const uint32_t aH = Wbase + c * 16384, aL = Wbase + 65536 + c * 16384;
        const uint32_t bHb = Bbase + (c & 1) * 32768, bLb = bHb + 16384;
#pragma unroll
        for (int kk = 0; kk < 4; kk++) {
            uint32_t Ah[4][4], Al[4][4], Bh[4][2], Bl[4][2];
#pragma unroll
            for (int mf = 0; mf < 4; mf++) {
                uint32_t off = SW128((wm * 64 + mf * 16 + lrow) * 128 + (kk * 2 + lch) * 16);
                ldsm_x4(Ah[mf], aH + off);
                ldsm_x4(Al[mf], aL + off);
            }
#pragma unroll
            for (int p = 0; p < 2; p++) {
                uint32_t off = SW128((wn * 32 + p * 16 + lrow) * 128 + (kk * 2 + lch) * 16);
                uint32_t r[4];
                ldsm_x4(r, bHb + off);
                Bh[2 * p][0] = r[0]; Bh[2 * p][1] = r[2];
                Bh[2 * p + 1][0] = r[1]; Bh[2 * p + 1][1] = r[3];
                ldsm_x4(r, bLb + off);
                Bl[2 * p][0] = r[0]; Bl[2 * p][1] = r[2];
                Bl[2 * p + 1][0] = r[1]; Bl[2 * p + 1][1] = r[3];
            }
#pragma unroll
            for (int mf = 0; mf < 4; mf++)
#pragma unroll
                for (int nf = 0; nf < 4; nf++) {
                    mma_bf16(acc[mf][nf], Ah[mf], Bh[nf]);
                    mma_bf16(acc[mf][nf], Al[mf], Bh[nf]);
                    mma_bf16(acc[mf][nf], Ah[mf], Bl[nf]);
                }
        }
        __syncthreads();
    }

    // ---- fused BN1 stats ----
    float ssum[4][2] = {}, ssq[4][2] = {};
#pragma unroll
    for (int mf = 0; mf < 4; mf++)
#pragma unroll
        for (int nf = 0; nf < 4; nf++) {
            const float* a = acc[mf][nf];
            ssum[mf][0] += a[0] + a[1];
            ssum[mf][1] += a[2] + a[3];
            ssq[mf][0]  += a[0] * a[0] + a[1] * a[1];
            ssq[mf][1]  += a[2] * a[2] + a[3] * a[3];
        }
#pragma unroll
    for (int mf = 0; mf < 4; mf++)
#pragma unroll
        for (int h = 0; h < 2; h++) {
            float s = ssum[mf][h], q = ssq[mf][h];
            s += __shfl_xor_sync(0xffffffffu, s, 1);
            s += __shfl_xor_sync(0xffffffffu, s, 2);
            q += __shfl_xor_sync(0xffffffffu, q, 1);
            q += __shfl_xor_sync(0xffffffffu, q, 2);
            if ((lane & 3) == 0) {
                int ch = wm * 64 + mf * 16 + (lane >> 2) + h * 8;
                atomicAdd(&d_stats[512 + ch], s);
                atomicAdd(&d_stats[640 + ch], q);
            }
        }

    // ---- store d_Z [c][m] (pt-pairs contiguous => coalesced 32B sectors) ----
#pragma unroll
    for (int mf = 0; mf < 4; mf++)
#pragma unroll
        for (int nf = 0; nf < 4; nf++) {
            int ch = wm * 64 + mf * 16 + (lane >> 2);
            int pt = m0 + wn * 32 + nf * 8 + (lane & 3) * 2;
            *(float2*)(d_Z + (size_t)ch * MTOT + pt) =
                make_float2(acc[mf][nf][0], acc[mf][nf][1]);
            *(float2*)(d_Z + (size_t)(ch + 8) * MTOT + pt) =
                make_float2(acc[mf][nf][2], acc[mf][nf][3]);
        }
}

// ---------------------------------------------------------------------------
// BN1 affine + ReLU + output [B,128,N]; d_Z is [c][m] so both sides coalesced.
// ---------------------------------------------------------------------------
__global__ __launch_bounds__(256)
void output_kernel(float* __restrict__ out)
{
    const int i = blockIdx.x * 256 + threadIdx.x;
    const int base = i * 4;
    const int o = base >> 16;
    const int m = base & 65535;
    const int b = m >> 13;
    const int n = m & 8191;
    float4 v = *(const float4*)(d_Z + (size_t)o * MTOT + m);
    const float sc = d_aff[512 + o];
    const float sh = d_aff[640 + o];
    v.x = fmaxf(fmaf(v.x, sc, sh), 0.f);
    v.y = fmaxf(fmaf(v.y, sc, sh), 0.f);
    v.z = fmaxf(fmaf(v.z, sc, sh), 0.f);
    v.w = fmaxf(fmaf(v.w, sc, sh), 0.f);
    *(float4*)(out + ((size_t)b * C1 + o) * NPTS + n) = v;
}

// ---------------------------------------------------------------------------
extern "C" void kernel_launch(void* const* d_in, const int* in_sizes, int n_in,
                              void* d_out, int out_size)
{
    const float* xyz1    = (const float*)d_in[0];
    const float* xyz2    = (const float*)d_in[1];
    const float* points1 = (const float*)d_in[2];
    const float* points2 = (const float*)d_in[3];
    const float* w0      = (const float*)d_in[4];
    const float* g0      = (const float*)d_in[6];
    const float* be0     = (const float*)d_in[7];
    const float* w1      = (const float*)d_in[8];
    const float* g1      = (const float*)d_in[10];
    const float* be1     = (const float*)d_in[11];
    float* out = (float*)d_out;

    cudaFuncSetAttribute(gemm0_kernel, cudaFuncAttributeMaxDynamicSharedMemorySize, G0_SMEM);
    cudaFuncSetAttribute(gemm1_kernel, cudaFuncAttributeMaxDynamicSharedMemorySize, G1_SMEM);

    zero_stats_kernel<<<1, 768>>>();
    split_w_kernel<<<(C0 * CIN + C1 * C0 + 255) / 256, 256>>>(w0, w1);
    knn_kernel<<<dim3(NPTS / 512, BATCH), 256>>>(xyz1, xyz2);
    transpose_p2_kernel<<<dim3(SPTS / 32, BATCH), 256>>>(points2);
    fused_x_kernel<<<MTOT / 32, 256>>>(points1);

    gemm0_kernel<<<dim3(MTOT / 128, 2), 256, G0_SMEM>>>();
    finalize_kernel<0><<<1, C0>>>(g0, be0);

    gemm1_kernel<<<MTOT / 128, 256, G1_SMEM>>>();
    finalize_kernel<1><<<1, C1>>>(g1, be1);

    output_kernel<<<(C1 * MTOT / 4) / 256, 256>>>(out);
}

// round 7
// speedup vs baseline: 1.4872x; 1.1134x over previous
#include <cuda_runtime.h>
#include <cuda_fp16.h>
#include <cstdint>

#define BATCH 8
#define NPTS  8192
#define SPTS  2048
#define MTOT  65536
#define CIN   384
#define C0    256
#define C1    128

// ------------------------- device scratch -------------------------
__device__ __half d_Xh[(size_t)MTOT * CIN];          // [m][384] fp16, k-contiguous
__device__ float  d_Y[(size_t)MTOT * C0];            // [m][256] ch-contiguous
__device__ float  d_Z[(size_t)C1 * MTOT];            // [c][m]   m-contiguous
__device__ float  d_P2T[(size_t)BATCH * SPTS * C0];  // [b][s][256]
__device__ __half d_W0h[C0 * CIN], d_W0l[C0 * CIN];  // [256][384]
__device__ __half d_W1h[C1 * C0],  d_W1l[C1 * C0];   // [128][256]
__device__ uint4  d_nn[MTOT];
__device__ float  d_stats[768];                      // sum0,sq0 | sum1,sq1
__device__ float  d_aff[768];                        // sc0,sh0  | sc1,sh1

// ------------------------- helpers -------------------------
__device__ __forceinline__ uint32_t smem_u32(const void* p) {
    uint32_t a;
    asm("{ .reg .u64 t; cvta.to.shared.u64 t, %1; cvt.u32.u64 %0, t; }" : "=r"(a) : "l"(p));
    return a;
}
#define SW128(o) ((o) ^ (((o) >> 3) & 0x70))
#define CP_COMMIT() asm volatile("cp.async.commit_group;" ::: "memory")

__device__ __forceinline__ void cp_async16(uint32_t dst, const void* src) {
    size_t g = __cvta_generic_to_global(src);
    asm volatile("cp.async.cg.shared.global [%0], [%1], 16;" :: "r"(dst), "l"(g));
}
__device__ __forceinline__ void ldsm_x4(uint32_t (&r)[4], uint32_t addr) {
    asm volatile("ldmatrix.sync.aligned.m8n8.x4.shared.b16 {%0,%1,%2,%3}, [%4];"
                 : "=r"(r[0]), "=r"(r[1]), "=r"(r[2]), "=r"(r[3]) : "r"(addr));
}
__device__ __forceinline__ void mma_f16(float (&c)[4], const uint32_t (&a)[4],
                                        const uint32_t (&b)[2]) {
    asm volatile(
        "mma.sync.aligned.m16n8k16.row.col.f32.f16.f16.f32 "
        "{%0,%1,%2,%3}, {%4,%5,%6,%7}, {%8,%9}, {%0,%1,%2,%3};"
        : "+f"(c[0]), "+f"(c[1]), "+f"(c[2]), "+f"(c[3])
        : "r"(a[0]), "r"(a[1]), "r"(a[2]), "r"(a[3]), "r"(b[0]), "r"(b[1]));
}
__device__ __forceinline__ uint32_t pack_h2(float v0, float v1) {
    __half2 h = __floats2half2_rn(v0, v1);
    return *reinterpret_cast<uint32_t*>(&h);
}
__device__ __forceinline__ void split_pack(float v0, float v1, uint32_t& h, uint32_t& l) {
    __half h0 = __float2half_rn(v0), h1 = __float2half_rn(v1);
    __half l0 = __float2half_rn(v0 - __half2float(h0));
    __half l1 = __float2half_rn(v1 - __half2float(h1));
    h = (uint32_t)__half_as_ushort(h0) | ((uint32_t)__half_as_ushort(h1) << 16);
    l = (uint32_t)__half_as_ushort(l0) | ((uint32_t)__half_as_ushort(l1) << 16);
}

// ---------------------------------------------------------------------------
__global__ void zero_stats_kernel() { if (threadIdx.x < 768) d_stats[threadIdx.x] = 0.f; }

__global__ __launch_bounds__(256)
void split_w_kernel(const float* __restrict__ w0, const float* __restrict__ w1)
{
    int i = blockIdx.x * 256 + threadIdx.x;
    if (i < C0 * CIN) {
        float v = w0[i];
        __half h = __float2half_rn(v);
        d_W0h[i] = h;
        d_W0l[i] = __float2half_rn(v - __half2float(h));
    }
    int j = i - C0 * CIN;
    if (j >= 0 && j < C1 * C0) {
        float v = w1[j];
        __half h = __float2half_rn(v);
        d_W1h[j] = h;
        d_W1l[j] = __float2half_rn(v - __half2float(h));
    }
}

// ---------------------------------------------------------------------------
// 3-NN search, 2 query points per thread.
// ---------------------------------------------------------------------------
__global__ __launch_bounds__(256)
void knn_kernel(const float* __restrict__ xyz1, const float* __restrict__ xyz2)
{
    __shared__ float4 sp[SPTS];
    const int b = blockIdx.y;
    const int t = threadIdx.x;

    const float* x2 = xyz2 + (size_t)b * 3 * SPTS;
    for (int s = t; s < SPTS; s += 256) {
        float x = x2[s], y = x2[SPTS + s], z = x2[2 * SPTS + s];
        sp[s] = make_float4(-2.f * x, -2.f * y, -2.f * z, x * x + y * y + z * z);
    }
    __syncthreads();

    const int nA = blockIdx.x * 512 + t;
    const int nB = nA + 256;
    const float* x1 = xyz1 + (size_t)b * 3 * NPTS;
    const float ax = x1[nA], ay = x1[NPTS + nA], az = x1[2 * NPTS + nA];
    const float bx = x1[nB], by = x1[NPTS + nB], bz = x1[2 * NPTS + nB];

    float a0 = 3.4e38f, a1 = 3.4e38f, a2 = 3.4e38f;
    float b0 = 3.4e38f, b1 = 3.4e38f, b2 = 3.4e38f;
    int ai0 = 0, ai1 = 0, ai2 = 0, bi0 = 0, bi1 = 0, bi2 = 0;

#pragma unroll 4
    for (int s = 0; s < SPTS; ++s) {
        float4 p = sp[s];
        float ka = fmaf(p.x, ax, fmaf(p.y, ay, fmaf(p.z, az, p.w)));
        float kb = fmaf(p.x, bx, fmaf(p.y, by, fmaf(p.z, bz, p.w)));
        if (ka < a2) {
            if (ka < a1) {
                a2 = a1; ai2 = ai1;
                if (ka < a0) { a1 = a0; ai1 = ai0; a0 = ka; ai0 = s; }
                else         { a1 = ka; ai1 = s; }
            } else { a2 = ka; ai2 = s; }
        }
        if (kb < b2) {
            if (kb < b1) {
                b2 = b1; bi2 = bi1;
                if (kb < b0) { b1 = b0; bi1 = bi0; b0 = kb; bi0 = s; }
                else         { b1 = kb; bi1 = s; }
            } else { b2 = kb; bi2 = s; }
        }
    }

    {
        const float sn = ax * ax + ay * ay + az * az;
        float r0 = 1.f / (a0 + sn + 1e-8f), r1 = 1.f / (a1 + sn + 1e-8f),
              r2 = 1.f / (a2 + sn + 1e-8f);
        float ws = r0 + r1 + r2;
        uint4 o;
        o.x = (uint32_t)ai0 | ((uint32_t)ai1 << 16);
        o.y = (uint32_t)ai2;
        o.z = __float_as_uint(r0 / ws);
        o.w = __float_as_uint(r1 / ws);
        d_nn[b * NPTS + nA] = o;
    }
    {
        const float sn = bx * bx + by * by + bz * bz;
        float r0 = 1.f / (b0 + sn + 1e-8f), r1 = 1.f / (b1 + sn + 1e-8f),
              r2 = 1.f / (b2 + sn + 1e-8f);
        float ws = r0 + r1 + r2;
        uint4 o;
        o.x = (uint32_t)bi0 | ((uint32_t)bi1 << 16);
        o.y = (uint32_t)bi2;
        o.z = __float_as_uint(r0 / ws);
        o.w = __float_as_uint(r1 / ws);
        d_nn[b * NPTS + nB] = o;
    }
}

// ---------------------------------------------------------------------------
// Transpose points2 [b][256][2048] -> d_P2T [b][s][256] fp32.
// ---------------------------------------------------------------------------
__global__ __launch_bounds__(256)
void transpose_p2_kernel(const float* __restrict__ points2)
{
    __shared__ float tile[32][260];
    const int b  = blockIdx.y;
    const int s0 = blockIdx.x * 32;
    const int tx = threadIdx.x & 31;
    const int ty = threadIdx.x >> 5;

    const float* src = points2 + (size_t)b * C0 * SPTS;
#pragma unroll
    for (int k = 0; k < 32; k++) {
        const int ch = ty + k * 8;
        tile[tx][ch] = src[(size_t)ch * SPTS + s0 + tx];
    }
    __syncthreads();

    const int w = threadIdx.x >> 5, lane = threadIdx.x & 31;
#pragma unroll
    for (int k = 0; k < 4; k++) {
        const int s = w + k * 8;
        float* dst = d_P2T + ((size_t)b * SPTS + s0 + s) * C0;
        *(float4*)(dst + lane * 8)     = *(const float4*)(&tile[s][lane * 8]);
        *(float4*)(dst + lane * 8 + 4) = *(const float4*)(&tile[s][lane * 8 + 4]);
    }
}

// ---------------------------------------------------------------------------
// Fused X-builder: warp-per-point, fp16-hi only (no lo plane).
// ---------------------------------------------------------------------------
__global__ __launch_bounds__(256)
void fused_x_kernel(const float* __restrict__ points1)
{
    __shared__ float tile[32][132];
    const int m0 = blockIdx.x * 32;
    const int b  = m0 >> 13;
    const int n0 = m0 & 8191;
    const int tx = threadIdx.x & 31;
    const int ty = threadIdx.x >> 5;

    const float* p1 = points1 + (size_t)b * C1 * NPTS;
#pragma unroll
    for (int k = 0; k < 16; k++) {
        const int ch = ty + k * 8;
        tile[tx][ch] = p1[(size_t)ch * NPTS + n0 + tx];
    }
    __syncthreads();

    const int w = threadIdx.x >> 5, lane = threadIdx.x & 31;
    const float* p2t = d_P2T + (size_t)b * SPTS * C0;

#pragma unroll
    for (int k = 0; k < 4; k++) {
        const int pt = w * 4 + k;
        const int m  = m0 + pt;
        const uint4 nn = d_nn[m];
        const int i0 = nn.x & 0xFFFF, i1 = nn.x >> 16, i2 = nn.y;
        const float w0 = __uint_as_float(nn.z);
        const float w1 = __uint_as_float(nn.w);
        const float w2 = 1.f - w0 - w1;

        const float4* r0 = (const float4*)(p2t + (size_t)i0 * C0);
        const float4* r1 = (const float4*)(p2t + (size_t)i1 * C0);
        const float4* r2 = (const float4*)(p2t + (size_t)i2 * C0);

        uint4 H;
        {
            float4 a0 = r0[lane * 2],     c0 = r1[lane * 2],     e0 = r2[lane * 2];
            float4 a1 = r0[lane * 2 + 1], c1 = r1[lane * 2 + 1], e1 = r2[lane * 2 + 1];
            float v0 = fmaf(a0.x, w0, fmaf(c0.x, w1, e0.x * w2));
            float v1 = fmaf(a0.y, w0, fmaf(c0.y, w1, e0.y * w2));
            float v2 = fmaf(a0.z, w0, fmaf(c0.z, w1, e0.z * w2));
            float v3 = fmaf(a0.w, w0, fmaf(c0.w, w1, e0.w * w2));
            float v4 = fmaf(a1.x, w0, fmaf(c1.x, w1, e1.x * w2));
            float v5 = fmaf(a1.y, w0, fmaf(c1.y, w1, e1.y * w2));
            float v6 = fmaf(a1.z, w0, fmaf(c1.z, w1, e1.z * w2));
            float v7 = fmaf(a1.w, w0, fmaf(c1.w, w1, e1.w * w2));
            H.x = pack_h2(v0, v1);
            H.y = pack_h2(v2, v3);
            H.z = pack_h2(v4, v5);
            H.w = pack_h2(v6, v7);
        }
        __half* xh = d_Xh + (size_t)m * CIN;
        *(uint4*)(xh + lane * 8) = H;               // warp: 512B contiguous

        {
            float4 v = *(const float4*)(&tile[pt][lane * 4]);
            uint2 h;
            h.x = pack_h2(v.x, v.y);
            h.y = pack_h2(v.z, v.w);
            *(uint2*)(xh + C0 + lane * 4) = h;      // warp: 256B contiguous
        }
    }
}

// ---------------------------------------------------------------------------
// GEMM0 (mma.sync fp16, 2-term W-split): Y[m][o] = X[m][:].W0[o][:], K=384.
// CTA: 128 ch x 128 pts. BK=64, 3-stage cp.async (48KB/stage).
// ---------------------------------------------------------------------------
#define G0_STG  49152
#define G0_SMEM (3 * G0_STG)

__global__ __launch_bounds__(256)
void gemm0_kernel()
{
    extern __shared__ char smem[];
    const uint32_t sb = smem_u32(smem);
    const int tid = threadIdx.x;
    const int m0 = blockIdx.x * 128;
    const int ct = blockIdx.y;
    const int w = tid >> 5, lane = tid & 31;
    const int wm = w >> 2, wn = w & 3;
    const int lrow = lane & 15, lch = lane >> 4;

    float acc[4][4][4];
#pragma unroll
    for (int i = 0; i < 4; i++)
#pragma unroll
        for (int j = 0; j < 4; j++)
#pragma unroll
            for (int q = 0; q < 4; q++) acc[i][j][q] = 0.f;

    auto load_chunk = [&](int c, int stage) {
        const int k0 = c * 64;
        const uint32_t stg = sb + stage * G0_STG;
#pragma unroll
        for (int it = 0; it < 12; it++) {
            int u = it * 256 + tid;
            int arr = u >> 10;                      // 0=W0h 1=W0l 2=Xh
            int v = u & 1023;
            int row = v >> 3, un = v & 7;
            uint32_t dst = stg + arr * 16384 + SW128(row * 128 + un * 16);
            const __half* src;
            if (arr == 0)      src = d_W0h + (size_t)(ct * 128 + row) * CIN + k0 + un * 8;
            else if (arr == 1) src = d_W0l + (size_t)(ct * 128 + row) * CIN + k0 + un * 8;
            else               src = d_Xh  + (size_t)(m0 + row) * CIN + k0 + un * 8;
            cp_async16(dst, src);
        }
        CP_COMMIT();
    };

    load_chunk(0, 0);
    load_chunk(1, 1);
    load_chunk(2, 2);

    for (int c = 0; c < 6; c++) {
        if (c <= 3)      asm volatile("cp.async.wait_group 2;" ::: "memory");
        else if (c == 4) asm volatile("cp.async.wait_group 1;" ::: "memory");
        else             asm volatile("cp.async.wait_group 0;" ::: "memory");
        __syncthreads();

        const uint32_t stg = sb + (c % 3) * G0_STG;
        const uint32_t aH = stg, aL = stg + 16384, bHb = stg + 32768;
#pragma unroll
        for (int kk = 0; kk < 4; kk++) {
            uint32_t Ah[4][4], Al[4][4], Bh[4][2];
#pragma unroll
            for (int mf = 0; mf < 4; mf++) {
                uint32_t off = SW128((wm * 64 + mf * 16 + lrow) * 128 + (kk * 2 + lch) * 16);
                ldsm_x4(Ah[mf], aH + off);
                ldsm_x4(Al[mf], aL + off);
            }
#pragma unroll
            for (int p = 0; p < 2; p++) {
                uint32_t off = SW128((wn * 32 + p * 16 + lrow) * 128 + (kk * 2 + lch) * 16);
                uint32_t r[4];
                ldsm_x4(r, bHb + off);
                Bh[2 * p][0] = r[0]; Bh[2 * p][1] = r[2];
                Bh[2 * p + 1][0] = r[1]; Bh[2 * p + 1][1] = r[3];
            }
#pragma unroll
            for (int mf = 0; mf < 4; mf++)
#pragma unroll
                for (int nf = 0; nf < 4; nf++) {
                    mma_f16(acc[mf][nf], Ah[mf], Bh[nf]);
                    mma_f16(acc[mf][nf], Al[mf], Bh[nf]);
                }
        }
        __syncthreads();
        if (c + 3 < 6) load_chunk(c + 3, c % 3);
    }

    // ---- fused BN0 stats via quad-shuffle + atomics ----
    float ssum[4][2] = {}, ssq[4][2] = {};
#pragma unroll
    for (int mf = 0; mf < 4; mf++)
#pragma unroll
        for (int nf = 0; nf < 4; nf++) {
            const float* a = acc[mf][nf];
            ssum[mf][0] += a[0] + a[1];
            ssum[mf][1] += a[2] + a[3];
            ssq[mf][0]  += a[0] * a[0] + a[1] * a[1];
            ssq[mf][1]  += a[2] * a[2] + a[3] * a[3];
        }
#pragma unroll
    for (int mf = 0; mf < 4; mf++)
#pragma unroll
        for (int h = 0; h < 2; h++) {
            float s = ssum[mf][h], q = ssq[mf][h];
            s += __shfl_xor_sync(0xffffffffu, s, 1);
            s += __shfl_xor_sync(0xffffffffu, s, 2);
            q += __shfl_xor_sync(0xffffffffu, q, 1);
            q += __shfl_xor_sync(0xffffffffu, q, 2);
            if ((lane & 3) == 0) {
                int ch = ct * 128 + wm * 64 + mf * 16 + (lane >> 2) + h * 8;
                atomicAdd(&d_stats[ch], s);
                atomicAdd(&d_stats[256 + ch], q);
            }
        }

    // ---- smem transpose -> coalesced d_Y [m][256] ----
    float* st = (float*)smem;
#pragma unroll
    for (int mf = 0; mf < 4; mf++)
#pragma unroll
        for (int nf = 0; nf < 4; nf++) {
            int ch = wm * 64 + mf * 16 + (lane >> 2);
            int pt = wn * 32 + nf * 8 + (lane & 3) * 2;
            st[pt * 132 + ch]           = acc[mf][nf][0];
            st[(pt + 1) * 132 + ch]     = acc[mf][nf][1];
            st[pt * 132 + ch + 8]       = acc[mf][nf][2];
            st[(pt + 1) * 132 + ch + 8] = acc[mf][nf][3];
        }
    __syncthreads();
    {
        const int row = tid >> 1, half = tid & 1;
        float4* dst = (float4*)(d_Y + (size_t)(m0 + row) * C0 + ct * 128 + half * 64);
        const float* sp = st + row * 132 + half * 64;
#pragma unroll
        for (int j = 0; j < 16; j++) dst[j] = *(const float4*)(sp + j * 4);
    }
}

// ---------------------------------------------------------------------------
// finalize BN constants (conv biases cancel under training-mode BN)
// ---------------------------------------------------------------------------
template<int LAYER>
__global__ void finalize_kernel(const float* __restrict__ g, const float* __restrict__ be)
{
    const int c  = threadIdx.x;
    const int o  = LAYER ? 512 : 0;
    const int cc = LAYER ? C1 : C0;
    const float mean = d_stats[o + c] * (1.f / MTOT);
    const float var  = d_stats[o + cc + c] * (1.f / MTOT) - mean * mean;
    const float sc   = g[c] * rsqrtf(var + 1e-5f);
    d_aff[o + c]      = sc;
    d_aff[o + cc + c] = be[c] - mean * sc;
}

// ---------------------------------------------------------------------------
// GEMM1: Z = relu(aff0(Y)) . W1^T, K=256, fp16 3-term split (in-register).
// ---------------------------------------------------------------------------
#define G1_SMEM (2048 + 131072 + 65536)

__global__ __launch_bounds__(256)
void gemm1_kernel()
{
    extern __shared__ char smem[];
    const uint32_t sb = smem_u32(smem);
    float* s_aff = (float*)smem;
    const uint32_t Wbase = sb + 2048;
    const uint32_t Bbase = sb + 2048 + 131072;
    const int tid = threadIdx.x;
    const int m0 = blockIdx.x * 128;
    const int w = tid >> 5, lane = tid & 31;
    const int wm = w >> 2, wn = w & 3;
    const int lrow = lane & 15, lch = lane >> 4;

    for (int i = tid; i < 512; i += 256) s_aff[i] = d_aff[i];

#pragma unroll
    for (int it = 0; it < 32; it++) {
        int u = it * 256 + tid;
        int arr = u >> 12;
        int v = u & 4095;
        int chunk = v >> 10;
        int vv = v & 1023;
        int row = vv >> 3, un = vv & 7;
        uint32_t dst = Wbase + arr * 65536 + chunk * 16384 + SW128(row * 128 + un * 16);
        const __half* src =
            (arr ? d_W1l : d_W1h) + (size_t)row * C0 + chunk * 64 + un * 8;
        cp_async16(dst, src);
    }
    CP_COMMIT();

    auto produce = [&](int c, int buf) {
        const uint32_t bH = Bbase + buf * 32768, bL = bH + 16384;
        const int yrow = tid >> 1;
        const int koff = (tid & 1) * 32;
        const float* yp  = d_Y + (size_t)(m0 + yrow) * C0 + c * 64 + koff;
        const float* af  = s_aff + c * 64 + koff;
        const float* af2 = s_aff + 256 + c * 64 + koff;
        uint32_t hi[16], lo[16];
#pragma unroll
        for (int i = 0; i < 32; i += 4) {
            float4 v = *(const float4*)(yp + i);
            float x0 = fmaxf(fmaf(v.x, af[i],     af2[i]),     0.f);
            float x1 = fmaxf(fmaf(v.y, af[i + 1], af2[i + 1]), 0.f);
            float x2 = fmaxf(fmaf(v.z, af[i + 2], af2[i + 2]), 0.f);
            float x3 = fmaxf(fmaf(v.w, af[i + 3], af2[i + 3]), 0.f);
            split_pack(x0, x1, hi[i >> 1], lo[i >> 1]);
            split_pack(x2, x3, hi[(i >> 1) + 1], lo[(i >> 1) + 1]);
        }
#pragma unroll
        for (int uu = 0; uu < 4; uu++) {
            uint32_t off = SW128(yrow * 128 + ((tid & 1) * 4 + uu) * 16);
            asm volatile("st.shared.v4.b32 [%0], {%1,%2,%3,%4};"
                         :: "r"(bH + off), "r"(hi[uu * 4]), "r"(hi[uu * 4 + 1]),
                            "r"(hi[uu * 4 + 2]), "r"(hi[uu * 4 + 3]) : "memory");
            asm volatile("st.shared.v4.b32 [%0], {%1,%2,%3,%4};"
                         :: "r"(bL + off), "r"(lo[uu * 4]), "r"(lo[uu * 4 + 1]),
                            "r"(lo[uu * 4 + 2]), "r"(lo[uu * 4 + 3]) : "memory");
        }
    };

    produce(0, 0);
    asm volatile("cp.async.wait_group 0;" ::: "memory");
    __syncthreads();

    float acc[4][4][4];
#pragma unroll
    for (int i = 0; i < 4; i++)
#pragma unroll
        for (int j = 0; j < 4; j++)
#pragma unroll
            for (int q = 0; q < 4; q++) acc[i][j][q] = 0.f;

    for (int c = 0; c < 4; c++) {
        if (c < 3) produce(c + 1, (c + 1) & 1);

        const uint32_t aH = Wbase + c * 16384, aL = Wbase + 65536 + c * 16384;
        const uint32_t bHb = Bbase + (c & 1) * 32768, bLb = bHb + 16384;
#pragma unroll
        for (int kk = 0; kk < 4; kk++) {
            uint32_t Ah[4][4], Al[4][4], Bh[4][2], Bl[4][2];
#pragma unroll
            for (int mf = 0; mf < 4; mf++) {
                uint32_t off = SW128((wm * 64 + mf * 16 + lrow) * 128 + (kk * 2 + lch) * 16);
                ldsm_x4(Ah[mf], aH + off);
                ldsm_x4(Al[mf], aL + off);
            }
#pragma unroll
            for (int p = 0; p < 2; p++) {
                uint32_t off = SW128((wn * 32 + p * 16 + lrow) * 128 + (kk * 2 + lch) * 16);
                uint32_t r[4];
                ldsm_x4(r, bHb + off);
                Bh[2 * p][0] = r[0]; Bh[2 * p][1] = r[2];
                Bh[2 * p + 1][0] = r[1]; Bh[2 * p + 1][1] = r[3];
                ldsm_x4(r, bLb + off);
                Bl[2 * p][0] = r[0]; Bl[2 * p][1] = r[2];
                Bl[2 * p + 1][0] = r[1]; Bl[2 * p + 1][1] = r[3];
            }
#pragma unroll
            for (int mf = 0; mf < 4; mf++)
#pragma unroll
                for (int nf = 0; nf < 4; nf++) {
                    mma_f16(acc[mf][nf], Ah[mf], Bh[nf]);
                    mma_f16(acc[mf][nf], Al[mf], Bh[nf]);
                    mma_f16(acc[mf][nf], Ah[mf], Bl[nf]);
                }
        }
        __syncthreads();
    }

    // ---- fused BN1 stats ----
    float ssum[4][2] = {}, ssq[4][2] = {};
#pragma unroll
    for (int mf = 0; mf < 4; mf++)
#pragma unroll
        for (int nf = 0; nf < 4; nf++) {
            const float* a = acc[mf][nf];
            ssum[mf][0] += a[0] + a[1];
            ssum[mf][1] += a[2] + a[3];
            ssq[mf][0]  += a[0] * a[0] + a[1] * a[1];
            ssq[mf][1]  += a[2] * a[2] + a[3] * a[3];
        }
#pragma unroll
    for (int mf = 0; mf < 4; mf++)
#pragma unroll
        for (int h = 0; h < 2; h++) {
            float s = ssum[mf][h], q = ssq[mf][h];
            s += __shfl_xor_sync(0xffffffffu, s, 1);
            s += __shfl_xor_sync(0xffffffffu, s, 2);
            q += __shfl_xor_sync(0xffffffffu, q, 1);
            q += __shfl_xor_sync(0xffffffffu, q, 2);
            if ((lane & 3) == 0) {
                int ch = wm * 64 + mf * 16 + (lane >> 2) + h * 8;
                atomicAdd(&d_stats[512 + ch], s);
                atomicAdd(&d_stats[640 + ch], q);
            }
        }

    // ---- store d_Z [c][m] ----
#pragma unroll
    for (int mf = 0; mf < 4; mf++)
#pragma unroll
        for (int nf = 0; nf < 4; nf++) {
            int ch = wm * 64 + mf * 16 + (lane >> 2);
            int pt = m0 + wn * 32 + nf * 8 + (lane & 3) * 2;
            *(float2*)(d_Z + (size_t)ch * MTOT + pt) =
                make_float2(acc[mf][nf][0], acc[mf][nf][1]);
            *(float2*)(d_Z + (size_t)(ch + 8) * MTOT + pt) =
                make_float2(acc[mf][nf][2], acc[mf][nf][3]);
        }
}

// ---------------------------------------------------------------------------
// BN1 affine + ReLU + output [B,128,N].
// ---------------------------------------------------------------------------
__global__ __launch_bounds__(256)
void output_kernel(float* __restrict__ out)
{
    const int i = blockIdx.x * 256 + threadIdx.x;
    const int base = i * 4;
    const int o = base >> 16;
    const int m = base & 65535;
    const int b = m >> 13;
    const int n = m & 8191;
    float4 v = *(const float4*)(d_Z + (size_t)o * MTOT + m);
    const float sc = d_aff[512 + o];
    const float sh = d_aff[640 + o];
    v.x = fmaxf(fmaf(v.x, sc, sh), 0.f);
    v.y = fmaxf(fmaf(v.y, sc, sh), 0.f);
    v.z = fmaxf(fmaf(v.z, sc, sh), 0.f);
    v.w = fmaxf(fmaf(v.w, sc, sh), 0.f);
    *(float4*)(out + ((size_t)b * C1 + o) * NPTS + n) = v;
}

// ---------------------------------------------------------------------------
extern "C" void kernel_launch(void* const* d_in, const int* in_sizes, int n_in,
                              void* d_out, int out_size)
{
    const float* xyz1    = (const float*)d_in[0];
    const float* xyz2    = (const float*)d_in[1];
    const float* points1 = (const float*)d_in[2];
    const float* points2 = (const float*)d_in[3];
    const float* w0      = (const float*)d_in[4];
    const float* g0      = (const float*)d_in[6];
    const float* be0     = (const float*)d_in[7];
    const float* w1      = (const float*)d_in[8];
    const float* g1      = (const float*)d_in[10];
    const float* be1     = (const float*)d_in[11];
    float* out = (float*)d_out;

    cudaFuncSetAttribute(gemm0_kernel, cudaFuncAttributeMaxDynamicSharedMemorySize, G0_SMEM);
    cudaFuncSetAttribute(gemm1_kernel, cudaFuncAttributeMaxDynamicSharedMemorySize, G1_SMEM);

    zero_stats_kernel<<<1, 768>>>();
    split_w_kernel<<<(C0 * CIN + C1 * C0 + 255) / 256, 256>>>(w0, w1);
    knn_kernel<<<dim3(NPTS / 512, BATCH), 256>>>(xyz1, xyz2);
    transpose_p2_kernel<<<dim3(SPTS / 32, BATCH), 256>>>(points2);
    fused_x_kernel<<<MTOT / 32, 256>>>(points1);

    gemm0_kernel<<<dim3(MTOT / 128, 2), 256, G0_SMEM>>>();
    finalize_kernel<0><<<1, C0>>>(g0, be0);

    gemm1_kernel<<<MTOT / 128, 256, G1_SMEM>>>();
    finalize_kernel<1><<<1, C1>>>(g1, be1);

    output_kernel<<<(C1 * MTOT / 4) / 256, 256>>>(out);
}

// round 8
// speedup vs baseline: 1.5404x; 1.0358x over previous
#include <cuda_runtime.h>
#include <cuda_fp16.h>
#include <cstdint>

#define BATCH 8
#define NPTS  8192
#define SPTS  2048
#define MTOT  65536
#define CIN   384
#define C0    256
#define C1    128

// ------------------------- device scratch -------------------------
__device__ __half d_Xh[(size_t)MTOT * CIN];          // [m][384] fp16, k-contiguous
__device__ float  d_Y[(size_t)MTOT * C0];            // [m][256] ch-contiguous
__device__ float  d_Z[(size_t)C1 * MTOT];            // [c][m]   m-contiguous
__device__ float  d_P2T[(size_t)BATCH * SPTS * C0];  // [b][s][256]
__device__ __half d_W0h[C0 * CIN], d_W0l[C0 * CIN];  // [256][384]
__device__ __half d_W1h[C1 * C0],  d_W1l[C1 * C0];   // [128][256]
__device__ uint4  d_nn[MTOT];
__device__ float  d_stats[768];                      // sum0,sq0 | sum1,sq1
__device__ float  d_aff[768];                        // sc0,sh0  | sc1,sh1

// ------------------------- helpers -------------------------
__device__ __forceinline__ uint32_t smem_u32(const void* p) {
    uint32_t a;
    asm("{ .reg .u64 t; cvta.to.shared.u64 t, %1; cvt.u32.u64 %0, t; }" : "=r"(a) : "l"(p));
    return a;
}
#define SW128(o) ((o) ^ (((o) >> 3) & 0x70))
#define CP_COMMIT() asm volatile("cp.async.commit_group;" ::: "memory")

__device__ __forceinline__ void cp_async16(uint32_t dst, const void* src) {
    size_t g = __cvta_generic_to_global(src);
    asm volatile("cp.async.cg.shared.global [%0], [%1], 16;" :: "r"(dst), "l"(g));
}
__device__ __forceinline__ void ldsm_x4(uint32_t (&r)[4], uint32_t addr) {
    asm volatile("ldmatrix.sync.aligned.m8n8.x4.shared.b16 {%0,%1,%2,%3}, [%4];"
                 : "=r"(r[0]), "=r"(r[1]), "=r"(r[2]), "=r"(r[3]) : "r"(addr));
}
__device__ __forceinline__ void mma_f16(float (&c)[4], const uint32_t (&a)[4],
                                        const uint32_t (&b)[2]) {
    asm volatile(
        "mma.sync.aligned.m16n8k16.row.col.f32.f16.f16.f32 "
        "{%0,%1,%2,%3}, {%4,%5,%6,%7}, {%8,%9}, {%0,%1,%2,%3};"
        : "+f"(c[0]), "+f"(c[1]), "+f"(c[2]), "+f"(c[3])
        : "r"(a[0]), "r"(a[1]), "r"(a[2]), "r"(a[3]), "r"(b[0]), "r"(b[1]));
}
__device__ __forceinline__ uint32_t pack_h2(float v0, float v1) {
    __half2 h = __floats2half2_rn(v0, v1);
    return *reinterpret_cast<uint32_t*>(&h);
}

// ---------------------------------------------------------------------------
// split_w (+ stats zero in block 0)
// ---------------------------------------------------------------------------
__global__ __launch_bounds__(256)
void split_w_kernel(const float* __restrict__ w0, const float* __restrict__ w1)
{
    if (blockIdx.x == 0)
        for (int i = threadIdx.x; i < 768; i += 256) d_stats[i] = 0.f;

    int i = blockIdx.x * 256 + threadIdx.x;
    if (i < C0 * CIN) {
        float v = w0[i];
        __half h = __float2half_rn(v);
        d_W0h[i] = h;
        d_W0l[i] = __float2half_rn(v - __half2float(h));
    }
    int j = i - C0 * CIN;
    if (j >= 0 && j < C1 * C0) {
        float v = w1[j];
        __half h = __float2half_rn(v);
        d_W1h[j] = h;
        d_W1l[j] = __float2half_rn(v - __half2float(h));
    }
}

// ---------------------------------------------------------------------------
// prep: blocks [0,128) = 3-NN search (2 pts/thread); blocks [128,640) =
// points2 transpose -> d_P2T [b][s][256]. Merged to compress launch count.
// ---------------------------------------------------------------------------
__global__ __launch_bounds__(256)
void prep_kernel(const float* __restrict__ xyz1, const float* __restrict__ xyz2,
                 const float* __restrict__ points2)
{
    __shared__ __align__(16) char shmem[33280];

    if (blockIdx.x < 128) {
        // ------------------- kNN -------------------
        float4* sp = (float4*)shmem;
        const int bx = blockIdx.x & 15;
        const int b  = blockIdx.x >> 4;
        const int t  = threadIdx.x;

        const float* x2 = xyz2 + (size_t)b * 3 * SPTS;
        for (int s = t; s < SPTS; s += 256) {
            float x = x2[s], y = x2[SPTS + s], z = x2[2 * SPTS + s];
            sp[s] = make_float4(-2.f * x, -2.f * y, -2.f * z, x * x + y * y + z * z);
        }
        __syncthreads();

        const int nA = bx * 512 + t;
        const int nB = nA + 256;
        const float* x1 = xyz1 + (size_t)b * 3 * NPTS;
        const float ax = x1[nA], ay = x1[NPTS + nA], az = x1[2 * NPTS + nA];
        const float bx2 = x1[nB], by = x1[NPTS + nB], bz = x1[2 * NPTS + nB];

        float a0 = 3.4e38f, a1 = 3.4e38f, a2 = 3.4e38f;
        float b0 = 3.4e38f, b1 = 3.4e38f, b2 = 3.4e38f;
        int ai0 = 0, ai1 = 0, ai2 = 0, bi0 = 0, bi1 = 0, bi2 = 0;

#pragma unroll 4
        for (int s = 0; s < SPTS; ++s) {
            float4 p = sp[s];
            float ka = fmaf(p.x, ax, fmaf(p.y, ay, fmaf(p.z, az, p.w)));
            float kb = fmaf(p.x, bx2, fmaf(p.y, by, fmaf(p.z, bz, p.w)));
            if (ka < a2) {
                if (ka < a1) {
                    a2 = a1; ai2 = ai1;
                    if (ka < a0) { a1 = a0; ai1 = ai0; a0 = ka; ai0 = s; }
                    else         { a1 = ka; ai1 = s; }
                } else { a2 = ka; ai2 = s; }
            }
            if (kb < b2) {
                if (kb < b1) {
                    b2 = b1; bi2 = bi1;
                    if (kb < b0) { b1 = b0; bi1 = bi0; b0 = kb; bi0 = s; }
                    else         { b1 = kb; bi1 = s; }
                } else { b2 = kb; bi2 = s; }
            }
        }

        {
            const float sn = ax * ax + ay * ay + az * az;
            float r0 = 1.f / (a0 + sn + 1e-8f), r1 = 1.f / (a1 + sn + 1e-8f),
                  r2 = 1.f / (a2 + sn + 1e-8f);
            float ws = r0 + r1 + r2;
            uint4 o;
            o.x = (uint32_t)ai0 | ((uint32_t)ai1 << 16);
            o.y = (uint32_t)ai2;
            o.z = __float_as_uint(r0 / ws);
            o.w = __float_as_uint(r1 / ws);
            d_nn[b * NPTS + nA] = o;
        }
        {
            const float sn = bx2 * bx2 + by * by + bz * bz;
            float r0 = 1.f / (b0 + sn + 1e-8f), r1 = 1.f / (b1 + sn + 1e-8f),
                  r2 = 1.f / (b2 + sn + 1e-8f);
            float ws = r0 + r1 + r2;
            uint4 o;
            o.x = (uint32_t)bi0 | ((uint32_t)bi1 << 16);
            o.y = (uint32_t)bi2;
            o.z = __float_as_uint(r0 / ws);
            o.w = __float_as_uint(r1 / ws);
            d_nn[b * NPTS + nB] = o;
        }
    } else {
        // ------------------- transpose points2 -------------------
        float (*tile)[260] = (float(*)[260])shmem;
        const int tb = blockIdx.x - 128;
        const int b  = tb >> 6;
        const int s0 = (tb & 63) * 32;
        const int tx = threadIdx.x & 31;
        const int ty = threadIdx.x >> 5;

        const float* src = points2 + (size_t)b * C0 * SPTS;
#pragma unroll
        for (int k = 0; k < 32; k++) {
            const int ch = ty + k * 8;
            tile[tx][ch] = src[(size_t)ch * SPTS + s0 + tx];
        }
        __syncthreads();

        const int w = threadIdx.x >> 5, lane = threadIdx.x & 31;
#pragma unroll
        for (int k = 0; k < 4; k++) {
            const int s = w + k * 8;
            float* dst = d_P2T + ((size_t)b * SPTS + s0 + s) * C0;
            *(float4*)(dst + lane * 8)     = *(const float4*)(&tile[s][lane * 8]);
            *(float4*)(dst + lane * 8 + 4) = *(const float4*)(&tile[s][lane * 8 + 4]);
        }
    }
}

// ---------------------------------------------------------------------------
// Fused X-builder: warp-per-point, fp16-hi only.
// ---------------------------------------------------------------------------
__global__ __launch_bounds__(256)
void fused_x_kernel(const float* __restrict__ points1)
{
    __shared__ float tile[32][132];
    const int m0 = blockIdx.x * 32;
    const int b  = m0 >> 13;
    const int n0 = m0 & 8191;
    const int tx = threadIdx.x & 31;
    const int ty = threadIdx.x >> 5;

    const float* p1 = points1 + (size_t)b * C1 * NPTS;
#pragma unroll
    for (int k = 0; k < 16; k++) {
        const int ch = ty + k * 8;
        tile[tx][ch] = p1[(size_t)ch * NPTS + n0 + tx];
    }
    __syncthreads();

    const int w = threadIdx.x >> 5, lane = threadIdx.x & 31;
    const float* p2t = d_P2T + (size_t)b * SPTS * C0;

#pragma unroll
    for (int k = 0; k < 4; k++) {
        const int pt = w * 4 + k;
        const int m  = m0 + pt;
        const uint4 nn = d_nn[m];
        const int i0 = nn.x & 0xFFFF, i1 = nn.x >> 16, i2 = nn.y;
        const float w0 = __uint_as_float(nn.z);
        const float w1 = __uint_as_float(nn.w);
        const float w2 = 1.f - w0 - w1;

        const float4* r0 = (const float4*)(p2t + (size_t)i0 * C0);
        const float4* r1 = (const float4*)(p2t + (size_t)i1 * C0);
        const float4* r2 = (const float4*)(p2t + (size_t)i2 * C0);

        uint4 H;
        {
            float4 a0 = r0[lane * 2],     c0 = r1[lane * 2],     e0 = r2[lane * 2];
            float4 a1 = r0[lane * 2 + 1], c1 = r1[lane * 2 + 1], e1 = r2[lane * 2 + 1];
            float v0 = fmaf(a0.x, w0, fmaf(c0.x, w1, e0.x * w2));
            float v1 = fmaf(a0.y, w0, fmaf(c0.y, w1, e0.y * w2));
            float v2 = fmaf(a0.z, w0, fmaf(c0.z, w1, e0.z * w2));
            float v3 = fmaf(a0.w, w0, fmaf(c0.w, w1, e0.w * w2));
            float v4 = fmaf(a1.x, w0, fmaf(c1.x, w1, e1.x * w2));
            float v5 = fmaf(a1.y, w0, fmaf(c1.y, w1, e1.y * w2));
            float v6 = fmaf(a1.z, w0, fmaf(c1.z, w1, e1.z * w2));
            float v7 = fmaf(a1.w, w0, fmaf(c1.w, w1, e1.w * w2));
            H.x = pack_h2(v0, v1);
            H.y = pack_h2(v2, v3);
            H.z = pack_h2(v4, v5);
            H.w = pack_h2(v6, v7);
        }
        __half* xh = d_Xh + (size_t)m * CIN;
        *(uint4*)(xh + lane * 8) = H;

        {
            float4 v = *(const float4*)(&tile[pt][lane * 4]);
            uint2 h;
            h.x = pack_h2(v.x, v.y);
            h.y = pack_h2(v.z, v.w);
            *(uint2*)(xh + C0 + lane * 4) = h;
        }
    }
}

// ---------------------------------------------------------------------------
// GEMM0 (mma.sync fp16, 2-term W-split): Y[m][o] = X[m][:].W0[o][:], K=384.
// CTA: 128 ch x 128 pts. BK=64, 2-stage cp.async (48KB/stage, 2 CTAs/SM).
// ---------------------------------------------------------------------------
#define G0_STG  49152
#define G0_SMEM (2 * G0_STG)

__global__ __launch_bounds__(256, 2)
void gemm0_kernel()
{
    extern __shared__ char smem[];
    const uint32_t sb = smem_u32(smem);
    const int tid = threadIdx.x;
    const int m0 = blockIdx.x * 128;
    const int ct = blockIdx.y;
    const int w = tid >> 5, lane = tid & 31;
    const int wm = w >> 2, wn = w & 3;
    const int lrow = lane & 15, lch = lane >> 4;

    float acc[4][4][4];
#pragma unroll
    for (int i = 0; i < 4; i++)
#pragma unroll
        for (int j = 0; j < 4; j++)
#pragma unroll
            for (int q = 0; q < 4; q++) acc[i][j][q] = 0.f;

    auto load_chunk = [&](int c, int stage) {
        const int k0 = c * 64;
        const uint32_t stg = sb + stage * G0_STG;
#pragma unroll
        for (int it = 0; it < 12; it++) {
            int u = it * 256 + tid;
            int arr = u >> 10;                      // 0=W0h 1=W0l 2=Xh
            int v = u & 1023;
            int row = v >> 3, un = v & 7;
            uint32_t dst = stg + arr * 16384 + SW128(row * 128 + un * 16);
            const __half* src;
            if (arr == 0)      src = d_W0h + (size_t)(ct * 128 + row) * CIN + k0 + un * 8;
            else if (arr == 1) src = d_W0l + (size_t)(ct * 128 + row) * CIN + k0 + un * 8;
            else               src = d_Xh  + (size_t)(m0 + row) * CIN + k0 + un * 8;
            cp_async16(dst, src);
        }
        CP_COMMIT();
    };

    load_chunk(0, 0);
    load_chunk(1, 1);

    for (int c = 0; c < 6; c++) {
        if (c < 5) asm volatile("cp.async.wait_group 1;" ::: "memory");
        else       asm volatile("cp.async.wait_group 0;" ::: "memory");
        __syncthreads();

        const uint32_t stg = sb + (c & 1) * G0_STG;
        const uint32_t aH = stg, aL = stg + 16384, bHb = stg + 32768;
#pragma unroll
        for (int kk = 0; kk < 4; kk++) {
            uint32_t Ah[4][4], Al[4][4], Bh[4][2];
#pragma unroll
            for (int mf = 0; mf < 4; mf++) {
                uint32_t off = SW128((wm * 64 + mf * 16 + lrow) * 128 + (kk * 2 + lch) * 16);
                ldsm_x4(Ah[mf], aH + off);
                ldsm_x4(Al[mf], aL + off);
            }
#pragma unroll
            for (int p = 0; p < 2; p++) {
                uint32_t off = SW128((wn * 32 + p * 16 + lrow) * 128 + (kk * 2 + lch) * 16);
                uint32_t r[4];
                ldsm_x4(r, bHb + off);
                Bh[2 * p][0] = r[0]; Bh[2 * p][1] = r[2];
                Bh[2 * p + 1][0] = r[1]; Bh[2 * p + 1][1] = r[3];
            }
#pragma unroll
            for (int mf = 0; mf < 4; mf++)
#pragma unroll
                for (int nf = 0; nf < 4; nf++) {
                    mma_f16(acc[mf][nf], Ah[mf], Bh[nf]);
                    mma_f16(acc[mf][nf], Al[mf], Bh[nf]);
                }
        }
        __syncthreads();
        if (c + 2 < 6) load_chunk(c + 2, c & 1);
    }

    // ---- fused BN0 stats via quad-shuffle + atomics ----
    float ssum[4][2] = {}, ssq[4][2] = {};
#pragma unroll
    for (int mf = 0; mf < 4; mf++)
#pragma unroll
        for (int nf = 0; nf < 4; nf++) {
            const float* a = acc[mf][nf];
            ssum[mf][0] += a[0] + a[1];
            ssum[mf][1] += a[2] + a[3];
            ssq[mf][0]  += a[0] * a[0] + a[1] * a[1];
            ssq[mf][1]  += a[2] * a[2] + a[3] * a[3];
        }
#pragma unroll
    for (int mf = 0; mf < 4; mf++)
#pragma unroll
        for (int h = 0; h < 2; h++) {
            float s = ssum[mf][h], q = ssq[mf][h];
            s += __shfl_xor_sync(0xffffffffu, s, 1);
            s += __shfl_xor_sync(0xffffffffu, s, 2);
            q += __shfl_xor_sync(0xffffffffu, q, 1);
            q += __shfl_xor_sync(0xffffffffu, q, 2);
            if ((lane & 3) == 0) {
                int ch = ct * 128 + wm * 64 + mf * 16 + (lane >> 2) + h * 8;
                atomicAdd(&d_stats[ch], s);
                atomicAdd(&d_stats[256 + ch], q);
            }
        }

    // ---- smem transpose -> coalesced d_Y [m][256] ----
    float* st = (float*)smem;
#pragma unroll
    for (int mf = 0; mf < 4; mf++)
#pragma unroll
        for (int nf = 0; nf < 4; nf++) {
            int ch = wm * 64 + mf * 16 + (lane >> 2);
            int pt = wn * 32 + nf * 8 + (lane & 3) * 2;
            st[pt * 132 + ch]           = acc[mf][nf][0];
            st[(pt + 1) * 132 + ch]     = acc[mf][nf][1];
            st[pt * 132 + ch + 8]       = acc[mf][nf][2];
            st[(pt + 1) * 132 + ch + 8] = acc[mf][nf][3];
        }
    __syncthreads();
    {
        const int row = tid >> 1, half = tid & 1;
        float4* dst = (float4*)(d_Y + (size_t)(m0 + row) * C0 + ct * 128 + half * 64);
        const float* sp = st + row * 132 + half * 64;
#pragma unroll
        for (int j = 0; j < 16; j++) dst[j] = *(const float4*)(sp + j * 4);
    }
}

// ---------------------------------------------------------------------------
// finalize BN constants (conv biases cancel under training-mode BN)
// ---------------------------------------------------------------------------
template<int LAYER>
__global__ void finalize_kernel(const float* __restrict__ g, const float* __restrict__ be)
{
    const int c  = threadIdx.x;
    const int o  = LAYER ? 512 : 0;
    const int cc = LAYER ? C1 : C0;
    const float mean = d_stats[o + c] * (1.f / MTOT);
    const float var  = d_stats[o + cc + c] * (1.f / MTOT) - mean * mean;
    const float sc   = g[c] * rsqrtf(var + 1e-5f);
    d_aff[o + c]      = sc;
    d_aff[o + cc + c] = be[c] - mean * sc;
}

// ---------------------------------------------------------------------------
// GEMM1: Z = relu(aff0(Y)) . W1^T, K=256, fp16 2-term (W split, B single).
// ---------------------------------------------------------------------------
#define G1_SMEM (2048 + 131072 + 32768)

__global__ __launch_bounds__(256)
void gemm1_kernel()
{
    extern __shared__ char smem[];
    const uint32_t sb = smem_u32(smem);
    float* s_aff = (float*)smem;
    const uint32_t Wbase = sb + 2048;            // Wh 64KB | Wl 64KB
    const uint32_t Bbase = sb + 2048 + 131072;   // 2 x Bh 16KB
    const int tid = threadIdx.x;
    const int m0 = blockIdx.x * 128;
    const int w = tid >> 5, lane = tid & 31;
    const int wm = w >> 2, wn = w & 3;
    const int lrow = lane & 15, lch = lane >> 4;

    for (int i = tid; i < 512; i += 256) s_aff[i] = d_aff[i];

#pragma unroll
    for (int it = 0; it < 32; it++) {
        int u = it * 256 + tid;
        int arr = u >> 12;
        int v = u & 4095;
        int chunk = v >> 10;
        int vv = v & 1023;
        int row = vv >> 3, un = vv & 7;
        uint32_t dst = Wbase + arr * 65536 + chunk * 16384 + SW128(row * 128 + un * 16);
        const __half* src =
            (arr ? d_W1l : d_W1h) + (size_t)row * C0 + chunk * 64 + un * 8;
        cp_async16(dst, src);
    }
    CP_COMMIT();

    auto produce = [&](int c, int buf) {
        const uint32_t bH = Bbase + buf * 16384;
        const int yrow = tid >> 1;
        const int koff = (tid & 1) * 32;
        const float* yp  = d_Y + (size_t)(m0 + yrow) * C0 + c * 64 + koff;
        const float* af  = s_aff + c * 64 + koff;
        const float* af2 = s_aff + 256 + c * 64 + koff;
        uint32_t hi[16];
#pragma unroll
        for (int i = 0; i < 32; i += 4) {
            float4 v = *(const float4*)(yp + i);
            float x0 = fmaxf(fmaf(v.x, af[i],     af2[i]),     0.f);
            float x1 = fmaxf(fmaf(v.y, af[i + 1], af2[i + 1]), 0.f);
            float x2 = fmaxf(fmaf(v.z, af[i + 2], af2[i + 2]), 0.f);
            float x3 = fmaxf(fmaf(v.w, af[i + 3], af2[i + 3]), 0.f);
            hi[i >> 1]       = pack_h2(x0, x1);
            hi[(i >> 1) + 1] = pack_h2(x2, x3);
        }
#pragma unroll
        for (int uu = 0; uu < 4; uu++) {
            uint32_t off = SW128(yrow * 128 + ((tid & 1) * 4 + uu) * 16);
            asm volatile("st.shared.v4.b32 [%0], {%1,%2,%3,%4};"
                         :: "r"(bH + off), "r"(hi[uu * 4]), "r"(hi[uu * 4 + 1]),
                            "r"(hi[uu * 4 + 2]), "r"(hi[uu * 4 + 3]) : "memory");
        }
    };

    produce(0, 0);
    asm volatile("cp.async.wait_group 0;" ::: "memory");
    __syncthreads();

    float acc[4][4][4];
#pragma unroll
    for (int i = 0; i < 4; i++)
#pragma unroll
        for (int j = 0; j < 4; j++)
#pragma unroll
            for (int q = 0; q < 4; q++) acc[i][j][q] = 0.f;

    for (int c = 0; c < 4; c++) {
        if (c < 3) produce(c + 1, (c + 1) & 1);

        const uint32_t aH = Wbase + c * 16384, aL = Wbase + 65536 + c * 16384;
        const uint32_t bHb = Bbase + (c & 1) * 16384;
#pragma unroll
        for (int kk = 0; kk < 4; kk++) {
            uint32_t Ah[4][4], Al[4][4], Bh[4][2];
#pragma unroll
            for (int mf = 0; mf < 4; mf++) {
                uint32_t off = SW128((wm * 64 + mf * 16 + lrow) * 128 + (kk * 2 + lch) * 16);
                ldsm_x4(Ah[mf], aH + off);
                ldsm_x4(Al[mf], aL + off);
            }
#pragma unroll
            for (int p = 0; p < 2; p++) {
                uint32_t off = SW128((wn * 32 + p * 16 + lrow) * 128 + (kk * 2 + lch) * 16);
                uint32_t r[4];
                ldsm_x4(r, bHb + off);
                Bh[2 * p][0] = r[0]; Bh[2 * p][1] = r[2];
                Bh[2 * p + 1][0] = r[1]; Bh[2 * p + 1][1] = r[3];
            }
#pragma unroll
            for (int mf = 0; mf < 4; mf++)
#pragma unroll
                for (int nf = 0; nf < 4; nf++) {
                    mma_f16(acc[mf][nf], Ah[mf], Bh[nf]);
                    mma_f16(acc[mf][nf], Al[mf], Bh[nf]);
                }
        }
        __syncthreads();
    }

    // ---- fused BN1 stats ----
    float ssum[4][2] = {}, ssq[4][2] = {};
#pragma unroll
    for (int mf = 0; mf < 4; mf++)
#pragma unroll
        for (int nf = 0; nf < 4; nf++) {
            const float* a = acc[mf][nf];
            ssum[mf][0] += a[0] + a[1];
            ssum[mf][1] += a[2] + a[3];
            ssq[mf][0]  += a[0] * a[0] + a[1] * a[1];
            ssq[mf][1]  += a[2] * a[2] + a[3] * a[3];
        }
#pragma unroll
    for (int mf = 0; mf < 4; mf++)
#pragma unroll
        for (int h = 0; h < 2; h++) {
            float s = ssum[mf][h], q = ssq[mf][h];
            s += __shfl_xor_sync(0xffffffffu, s, 1);
            s += __shfl_xor_sync(0xffffffffu, s, 2);
            q += __shfl_xor_sync(0xffffffffu, q, 1);
            q += __shfl_xor_sync(0xffffffffu, q, 2);
            if ((lane & 3) == 0) {
                int ch = wm * 64 + mf * 16 + (lane >> 2) + h * 8;
                atomicAdd(&d_stats[512 + ch], s);
                atomicAdd(&d_stats[640 + ch], q);
            }
        }

    // ---- store d_Z [c][m] ----
#pragma unroll
    for (int mf = 0; mf < 4; mf++)
#pragma unroll
        for (int nf = 0; nf < 4; nf++) {
            int ch = wm * 64 + mf * 16 + (lane >> 2);
            int pt = m0 + wn * 32 + nf * 8 + (lane & 3) * 2;
            *(float2*)(d_Z + (size_t)ch * MTOT + pt) =
                make_float2(acc[mf][nf][0], acc[mf][nf][1]);
            *(float2*)(d_Z + (size_t)(ch + 8) * MTOT + pt) =
                make_float2(acc[mf][nf][2], acc[mf][nf][3]);
        }
}

// ---------------------------------------------------------------------------
// BN1 affine + ReLU + output [B,128,N].
// ---------------------------------------------------------------------------
__global__ __launch_bounds__(256)
void output_kernel(float* __restrict__ out)
{
    const int i = blockIdx.x * 256 + threadIdx.x;
    const int base = i * 4;
    const int o = base >> 16;
    const int m = base & 65535;
    const int b = m >> 13;
    const int n = m & 8191;
    float4 v = *(const float4*)(d_Z + (size_t)o * MTOT + m);
    const float sc = d_aff[512 + o];
    const float sh = d_aff[640 + o];
    v.x = fmaxf(fmaf(v.x, sc, sh), 0.f);
    v.y = fmaxf(fmaf(v.y, sc, sh), 0.f);
    v.z = fmaxf(fmaf(v.z, sc, sh), 0.f);
    v.w = fmaxf(fmaf(v.w, sc, sh), 0.f);
    *(float4*)(out + ((size_t)b * C1 + o) * NPTS + n) = v;
}

// ---------------------------------------------------------------------------
extern "C" void kernel_launch(void* const* d_in, const int* in_sizes, int n_in,
                              void* d_out, int out_size)
{
    const float* xyz1    = (const float*)d_in[0];
    const float* xyz2    = (const float*)d_in[1];
    const float* points1 = (const float*)d_in[2];
    const float* points2 = (const float*)d_in[3];
    const float* w0      = (const float*)d_in[4];
    const float* g0      = (const float*)d_in[6];
    const float* be0     = (const float*)d_in[7];
    const float* w1      = (const float*)d_in[8];
    const float* g1      = (const float*)d_in[10];
    const float* be1     = (const float*)d_in[11];
    float* out = (float*)d_out;

    cudaFuncSetAttribute(gemm0_kernel, cudaFuncAttributeMaxDynamicSharedMemorySize, G0_SMEM);
    cudaFuncSetAttribute(gemm1_kernel, cudaFuncAttributeMaxDynamicSharedMemorySize, G1_SMEM);

    split_w_kernel<<<(C0 * CIN + C1 * C0 + 255) / 256, 256>>>(w0, w1);   // (1)
    prep_kernel<<<640, 256>>>(xyz1, xyz2, points2);                      // (2)
    fused_x_kernel<<<MTOT / 32, 256>>>(points1);                         // (3)

    gemm0_kernel<<<dim3(MTOT / 128, 2), 256, G0_SMEM>>>();               // (4) <- profiled
    finalize_kernel<0><<<1, C0>>>(g0, be0);                              // (5)

    gemm1_kernel<<<MTOT / 128, 256, G1_SMEM>>>();                        // (6)
    finalize_kernel<1><<<1, C1>>>(g1, be1);                              // (7)

    output_kernel<<<(C1 * MTOT / 4) / 256, 256>>>(out);                  // (8)
}

// round 9
// speedup vs baseline: 1.5497x; 1.0060x over previous
#include <cuda_runtime.h>
#include <cuda_fp16.h>
#include <cstdint>

#define BATCH 8
#define NPTS  8192
#define SPTS  2048
#define MTOT  65536
#define CIN   384
#define C0    256
#define C1    128

// ------------------------- device scratch -------------------------
__device__ __half d_Xh[(size_t)MTOT * CIN];          // [m][384] fp16, k-contiguous
__device__ float  d_Y[(size_t)MTOT * C0];            // [m][256] ch-contiguous
__device__ float  d_Z[(size_t)C1 * MTOT];            // [c][m]   m-contiguous
__device__ float  d_P2T[(size_t)BATCH * SPTS * C0];  // [b][s][256]
__device__ __half d_W0h[C0 * CIN], d_W0l[C0 * CIN];  // [256][384]
__device__ __half d_W1h[C1 * C0],  d_W1l[C1 * C0];   // [128][256]
__device__ uint4  d_nn[MTOT];
__device__ float  d_stats[768];                      // sum0,sq0 | sum1,sq1
__device__ float  d_aff[768];                        // sc0,sh0  | sc1,sh1

// ------------------------- helpers -------------------------
__device__ __forceinline__ uint32_t smem_u32(const void* p) {
    uint32_t a;
    asm("{ .reg .u64 t; cvta.to.shared.u64 t, %1; cvt.u32.u64 %0, t; }" : "=r"(a) : "l"(p));
    return a;
}
#define SW128(o) ((o) ^ (((o) >> 3) & 0x70))
#define CP_COMMIT() asm volatile("cp.async.commit_group;" ::: "memory")

__device__ __forceinline__ void cp_async16(uint32_t dst, const void* src) {
    size_t g = __cvta_generic_to_global(src);
    asm volatile("cp.async.cg.shared.global [%0], [%1], 16;" :: "r"(dst), "l"(g));
}
__device__ __forceinline__ void ldsm_x4(uint32_t (&r)[4], uint32_t addr) {
    asm volatile("ldmatrix.sync.aligned.m8n8.x4.shared.b16 {%0,%1,%2,%3}, [%4];"
                 : "=r"(r[0]), "=r"(r[1]), "=r"(r[2]), "=r"(r[3]) : "r"(addr));
}
__device__ __forceinline__ void mma_f16(float (&c)[4], const uint32_t (&a)[4],
                                        const uint32_t (&b)[2]) {
    asm volatile(
        "mma.sync.aligned.m16n8k16.row.col.f32.f16.f16.f32 "
        "{%0,%1,%2,%3}, {%4,%5,%6,%7}, {%8,%9}, {%0,%1,%2,%3};"
        : "+f"(c[0]), "+f"(c[1]), "+f"(c[2]), "+f"(c[3])
        : "r"(a[0]), "r"(a[1]), "r"(a[2]), "r"(a[3]), "r"(b[0]), "r"(b[1]));
}
__device__ __forceinline__ uint32_t pack_h2(float v0, float v1) {
    __half2 h = __floats2half2_rn(v0, v1);
    return *reinterpret_cast<uint32_t*>(&h);
}

// ---------------------------------------------------------------------------
// split_w (+ stats zero in block 0)
// ---------------------------------------------------------------------------
__global__ __launch_bounds__(256)
void split_w_kernel(const float* __restrict__ w0, const float* __restrict__ w1)
{
    if (blockIdx.x == 0)
        for (int i = threadIdx.x; i < 768; i += 256) d_stats[i] = 0.f;

    int i = blockIdx.x * 256 + threadIdx.x;
    if (i < C0 * CIN) {
        float v = w0[i];
        __half h = __float2half_rn(v);
        d_W0h[i] = h;
        d_W0l[i] = __float2half_rn(v - __half2float(h));
    }
    int j = i - C0 * CIN;
    if (j >= 0 && j < C1 * C0) {
        float v = w1[j];
        __half h = __float2half_rn(v);
        d_W1h[j] = h;
        d_W1l[j] = __float2half_rn(v - __half2float(h));
    }
}

// ---------------------------------------------------------------------------
// prep: blocks [0,128) = 3-NN search (2 pts/thread); blocks [128,640) =
// points2 transpose -> d_P2T [b][s][256].
// ---------------------------------------------------------------------------
__global__ __launch_bounds__(256)
void prep_kernel(const float* __restrict__ xyz1, const float* __restrict__ xyz2,
                 const float* __restrict__ points2)
{
    __shared__ __align__(16) char shmem[33280];

    if (blockIdx.x < 128) {
        float4* sp = (float4*)shmem;
        const int bx = blockIdx.x & 15;
        const int b  = blockIdx.x >> 4;
        const int t  = threadIdx.x;

        const float* x2 = xyz2 + (size_t)b * 3 * SPTS;
        for (int s = t; s < SPTS; s += 256) {
            float x = x2[s], y = x2[SPTS + s], z = x2[2 * SPTS + s];
            sp[s] = make_float4(-2.f * x, -2.f * y, -2.f * z, x * x + y * y + z * z);
        }
        __syncthreads();

        const int nA = bx * 512 + t;
        const int nB = nA + 256;
        const float* x1 = xyz1 + (size_t)b * 3 * NPTS;
        const float ax = x1[nA], ay = x1[NPTS + nA], az = x1[2 * NPTS + nA];
        const float bx2 = x1[nB], by = x1[NPTS + nB], bz = x1[2 * NPTS + nB];

        float a0 = 3.4e38f, a1 = 3.4e38f, a2 = 3.4e38f;
        float b0 = 3.4e38f, b1 = 3.4e38f, b2 = 3.4e38f;
        int ai0 = 0, ai1 = 0, ai2 = 0, bi0 = 0, bi1 = 0, bi2 = 0;

#pragma unroll 4
        for (int s = 0; s < SPTS; ++s) {
            float4 p = sp[s];
            float ka = fmaf(p.x, ax, fmaf(p.y, ay, fmaf(p.z, az, p.w)));
            float kb = fmaf(p.x, bx2, fmaf(p.y, by, fmaf(p.z, bz, p.w)));
            if (ka < a2) {
                if (ka < a1) {
                    a2 = a1; ai2 = ai1;
                    if (ka < a0) { a1 = a0; ai1 = ai0; a0 = ka; ai0 = s; }
                    else         { a1 = ka; ai1 = s; }
                } else { a2 = ka; ai2 = s; }
            }
            if (kb < b2) {
                if (kb < b1) {
                    b2 = b1; bi2 = bi1;
                    if (kb < b0) { b1 = b0; bi1 = bi0; b0 = kb; bi0 = s; }
                    else         { b1 = kb; bi1 = s; }
                } else { b2 = kb; bi2 = s; }
            }
        }

        {
            const float sn = ax * ax + ay * ay + az * az;
            float r0 = 1.f / (a0 + sn + 1e-8f), r1 = 1.f / (a1 + sn + 1e-8f),
                  r2 = 1.f / (a2 + sn + 1e-8f);
            float ws = r0 + r1 + r2;
            uint4 o;
            o.x = (uint32_t)ai0 | ((uint32_t)ai1 << 16);
            o.y = (uint32_t)ai2;
            o.z = __float_as_uint(r0 / ws);
            o.w = __float_as_uint(r1 / ws);
            d_nn[b * NPTS + nA] = o;
        }
        {
            const float sn = bx2 * bx2 + by * by + bz * bz;
            float r0 = 1.f / (b0 + sn + 1e-8f), r1 = 1.f / (b1 + sn + 1e-8f),
                  r2 = 1.f / (b2 + sn + 1e-8f);
            float ws = r0 + r1 + r2;
            uint4 o;
            o.x = (uint32_t)bi0 | ((uint32_t)bi1 << 16);
            o.y = (uint32_t)bi2;
            o.z = __float_as_uint(r0 / ws);
            o.w = __float_as_uint(r1 / ws);
            d_nn[b * NPTS + nB] = o;
        }
    } else {
        float (*tile)[260] = (float(*)[260])shmem;
        const int tb = blockIdx.x - 128;
        const int b  = tb >> 6;
        const int s0 = (tb & 63) * 32;
        const int tx = threadIdx.x & 31;
        const int ty = threadIdx.x >> 5;

        const float* src = points2 + (size_t)b * C0 * SPTS;
#pragma unroll
        for (int k = 0; k < 32; k++) {
            const int ch = ty + k * 8;
            tile[tx][ch] = src[(size_t)ch * SPTS + s0 + tx];
        }
        __syncthreads();

        const int w = threadIdx.x >> 5, lane = threadIdx.x & 31;
#pragma unroll
        for (int k = 0; k < 4; k++) {
            const int s = w + k * 8;
            float* dst = d_P2T + ((size_t)b * SPTS + s0 + s) * C0;
            *(float4*)(dst + lane * 8)     = *(const float4*)(&tile[s][lane * 8]);
            *(float4*)(dst + lane * 8 + 4) = *(const float4*)(&tile[s][lane * 8 + 4]);
        }
    }
}

// ---------------------------------------------------------------------------
// Fused X-builder: warp-per-point, fp16-hi only.
// ---------------------------------------------------------------------------
__global__ __launch_bounds__(256)
void fused_x_kernel(const float* __restrict__ points1)
{
    __shared__ float tile[32][132];
    const int m0 = blockIdx.x * 32;
    const int b  = m0 >> 13;
    const int n0 = m0 & 8191;
    const int tx = threadIdx.x & 31;
    const int ty = threadIdx.x >> 5;

    const float* p1 = points1 + (size_t)b * C1 * NPTS;
#pragma unroll
    for (int k = 0; k < 16; k++) {
        const int ch = ty + k * 8;
        tile[tx][ch] = p1[(size_t)ch * NPTS + n0 + tx];
    }
    __syncthreads();

    const int w = threadIdx.x >> 5, lane = threadIdx.x & 31;
    const float* p2t = d_P2T + (size_t)b * SPTS * C0;

#pragma unroll
    for (int k = 0; k < 4; k++) {
        const int pt = w * 4 + k;
        const int m  = m0 + pt;
        const uint4 nn = d_nn[m];
        const int i0 = nn.x & 0xFFFF, i1 = nn.x >> 16, i2 = nn.y;
        const float w0 = __uint_as_float(nn.z);
        const float w1 = __uint_as_float(nn.w);
        const float w2 = 1.f - w0 - w1;

        const float4* r0 = (const float4*)(p2t + (size_t)i0 * C0);
        const float4* r1 = (const float4*)(p2t + (size_t)i1 * C0);
        const float4* r2 = (const float4*)(p2t + (size_t)i2 * C0);

        uint4 H;
        {
            float4 a0 = r0[lane * 2],     c0 = r1[lane * 2],     e0 = r2[lane * 2];
            float4 a1 = r0[lane * 2 + 1], c1 = r1[lane * 2 + 1], e1 = r2[lane * 2 + 1];
            float v0 = fmaf(a0.x, w0, fmaf(c0.x, w1, e0.x * w2));
            float v1 = fmaf(a0.y, w0, fmaf(c0.y, w1, e0.y * w2));
            float v2 = fmaf(a0.z, w0, fmaf(c0.z, w1, e0.z * w2));
            float v3 = fmaf(a0.w, w0, fmaf(c0.w, w1, e0.w * w2));
            float v4 = fmaf(a1.x, w0, fmaf(c1.x, w1, e1.x * w2));
            float v5 = fmaf(a1.y, w0, fmaf(c1.y, w1, e1.y * w2));
            float v6 = fmaf(a1.z, w0, fmaf(c1.z, w1, e1.z * w2));
            float v7 = fmaf(a1.w, w0, fmaf(c1.w, w1, e1.w * w2));
            H.x = pack_h2(v0, v1);
            H.y = pack_h2(v2, v3);
            H.z = pack_h2(v4, v5);
            H.w = pack_h2(v6, v7);
        }
        __half* xh = d_Xh + (size_t)m * CIN;
        *(uint4*)(xh + lane * 8) = H;

        {
            float4 v = *(const float4*)(&tile[pt][lane * 4]);
            uint2 h;
            h.x = pack_h2(v.x, v.y);
            h.y = pack_h2(v.z, v.w);
            *(uint2*)(xh + C0 + lane * 4) = h;
        }
    }
}

// ---------------------------------------------------------------------------
// GEMM0 (mma.sync fp16, 2-term W-split): Y[m][o] = X[m][:].W0[o][:], K=384.
// CTA: 128 ch x 128 pts. BK=64, 2-stage cp.async (48KB/stage, 2 CTAs/SM).
// ---------------------------------------------------------------------------
#define G0_STG  49152
#define G0_SMEM (2 * G0_STG)

__global__ __launch_bounds__(256, 2)
void gemm0_kernel()
{
    extern __shared__ char smem[];
    const uint32_t sb = smem_u32(smem);
    const int tid = threadIdx.x;
    const int m0 = blockIdx.x * 128;
    const int ct = blockIdx.y;
    const int w = tid >> 5, lane = tid & 31;
    const int wm = w >> 2, wn = w & 3;
    const int lrow = lane & 15, lch = lane >> 4;

    float acc[4][4][4];
#pragma unroll
    for (int i = 0; i < 4; i++)
#pragma unroll
        for (int j = 0; j < 4; j++)
#pragma unroll
            for (int q = 0; q < 4; q++) acc[i][j][q] = 0.f;

    auto load_chunk = [&](int c, int stage) {
        const int k0 = c * 64;
        const uint32_t stg = sb + stage * G0_STG;
#pragma unroll
        for (int it = 0; it < 12; it++) {
            int u = it * 256 + tid;
            int arr = u >> 10;                      // 0=W0h 1=W0l 2=Xh
            int v = u & 1023;
            int row = v >> 3, un = v & 7;
            uint32_t dst = stg + arr * 16384 + SW128(row * 128 + un * 16);
            const __half* src;
            if (arr == 0)      src = d_W0h + (size_t)(ct * 128 + row) * CIN + k0 + un * 8;
            else if (arr == 1) src = d_W0l + (size_t)(ct * 128 + row) * CIN + k0 + un * 8;
            else               src = d_Xh  + (size_t)(m0 + row) * CIN + k0 + un * 8;
            cp_async16(dst, src);
        }
        CP_COMMIT();
    };

    load_chunk(0, 0);
    load_chunk(1, 1);

    for (int c = 0; c < 6; c++) {
        if (c < 5) asm volatile("cp.async.wait_group 1;" ::: "memory");
        else       asm volatile("cp.async.wait_group 0;" ::: "memory");
        __syncthreads();

        const uint32_t stg = sb + (c & 1) * G0_STG;
        const uint32_t aH = stg, aL = stg + 16384, bHb = stg + 32768;
#pragma unroll
        for (int kk = 0; kk < 4; kk++) {
            uint32_t Ah[4][4], Al[4][4], Bh[4][2];
#pragma unroll
            for (int mf = 0; mf < 4; mf++) {
                uint32_t off = SW128((wm * 64 + mf * 16 + lrow) * 128 + (kk * 2 + lch) * 16);
                ldsm_x4(Ah[mf], aH + off);
                ldsm_x4(Al[mf], aL + off);
            }
#pragma unroll
            for (int p = 0; p < 2; p++) {
                uint32_t off = SW128((wn * 32 + p * 16 + lrow) * 128 + (kk * 2 + lch) * 16);
                uint32_t r[4];
                ldsm_x4(r, bHb + off);
                Bh[2 * p][0] = r[0]; Bh[2 * p][1] = r[2];
                Bh[2 * p + 1][0] = r[1]; Bh[2 * p + 1][1] = r[3];
            }
#pragma unroll
            for (int mf = 0; mf < 4; mf++)
#pragma unroll
                for (int nf = 0; nf < 4; nf++) {
                    mma_f16(acc[mf][nf], Ah[mf], Bh[nf]);
                    mma_f16(acc[mf][nf], Al[mf], Bh[nf]);
                }
        }
        __syncthreads();
        if (c + 2 < 6) load_chunk(c + 2, c & 1);
    }

    // ---- fused BN0 stats via quad-shuffle + atomics ----
    float ssum[4][2] = {}, ssq[4][2] = {};
#pragma unroll
    for (int mf = 0; mf < 4; mf++)
#pragma unroll
        for (int nf = 0; nf < 4; nf++) {
            const float* a = acc[mf][nf];
            ssum[mf][0] += a[0] + a[1];
            ssum[mf][1] += a[2] + a[3];
            ssq[mf][0]  += a[0] * a[0] + a[1] * a[1];
            ssq[mf][1]  += a[2] * a[2] + a[3] * a[3];
        }
#pragma unroll
    for (int mf = 0; mf < 4; mf++)
#pragma unroll
        for (int h = 0; h < 2; h++) {
            float s = ssum[mf][h], q = ssq[mf][h];
            s += __shfl_xor_sync(0xffffffffu, s, 1);
            s += __shfl_xor_sync(0xffffffffu, s, 2);
            q += __shfl_xor_sync(0xffffffffu, q, 1);
            q += __shfl_xor_sync(0xffffffffu, q, 2);
            if ((lane & 3) == 0) {
                int ch = ct * 128 + wm * 64 + mf * 16 + (lane >> 2) + h * 8;
                atomicAdd(&d_stats[ch], s);
                atomicAdd(&d_stats[256 + ch], q);
            }
        }

    // ---- smem transpose -> coalesced d_Y [m][256] ----
    float* st = (float*)smem;
#pragma unroll
    for (int mf = 0; mf < 4; mf++)
#pragma unroll
        for (int nf = 0; nf < 4; nf++) {
            int ch = wm * 64 + mf * 16 + (lane >> 2);
            int pt = wn * 32 + nf * 8 + (lane & 3) * 2;
            st[pt * 132 + ch]           = acc[mf][nf][0];
            st[(pt + 1) * 132 + ch]     = acc[mf][nf][1];
            st[pt * 132 + ch + 8]       = acc[mf][nf][2];
            st[(pt + 1) * 132 + ch + 8] = acc[mf][nf][3];
        }
    __syncthreads();
    {
        const int row = tid >> 1, half = tid & 1;
        float4* dst = (float4*)(d_Y + (size_t)(m0 + row) * C0 + ct * 128 + half * 64);
        const float* sp = st + row * 132 + half * 64;
#pragma unroll
        for (int j = 0; j < 16; j++) dst[j] = *(const float4*)(sp + j * 4);
    }
}

// ---------------------------------------------------------------------------
// finalize BN constants (conv biases cancel under training-mode BN)
// ---------------------------------------------------------------------------
template<int LAYER>
__global__ void finalize_kernel(const float* __restrict__ g, const float* __restrict__ be)
{
    const int c  = threadIdx.x;
    const int o  = LAYER ? 512 : 0;
    const int cc = LAYER ? C1 : C0;
    const float mean = d_stats[o + c] * (1.f / MTOT);
    const float var  = d_stats[o + cc + c] * (1.f / MTOT) - mean * mean;
    const float sc   = g[c] * rsqrtf(var + 1e-5f);
    d_aff[o + c]      = sc;
    d_aff[o + cc + c] = be[c] - mean * sc;
}

// ---------------------------------------------------------------------------
// GEMM1: Z = relu(aff0(Y)) . W1^T, K=256, fp16 2-term (W split, B single).
// Streamed like gemm0: 2-stage 48KB (Wh|Wl via cp.async, B produced in-reg),
// 2 CTAs/SM. W1 is L2-resident so per-chunk re-reads are cheap.
// ---------------------------------------------------------------------------
#define G1_STG  49152
#define G1_SMEM (2048 + 2 * G1_STG)

__global__ __launch_bounds__(256, 2)
void gemm1_kernel()
{
    extern __shared__ char smem[];
    const uint32_t sb = smem_u32(smem);
    float* s_aff = (float*)smem;                 // 512 floats
    const int tid = threadIdx.x;
    const int m0 = blockIdx.x * 128;
    const int w = tid >> 5, lane = tid & 31;
    const int wm = w >> 2, wn = w & 3;
    const int lrow = lane & 15, lch = lane >> 4;

    for (int i = tid; i < 512; i += 256) s_aff[i] = d_aff[i];
    __syncthreads();   // s_aff visible before any produce()

    auto load_chunk = [&](int c, int stage) {
        const int k0 = c * 64;
        const uint32_t stg = sb + 2048 + stage * G1_STG;
        // W1h/W1l chunk tiles via cp.async (2048 16B units, 8/thread)
#pragma unroll
        for (int it = 0; it < 8; it++) {
            int u = it * 256 + tid;
            int arr = u >> 10;                    // 0=Wh 1=Wl
            int v = u & 1023;
            int row = v >> 3, un = v & 7;
            uint32_t dst = stg + arr * 16384 + SW128(row * 128 + un * 16);
            const __half* src = (arr ? d_W1l : d_W1h) + (size_t)row * C0 + k0 + un * 8;
            cp_async16(dst, src);
        }
        CP_COMMIT();
        // B: affine+relu+fp16 from d_Y, stored swizzled (yrow = point row)
        const uint32_t bB = stg + 32768;
        const int yrow = tid >> 1;
        const int koff = (tid & 1) * 32;
        const float* yp  = d_Y + (size_t)(m0 + yrow) * C0 + c * 64 + koff;
        const float* af  = s_aff + c * 64 + koff;
        const float* af2 = s_aff + 256 + c * 64 + koff;
        uint32_t hi[16];
#pragma unroll
        for (int i = 0; i < 32; i += 4) {
            float4 v = *(const float4*)(yp + i);
            float x0 = fmaxf(fmaf(v.x, af[i],     af2[i]),     0.f);
            float x1 = fmaxf(fmaf(v.y, af[i + 1], af2[i + 1]), 0.f);
            float x2 = fmaxf(fmaf(v.z, af[i + 2], af2[i + 2]), 0.f);
            float x3 = fmaxf(fmaf(v.w, af[i + 3], af2[i + 3]), 0.f);
            hi[i >> 1]       = pack_h2(x0, x1);
            hi[(i >> 1) + 1] = pack_h2(x2, x3);
        }
#pragma unroll
        for (int uu = 0; uu < 4; uu++) {
            uint32_t off = SW128(yrow * 128 + ((tid & 1) * 4 + uu) * 16);
            asm volatile("st.shared.v4.b32 [%0], {%1,%2,%3,%4};"
                         :: "r"(bB + off), "r"(hi[uu * 4]), "r"(hi[uu * 4 + 1]),
                            "r"(hi[uu * 4 + 2]), "r"(hi[uu * 4 + 3]) : "memory");
        }
    };

    float acc[4][4][4];
#pragma unroll
    for (int i = 0; i < 4; i++)
#pragma unroll
        for (int j = 0; j < 4; j++)
#pragma unroll
            for (int q = 0; q < 4; q++) acc[i][j][q] = 0.f;

    load_chunk(0, 0);
    load_chunk(1, 1);

    for (int c = 0; c < 4; c++) {
        if (c < 3) asm volatile("cp.async.wait_group 1;" ::: "memory");
        else       asm volatile("cp.async.wait_group 0;" ::: "memory");
        __syncthreads();

        const uint32_t stg = sb + 2048 + (c & 1) * G1_STG;
        const uint32_t aH = stg, aL = stg + 16384, bHb = stg + 32768;
#pragma unroll
        for (int kk = 0; kk < 4; kk++) {
            uint32_t Ah[4][4], Al[4][4], Bh[4][2];
#pragma unroll
            for (int mf = 0; mf < 4; mf++) {
                uint32_t off = SW128((wm * 64 + mf * 16 + lrow) * 128 + (kk * 2 + lch) * 16);
                ldsm_x4(Ah[mf], aH + off);
                ldsm_x4(Al[mf], aL + off);
            }
#pragma unroll
            for (int p = 0; p < 2; p++) {
                uint32_t off = SW128((wn * 32 + p * 16 + lrow) * 128 + (kk * 2 + lch) * 16);
                uint32_t r[4];
                ldsm_x4(r, bHb + off);
                Bh[2 * p][0] = r[0]; Bh[2 * p][1] = r[2];
                Bh[2 * p + 1][0] = r[1]; Bh[2 * p + 1][1] = r[3];
            }
#pragma unroll
            for (int mf = 0; mf < 4; mf++)
#pragma unroll
                for (int nf = 0; nf < 4; nf++) {
                    mma_f16(acc[mf][nf], Ah[mf], Bh[nf]);
                    mma_f16(acc[mf][nf], Al[mf], Bh[nf]);
                }
        }
        __syncthreads();
        if (c + 2 < 4) load_chunk(c + 2, c & 1);
    }

    // ---- fused BN1 stats ----
    float ssum[4][2] = {}, ssq[4][2] = {};
#pragma unroll
    for (int mf = 0; mf < 4; mf++)
#pragma unroll
        for (int nf = 0; nf < 4; nf++) {
            const float* a = acc[mf][nf];
            ssum[mf][0] += a[0] + a[1];
            ssum[mf][1] += a[2] + a[3];
            ssq[mf][0]  += a[0] * a[0] + a[1] * a[1];
            ssq[mf][1]  += a[2] * a[2] + a[3] * a[3];
        }
#pragma unroll
    for (int mf = 0; mf < 4; mf++)
#pragma unroll
        for (int h = 0; h < 2; h++) {
            float s = ssum[mf][h], q = ssq[mf][h];
            s += __shfl_xor_sync(0xffffffffu, s, 1);
            s += __shfl_xor_sync(0xffffffffu, s, 2);
            q += __shfl_xor_sync(0xffffffffu, q, 1);
            q += __shfl_xor_sync(0xffffffffu, q, 2);
            if ((lane & 3) == 0) {
                int ch = wm * 64 + mf * 16 + (lane >> 2) + h * 8;
                atomicAdd(&d_stats[512 + ch], s);
                atomicAdd(&d_stats[640 + ch], q);
            }
        }

    // ---- store d_Z [c][m] ----
#pragma unroll
    for (int mf = 0; mf < 4; mf++)
#pragma unroll
        for (int nf = 0; nf < 4; nf++) {
            int ch = wm * 64 + mf * 16 + (lane >> 2);
            int pt = m0 + wn * 32 + nf * 8 + (lane & 3) * 2;
            *(float2*)(d_Z + (size_t)ch * MTOT + pt) =
                make_float2(acc[mf][nf][0], acc[mf][nf][1]);
            *(float2*)(d_Z + (size_t)(ch + 8) * MTOT + pt) =
                make_float2(acc[mf][nf][2], acc[mf][nf][3]);
        }
}

// ---------------------------------------------------------------------------
// BN1 affine + ReLU + output [B,128,N].
// ---------------------------------------------------------------------------
__global__ __launch_bounds__(256)
void output_kernel(float* __restrict__ out)
{
    const int i = blockIdx.x * 256 + threadIdx.x;
    const int base = i * 4;
    const int o = base >> 16;
    const int m = base & 65535;
    const int b = m >> 13;
    const int n = m & 8191;
    float4 v = *(const float4*)(d_Z + (size_t)o * MTOT + m);
    const float sc = d_aff[512 + o];
    const float sh = d_aff[640 + o];
    v.x = fmaxf(fmaf(v.x, sc, sh), 0.f);
    v.y = fmaxf(fmaf(v.y, sc, sh), 0.f);
    v.z = fmaxf(fmaf(v.z, sc, sh), 0.f);
    v.w = fmaxf(fmaf(v.w, sc, sh), 0.f);
    *(float4*)(out + ((size_t)b * C1 + o) * NPTS + n) = v;
}

// ---------------------------------------------------------------------------
extern "C" void kernel_launch(void* const* d_in, const int* in_sizes, int n_in,
                              void* d_out, int out_size)
{
    const float* xyz1    = (const float*)d_in[0];
    const float* xyz2    = (const float*)d_in[1];
    const float* points1 = (const float*)d_in[2];
    const float* points2 = (const float*)d_in[3];
    const float* w0      = (const float*)d_in[4];
    const float* g0      = (const float*)d_in[6];
    const float* be0     = (const float*)d_in[7];
    const float* w1      = (const float*)d_in[8];
    const float* g1      = (const float*)d_in[10];
    const float* be1     = (const float*)d_in[11];
    float* out = (float*)d_out;

    cudaFuncSetAttribute(gemm0_kernel, cudaFuncAttributeMaxDynamicSharedMemorySize, G0_SMEM);
    cudaFuncSetAttribute(gemm1_kernel, cudaFuncAttributeMaxDynamicSharedMemorySize, G1_SMEM);

    split_w_kernel<<<(C0 * CIN + C1 * C0 + 255) / 256, 256>>>(w0, w1);   // (1)
    prep_kernel<<<640, 256>>>(xyz1, xyz2, points2);                      // (2)
    fused_x_kernel<<<MTOT / 32, 256>>>(points1);                         // (3)

    gemm0_kernel<<<dim3(MTOT / 128, 2), 256, G0_SMEM>>>();               // (4)
    finalize_kernel<0><<<1, C0>>>(g0, be0);                              // (5)

    gemm1_kernel<<<MTOT / 128, 256, G1_SMEM>>>();                        // (6)
    finalize_kernel<1><<<1, C1>>>(g1, be1);                              // (7)

    output_kernel<<<(C1 * MTOT / 4) / 256, 256>>>(out);                  // (8)
}

// round 11
// speedup vs baseline: 1.8071x; 1.1661x over previous
#include <cuda_runtime.h>
#include <cuda_fp16.h>
#include <cstdint>

#define BATCH 8
#define NPTS  8192
#define SPTS  2048
#define MTOT  65536
#define CIN   384
#define C0    256
#define C1    128

// ------------------------- device scratch -------------------------
__device__ __half d_Xh[(size_t)MTOT * CIN];          // [m][384] fp16, k-contiguous
__device__ float  d_Y[(size_t)MTOT * C0];            // [m][256] ch-contiguous
__device__ float  d_Z[(size_t)C1 * MTOT];            // [c][m]   m-contiguous
__device__ float  d_P2T[(size_t)BATCH * SPTS * C0];  // [b][s][256]
__device__ __half d_W0h[C0 * CIN];                   // [256][384]
__device__ __half d_W1h[C1 * C0];                    // [128][256]
__device__ uint4  d_nn[MTOT];
__device__ float  d_stats[768];                      // sum0,sq0 | sum1,sq1
__device__ float  d_aff[768];                        // sc0,sh0  | sc1,sh1

// ------------------------- helpers -------------------------
__device__ __forceinline__ uint32_t smem_u32(const void* p) {
    uint32_t a;
    asm("{ .reg .u64 t; cvta.to.shared.u64 t, %1; cvt.u32.u64 %0, t; }" : "=r"(a) : "l"(p));
    return a;
}
#define SW128(o) ((o) ^ (((o) >> 3) & 0x70))
#define CP_COMMIT() asm volatile("cp.async.commit_group;" ::: "memory")

__device__ __forceinline__ void cp_async16(uint32_t dst, const void* src) {
    size_t g = __cvta_generic_to_global(src);
    asm volatile("cp.async.cg.shared.global [%0], [%1], 16;" :: "r"(dst), "l"(g));
}
__device__ __forceinline__ void ldsm_x4(uint32_t (&r)[4], uint32_t addr) {
    asm volatile("ldmatrix.sync.aligned.m8n8.x4.shared.b16 {%0,%1,%2,%3}, [%4];"
                 : "=r"(r[0]), "=r"(r[1]), "=r"(r[2]), "=r"(r[3]) : "r"(addr));
}
__device__ __forceinline__ void mma_f16(float (&c)[4], const uint32_t (&a)[4],
                                        const uint32_t (&b)[2]) {
    asm volatile(
        "mma.sync.aligned.m16n8k16.row.col.f32.f16.f16.f32 "
        "{%0,%1,%2,%3}, {%4,%5,%6,%7}, {%8,%9}, {%0,%1,%2,%3};"
        : "+f"(c[0]), "+f"(c[1]), "+f"(c[2]), "+f"(c[3])
        : "r"(a[0]), "r"(a[1]), "r"(a[2]), "r"(a[3]), "r"(b[0]), "r"(b[1]));
}
__device__ __forceinline__ uint32_t pack_h2(float v0, float v1) {
    __half2 h = __floats2half2_rn(v0, v1);
    return *reinterpret_cast<uint32_t*>(&h);
}

// ---------------------------------------------------------------------------
// split_w0: convert W0 -> fp16 (+ stats zero in block 0)
// ---------------------------------------------------------------------------
__global__ __launch_bounds__(256)
void split_w0_kernel(const float* __restrict__ w0)
{
    if (blockIdx.x == 0)
        for (int i = threadIdx.x; i < 768; i += 256) d_stats[i] = 0.f;
    int i = blockIdx.x * 256 + threadIdx.x;
    if (i < C0 * CIN) d_W0h[i] = __float2half_rn(w0[i]);
}

// split_w1: convert W1 -> fp16
__global__ __launch_bounds__(256)
void split_w1_kernel(const float* __restrict__ w1)
{
    int i = blockIdx.x * 256 + threadIdx.x;
    if (i < C1 * C0) d_W1h[i] = __float2half_rn(w1[i]);
}

// ---------------------------------------------------------------------------
// prep: blocks [0,128) = 3-NN search (2 pts/thread); blocks [128,640) =
// points2 transpose -> d_P2T [b][s][256].
// ---------------------------------------------------------------------------
__global__ __launch_bounds__(256)
void prep_kernel(const float* __restrict__ xyz1, const float* __restrict__ xyz2,
                 const float* __restrict__ points2)
{
    __shared__ __align__(16) char shmem[33280];

    if (blockIdx.x < 128) {
        float4* sp = (float4*)shmem;
        const int bx = blockIdx.x & 15;
        const int b  = blockIdx.x >> 4;
        const int t  = threadIdx.x;

        const float* x2 = xyz2 + (size_t)b * 3 * SPTS;
        for (int s = t; s < SPTS; s += 256) {
            float x = x2[s], y = x2[SPTS + s], z = x2[2 * SPTS + s];
            sp[s] = make_float4(-2.f * x, -2.f * y, -2.f * z, x * x + y * y + z * z);
        }
        __syncthreads();

        const int nA = bx * 512 + t;
        const int nB = nA + 256;
        const float* x1 = xyz1 + (size_t)b * 3 * NPTS;
        const float ax = x1[nA], ay = x1[NPTS + nA], az = x1[2 * NPTS + nA];
        const float bx2 = x1[nB], by = x1[NPTS + nB], bz = x1[2 * NPTS + nB];

        float a0 = 3.4e38f, a1 = 3.4e38f, a2 = 3.4e38f;
        float b0 = 3.4e38f, b1 = 3.4e38f, b2 = 3.4e38f;
        int ai0 = 0, ai1 = 0, ai2 = 0, bi0 = 0, bi1 = 0, bi2 = 0;

#pragma unroll 4
        for (int s = 0; s < SPTS; ++s) {
            float4 p = sp[s];
            float ka = fmaf(p.x, ax, fmaf(p.y, ay, fmaf(p.z, az, p.w)));
            float kb = fmaf(p.x, bx2, fmaf(p.y, by, fmaf(p.z, bz, p.w)));
            if (ka < a2) {
                if (ka < a1) {
                    a2 = a1; ai2 = ai1;
                    if (ka < a0) { a1 = a0; ai1 = ai0; a0 = ka; ai0 = s; }
                    else         { a1 = ka; ai1 = s; }
                } else { a2 = ka; ai2 = s; }
            }
            if (kb < b2) {
                if (kb < b1) {
                    b2 = b1; bi2 = bi1;
                    if (kb < b0) { b1 = b0; bi1 = bi0; b0 = kb; bi0 = s; }
                    else         { b1 = kb; bi1 = s; }
                } else { b2 = kb; bi2 = s; }
            }
        }

        {
            const float sn = ax * ax + ay * ay + az * az;
            float r0 = 1.f / (a0 + sn + 1e-8f), r1 = 1.f / (a1 + sn + 1e-8f),
                  r2 = 1.f / (a2 + sn + 1e-8f);
            float ws = r0 + r1 + r2;
            uint4 o;
            o.x = (uint32_t)ai0 | ((uint32_t)ai1 << 16);
            o.y = (uint32_t)ai2;
            o.z = __float_as_uint(r0 / ws);
            o.w = __float_as_uint(r1 / ws);
            d_nn[b * NPTS + nA] = o;
        }
        {
            const float sn = bx2 * bx2 + by * by + bz * bz;
            float r0 = 1.f / (b0 + sn + 1e-8f), r1 = 1.f / (b1 + sn + 1e-8f),
                  r2 = 1.f / (b2 + sn + 1e-8f);
            float ws = r0 + r1 + r2;
            uint4 o;
            o.x = (uint32_t)bi0 | ((uint32_t)bi1 << 16);
            o.y = (uint32_t)bi2;
            o.z = __float_as_uint(r0 / ws);
            o.w = __float_as_uint(r1 / ws);
            d_nn[b * NPTS + nB] = o;
        }
    } else {
        float (*tile)[260] = (float(*)[260])shmem;
        const int tb = blockIdx.x - 128;
        const int b  = tb >> 6;
        const int s0 = (tb & 63) * 32;
        const int tx = threadIdx.x & 31;
        const int ty = threadIdx.x >> 5;

        const float* src = points2 + (size_t)b * C0 * SPTS;
#pragma unroll
        for (int k = 0; k < 32; k++) {
            const int ch = ty + k * 8;
            tile[tx][ch] = src[(size_t)ch * SPTS + s0 + tx];
        }
        __syncthreads();

        const int w = threadIdx.x >> 5, lane = threadIdx.x & 31;
#pragma unroll
        for (int k = 0; k < 4; k++) {
            const int s = w + k * 8;
            float* dst = d_P2T + ((size_t)b * SPTS + s0 + s) * C0;
            *(float4*)(dst + lane * 8)     = *(const float4*)(&tile[s][lane * 8]);
            *(float4*)(dst + lane * 8 + 4) = *(const float4*)(&tile[s][lane * 8 + 4]);
        }
    }
}

// ---------------------------------------------------------------------------
// Fused X-builder: warp-per-point, fp16-hi only.
// ---------------------------------------------------------------------------
__global__ __launch_bounds__(256)
void fused_x_kernel(const float* __restrict__ points1)
{
    __shared__ float tile[32][132];
    const int m0 = blockIdx.x * 32;
    const int b  = m0 >> 13;
    const int n0 = m0 & 8191;
    const int tx = threadIdx.x & 31;
    const int ty = threadIdx.x >> 5;

    const float* p1 = points1 + (size_t)b * C1 * NPTS;
#pragma unroll
    for (int k = 0; k < 16; k++) {
        const int ch = ty + k * 8;
        tile[tx][ch] = p1[(size_t)ch * NPTS + n0 + tx];
    }
    __syncthreads();

    const int w = threadIdx.x >> 5, lane = threadIdx.x & 31;
    const float* p2t = d_P2T + (size_t)b * SPTS * C0;

#pragma unroll
    for (int k = 0; k < 4; k++) {
        const int pt = w * 4 + k;
        const int m  = m0 + pt;
        const uint4 nn = d_nn[m];
        const int i0 = nn.x & 0xFFFF, i1 = nn.x >> 16, i2 = nn.y;
        const float w0 = __uint_as_float(nn.z);
        const float w1 = __uint_as_float(nn.w);
        const float w2 = 1.f - w0 - w1;

        const float4* r0 = (const float4*)(p2t + (size_t)i0 * C0);
        const float4* r1 = (const float4*)(p2t + (size_t)i1 * C0);
        const float4* r2 = (const float4*)(p2t + (size_t)i2 * C0);

        uint4 H;
        {
            float4 a0 = r0[lane * 2],     c0 = r1[lane * 2],     e0 = r2[lane * 2];
            float4 a1 = r0[lane * 2 + 1], c1 = r1[lane * 2 + 1], e1 = r2[lane * 2 + 1];
            float v0 = fmaf(a0.x, w0, fmaf(c0.x, w1, e0.x * w2));
            float v1 = fmaf(a0.y, w0, fmaf(c0.y, w1, e0.y * w2));
            float v2 = fmaf(a0.z, w0, fmaf(c0.z, w1, e0.z * w2));
            float v3 = fmaf(a0.w, w0, fmaf(c0.w, w1, e0.w * w2));
            float v4 = fmaf(a1.x, w0, fmaf(c1.x, w1, e1.x * w2));
            float v5 = fmaf(a1.y, w0, fmaf(c1.y, w1, e1.y * w2));
            float v6 = fmaf(a1.z, w0, fmaf(c1.z, w1, e1.z * w2));
            float v7 = fmaf(a1.w, w0, fmaf(c1.w, w1, e1.w * w2));
            H.x = pack_h2(v0, v1);
            H.y = pack_h2(v2, v3);
            H.z = pack_h2(v4, v5);
            H.w = pack_h2(v6, v7);
        }
        __half* xh = d_Xh + (size_t)m * CIN;
        *(uint4*)(xh + lane * 8) = H;

        {
            float4 v = *(const float4*)(&tile[pt][lane * 4]);
            uint2 h;
            h.x = pack_h2(v.x, v.y);
            h.y = pack_h2(v.z, v.w);
            *(uint2*)(xh + C0 + lane * 4) = h;
        }
    }
}

// ---------------------------------------------------------------------------
// GEMM0 (mma.sync fp16, single-term): Y[m][o] = X[m][:].W0[o][:], K=384.
// CTA: 128 ch x 128 pts. BK=64, 2-stage cp.async (32KB/stage, 2 CTAs/SM).
// ---------------------------------------------------------------------------
#define G0_STG  32768
#define G0_SMEM 69632   // max(2*G0_STG, 128*132*4 epilogue transpose)

__global__ __launch_bounds__(256, 2)
void gemm0_kernel()
{
    extern __shared__ char smem[];
    const uint32_t sb = smem_u32(smem);
    const int tid = threadIdx.x;
    const int m0 = blockIdx.x * 128;
    const int ct = blockIdx.y;
    const int w = tid >> 5, lane = tid & 31;
    const int wm = w >> 2, wn = w & 3;
    const int lrow = lane & 15, lch = lane >> 4;

    float acc[4][4][4];
#pragma unroll
    for (int i = 0; i < 4; i++)
#pragma unroll
        for (int j = 0; j < 4; j++)
#pragma unroll
            for (int q = 0; q < 4; q++) acc[i][j][q] = 0.f;

    auto load_chunk = [&](int c, int stage) {
        const int k0 = c * 64;
        const uint32_t stg = sb + stage * G0_STG;
#pragma unroll
        for (int it = 0; it < 8; it++) {
            int u = it * 256 + tid;
            int arr = u >> 10;                      // 0=W0h 1=Xh
            int v = u & 1023;
            int row = v >> 3, un = v & 7;
            uint32_t dst = stg + arr * 16384 + SW128(row * 128 + un * 16);
            const __half* src;
            if (arr == 0) src = d_W0h + (size_t)(ct * 128 + row) * CIN + k0 + un * 8;
            else          src = d_Xh  + (size_t)(m0 + row) * CIN + k0 + un * 8;
            cp_async16(dst, src);
        }
        CP_COMMIT();
    };

    load_chunk(0, 0);
    load_chunk(1, 1);

    for (int c = 0; c < 6; c++) {
        if (c < 5) asm volatile("cp.async.wait_group 1;" ::: "memory");
        else       asm volatile("cp.async.wait_group 0;" ::: "memory");
        __syncthreads();

        const uint32_t stg = sb + (c & 1) * G0_STG;
        const uint32_t aH = stg, bHb = stg + 16384;
#pragma unroll
        for (int kk = 0; kk < 4; kk++) {
            uint32_t Ah[4][4], Bh[4][2];
#pragma unroll
            for (int mf = 0; mf < 4; mf++) {
                uint32_t off = SW128((wm * 64 + mf * 16 + lrow) * 128 + (kk * 2 + lch) * 16);
                ldsm_x4(Ah[mf], aH + off);
            }
#pragma unroll
            for (int p = 0; p < 2; p++) {
                uint32_t off = SW128((wn * 32 + p * 16 + lrow) * 128 + (kk * 2 + lch) * 16);
                uint32_t r[4];
                ldsm_x4(r, bHb + off);
                Bh[2 * p][0] = r[0]; Bh[2 * p][1] = r[2];
                Bh[2 * p + 1][0] = r[1]; Bh[2 * p + 1][1] = r[3];
            }
#pragma unroll
            for (int mf = 0; mf < 4; mf++)
#pragma unroll
                for (int nf = 0; nf < 4; nf++)
                    mma_f16(acc[mf][nf], Ah[mf], Bh[nf]);
        }
        __syncthreads();
        if (c + 2 < 6) load_chunk(c + 2, c & 1);
    }

    // ---- fused BN0 stats via quad-shuffle + atomics ----
    float ssum[4][2] = {}, ssq[4][2] = {};
#pragma unroll
    for (int mf = 0; mf < 4; mf++)
#pragma unroll
        for (int nf = 0; nf < 4; nf++) {
            const float* a = acc[mf][nf];
            ssum[mf][0] += a[0] + a[1];
            ssum[mf][1] += a[2] + a[3];
            ssq[mf][0]  += a[0] * a[0] + a[1] * a[1];
            ssq[mf][1]  += a[2] * a[2] + a[3] * a[3];
        }
#pragma unroll
    for (int mf = 0; mf < 4; mf++)
#pragma unroll
        for (int h = 0; h < 2; h++) {
            float s = ssum[mf][h], q = ssq[mf][h];
            s += __shfl_xor_sync(0xffffffffu, s, 1);
            s += __shfl_xor_sync(0xffffffffu, s, 2);
            q += __shfl_xor_sync(0xffffffffu, q, 1);
            q += __shfl_xor_sync(0xffffffffu, q, 2);
            if ((lane & 3) == 0) {
                int ch = ct * 128 + wm * 64 + mf * 16 + (lane >> 2) + h * 8;
                atomicAdd(&d_stats[ch], s);
                atomicAdd(&d_stats[256 + ch], q);
            }
        }

    // ---- smem transpose -> coalesced d_Y [m][256] ----
    float* st = (float*)smem;
#pragma unroll
    for (int mf = 0; mf < 4; mf++)
#pragma unroll
        for (int nf = 0; nf < 4; nf++) {
            int ch = wm * 64 + mf * 16 + (lane >> 2);
            int pt = wn * 32 + nf * 8 + (lane & 3) * 2;
            st[pt * 132 + ch]           = acc[mf][nf][0];
            st[(pt + 1) * 132 + ch]     = acc[mf][nf][1];
            st[pt * 132 + ch + 8]       = acc[mf][nf][2];
            st[(pt + 1) * 132 + ch + 8] = acc[mf][nf][3];
        }
    __syncthreads();
    {
        const int row = tid >> 1, half = tid & 1;
        float4* dst = (float4*)(d_Y + (size_t)(m0 + row) * C0 + ct * 128 + half * 64);
        const float* sp = st + row * 132 + half * 64;
#pragma unroll
        for (int j = 0; j < 16; j++) dst[j] = *(const float4*)(sp + j * 4);
    }
}

// ---------------------------------------------------------------------------
// finalize BN constants (conv biases cancel under training-mode BN)
// ---------------------------------------------------------------------------
template<int LAYER>
__global__ void finalize_kernel(const float* __restrict__ g, const float* __restrict__ be)
{
    const int c  = threadIdx.x;
    const int o  = LAYER ? 512 : 0;
    const int cc = LAYER ? C1 : C0;
    const float mean = d_stats[o + c] * (1.f / MTOT);
    const float var  = d_stats[o + cc + c] * (1.f / MTOT) - mean * mean;
    const float sc   = g[c] * rsqrtf(var + 1e-5f);
    d_aff[o + c]      = sc;
    d_aff[o + cc + c] = be[c] - mean * sc;
}

// ---------------------------------------------------------------------------
// GEMM1: Z = relu(aff0(Y)) . W1^T, K=256, single-term fp16. 2-stage 32KB.
// ---------------------------------------------------------------------------
#define G1_STG  32768
#define G1_SMEM (2048 + 2 * G1_STG)

__global__ __launch_bounds__(256, 2)
void gemm1_kernel()
{
    extern __shared__ char smem[];
    const uint32_t sb = smem_u32(smem);
    float* s_aff = (float*)smem;                 // 512 floats
    const int tid = threadIdx.x;
    const int m0 = blockIdx.x * 128;
    const int w = tid >> 5, lane = tid & 31;
    const int wm = w >> 2, wn = w & 3;
    const int lrow = lane & 15, lch = lane >> 4;

    for (int i = tid; i < 512; i += 256) s_aff[i] = d_aff[i];
    __syncthreads();

    auto load_chunk = [&](int c, int stage) {
        const int k0 = c * 64;
        const uint32_t stg = sb + 2048 + stage * G1_STG;
        // W1h chunk tile via cp.async (1024 16B units, 4/thread)
#pragma unroll
        for (int it = 0; it < 4; it++) {
            int u = it * 256 + tid;
            int row = u >> 3, un = u & 7;
            uint32_t dst = stg + SW128(row * 128 + un * 16);
            const __half* src = d_W1h + (size_t)row * C0 + k0 + un * 8;
            cp_async16(dst, src);
        }
        CP_COMMIT();
        // B: affine+relu+fp16 from d_Y, stored swizzled
        const uint32_t bB = stg + 16384;
        const int yrow = tid >> 1;
        const int koff = (tid & 1) * 32;
        const float* yp  = d_Y + (size_t)(m0 + yrow) * C0 + c * 64 + koff;
        const float* af  = s_aff + c * 64 + koff;
        const float* af2 = s_aff + 256 + c * 64 + koff;
        uint32_t hi[16];
#pragma unroll
        for (int i = 0; i < 32; i += 4) {
            float4 v = *(const float4*)(yp + i);
            float x0 = fmaxf(fmaf(v.x, af[i],     af2[i]),     0.f);
            float x1 = fmaxf(fmaf(v.y, af[i + 1], af2[i + 1]), 0.f);
            float x2 = fmaxf(fmaf(v.z, af[i + 2], af2[i + 2]), 0.f);
            float x3 = fmaxf(fmaf(v.w, af[i + 3], af2[i + 3]), 0.f);
            hi[i >> 1]       = pack_h2(x0, x1);
            hi[(i >> 1) + 1] = pack_h2(x2, x3);
        }
#pragma unroll
        for (int uu = 0; uu < 4; uu++) {
            uint32_t off = SW128(yrow * 128 + ((tid & 1) * 4 + uu) * 16);
            asm volatile("st.shared.v4.b32 [%0], {%1,%2,%3,%4};"
                         :: "r"(bB + off), "r"(hi[uu * 4]), "r"(hi[uu * 4 + 1]),
                            "r"(hi[uu * 4 + 2]), "r"(hi[uu * 4 + 3]) : "memory");
        }
    };

    float acc[4][4][4];
#pragma unroll
    for (int i = 0; i < 4; i++)
#pragma unroll
        for (int j = 0; j < 4; j++)
#pragma unroll
            for (int q = 0; q < 4; q++) acc[i][j][q] = 0.f;

    load_chunk(0, 0);
    load_chunk(1, 1);

    for (int c = 0; c < 4; c++) {
        if (c < 3) asm volatile("cp.async.wait_group 1;" ::: "memory");
        else       asm volatile("cp.async.wait_group 0;" ::: "memory");
        __syncthreads();

        const uint32_t stg = sb + 2048 + (c & 1) * G1_STG;
        const uint32_t aH = stg, bHb = stg + 16384;
#pragma unroll
        for (int kk = 0; kk < 4; kk++) {
            uint32_t Ah[4][4], Bh[4][2];
#pragma unroll
            for (int mf = 0; mf < 4; mf++) {
                uint32_t off = SW128((wm * 64 + mf * 16 + lrow) * 128 + (kk * 2 + lch) * 16);
                ldsm_x4(Ah[mf], aH + off);
            }
#pragma unroll
            for (int p = 0; p < 2; p++) {
                uint32_t off = SW128((wn * 32 + p * 16 + lrow) * 128 + (kk * 2 + lch) * 16);
                uint32_t r[4];
                ldsm_x4(r, bHb + off);
                Bh[2 * p][0] = r[0]; Bh[2 * p][1] = r[2];
                Bh[2 * p + 1][0] = r[1]; Bh[2 * p + 1][1] = r[3];
            }
#pragma unroll
            for (int mf = 0; mf < 4; mf++)
#pragma unroll
                for (int nf = 0; nf < 4; nf++)
                    mma_f16(acc[mf][nf], Ah[mf], Bh[nf]);
        }
        __syncthreads();
        if (c + 2 < 4) load_chunk(c + 2, c & 1);
    }

    // ---- fused BN1 stats ----
    float ssum[4][2] = {}, ssq[4][2] = {};
#pragma unroll
    for (int mf = 0; mf < 4; mf++)
#pragma unroll
        for (int nf = 0; nf < 4; nf++) {
            const float* a = acc[mf][nf];
            ssum[mf][0] += a[0] + a[1];
            ssum[mf][1] += a[2] + a[3];
            ssq[mf][0]  += a[0] * a[0] + a[1] * a[1];
            ssq[mf][1]  += a[2] * a[2] + a[3] * a[3];
        }
#pragma unroll
    for (int mf = 0; mf < 4; mf++)
#pragma unroll
        for (int h = 0; h < 2; h++) {
            float s = ssum[mf][h], q = ssq[mf][h];
            s += __shfl_xor_sync(0xffffffffu, s, 1);
            s += __shfl_xor_sync(0xffffffffu, s, 2);
            q += __shfl_xor_sync(0xffffffffu, q, 1);
            q += __shfl_xor_sync(0xffffffffu, q, 2);
            if ((lane & 3) == 0) {
                int ch = wm * 64 + mf * 16 + (lane >> 2) + h * 8;
                atomicAdd(&d_stats[512 + ch], s);
                atomicAdd(&d_stats[640 + ch], q);
            }
        }

    // ---- store d_Z [c][m] ----
#pragma unroll
    for (int mf = 0; mf < 4; mf++)
#pragma unroll
        for (int nf = 0; nf < 4; nf++) {
            int ch = wm * 64 + mf * 16 + (lane >> 2);
            int pt = m0 + wn * 32 + nf * 8 + (lane & 3) * 2;
            *(float2*)(d_Z + (size_t)ch * MTOT + pt) =
                make_float2(acc[mf][nf][0], acc[mf][nf][1]);
            *(float2*)(d_Z + (size_t)(ch + 8) * MTOT + pt) =
                make_float2(acc[mf][nf][2], acc[mf][nf][3]);
        }
}

// ---------------------------------------------------------------------------
// BN1 affine + ReLU + output [B,128,N].
// ---------------------------------------------------------------------------
__global__ __launch_bounds__(256)
void output_kernel(float* __restrict__ out)
{
    const int i = blockIdx.x * 256 + threadIdx.x;
    const int base = i * 4;
    const int o = base >> 16;
    const int m = base & 65535;
    const int b = m >> 13;
    const int n = m & 8191;
    float4 v = *(const float4*)(d_Z + (size_t)o * MTOT + m);
    const float sc = d_aff[512 + o];
    const float sh = d_aff[640 + o];
    v.x = fmaxf(fmaf(v.x, sc, sh), 0.f);
    v.y = fmaxf(fmaf(v.y, sc, sh), 0.f);
    v.z = fmaxf(fmaf(v.z, sc, sh), 0.f);
    v.w = fmaxf(fmaf(v.w, sc, sh), 0.f);
    *(float4*)(out + ((size_t)b * C1 + o) * NPTS + n) = v;
}

// ---------------------------------------------------------------------------
extern "C" void kernel_launch(void* const* d_in, const int* in_sizes, int n_in,
                              void* d_out, int out_size)
{
    const float* xyz1    = (const float*)d_in[0];
    const float* xyz2    = (const float*)d_in[1];
    const float* points1 = (const float*)d_in[2];
    const float* points2 = (const float*)d_in[3];
    const float* w0      = (const float*)d_in[4];
    const float* g0      = (const float*)d_in[6];
    const float* be0     = (const float*)d_in[7];
    const float* w1      = (const float*)d_in[8];
    const float* g1      = (const float*)d_in[10];
    const float* be1     = (const float*)d_in[11];
    float* out = (float*)d_out;

    cudaFuncSetAttribute(gemm0_kernel, cudaFuncAttributeMaxDynamicSharedMemorySize, G0_SMEM);
    cudaFuncSetAttribute(gemm1_kernel, cudaFuncAttributeMaxDynamicSharedMemorySize, G1_SMEM);

    prep_kernel<<<640, 256>>>(xyz1, xyz2, points2);                      // (1)
    split_w0_kernel<<<(C0 * CIN + 255) / 256, 256>>>(w0);                // (2)
    split_w1_kernel<<<(C1 * C0 + 255) / 256, 256>>>(w1);                 // (3)
    fused_x_kernel<<<MTOT / 32, 256>>>(points1);                         // (4) <- profiled

    gemm0_kernel<<<dim3(MTOT / 128, 2), 256, G0_SMEM>>>();               // (5)
    finalize_kernel<0><<<1, C0>>>(g0, be0);                              // (6)

    gemm1_kernel<<<MTOT / 128, 256, G1_SMEM>>>();                        // (7)
    finalize_kernel<1><<<1, C1>>>(g1, be1);                              // (8)

    output_kernel<<<(C1 * MTOT / 4) / 256, 256>>>(out);                  // (9)
}

// round 12
// speedup vs baseline: 1.9326x; 1.0695x over previous
#include <cuda_runtime.h>
#include <cuda_fp16.h>
#include <cstdint>

#define BATCH 8
#define NPTS  8192
#define SPTS  2048
#define MTOT  65536
#define CIN   384
#define C0    256
#define C1    128

// ------------------------- device scratch -------------------------
__device__ __half d_Xh[(size_t)MTOT * CIN];          // [m][384] fp16, k-contiguous
__device__ __half d_Y[(size_t)MTOT * C0];            // [m][256] fp16 (raw conv0 out)
__device__ __half d_Z[(size_t)C1 * MTOT];            // [c][m]   fp16 (raw conv1 out)
__device__ float  d_P2T[(size_t)BATCH * SPTS * C0];  // [b][s][256]
__device__ __half d_W0h[C0 * CIN];                   // [256][384]
__device__ __half d_W1h[C1 * C0];                    // [128][256]
__device__ uint4  d_nn[MTOT];
__device__ float  d_stats[768];                      // sum0,sq0 | sum1,sq1
__device__ float  d_aff[768];                        // sc0,sh0  | sc1,sh1

// ------------------------- helpers -------------------------
__device__ __forceinline__ uint32_t smem_u32(const void* p) {
    uint32_t a;
    asm("{ .reg .u64 t; cvta.to.shared.u64 t, %1; cvt.u32.u64 %0, t; }" : "=r"(a) : "l"(p));
    return a;
}
#define SW128(o) ((o) ^ (((o) >> 3) & 0x70))
#define CP_COMMIT() asm volatile("cp.async.commit_group;" ::: "memory")

__device__ __forceinline__ void cp_async16(uint32_t dst, const void* src) {
    size_t g = __cvta_generic_to_global(src);
    asm volatile("cp.async.cg.shared.global [%0], [%1], 16;" :: "r"(dst), "l"(g));
}
__device__ __forceinline__ void ldsm_x4(uint32_t (&r)[4], uint32_t addr) {
    asm volatile("ldmatrix.sync.aligned.m8n8.x4.shared.b16 {%0,%1,%2,%3}, [%4];"
                 : "=r"(r[0]), "=r"(r[1]), "=r"(r[2]), "=r"(r[3]) : "r"(addr));
}
__device__ __forceinline__ void mma_f16(float (&c)[4], const uint32_t (&a)[4],
                                        const uint32_t (&b)[2]) {
    asm volatile(
        "mma.sync.aligned.m16n8k16.row.col.f32.f16.f16.f32 "
        "{%0,%1,%2,%3}, {%4,%5,%6,%7}, {%8,%9}, {%0,%1,%2,%3};"
        : "+f"(c[0]), "+f"(c[1]), "+f"(c[2]), "+f"(c[3])
        : "r"(a[0]), "r"(a[1]), "r"(a[2]), "r"(a[3]), "r"(b[0]), "r"(b[1]));
}
__device__ __forceinline__ uint32_t pack_h2(float v0, float v1) {
    __half2 h = __floats2half2_rn(v0, v1);
    return *reinterpret_cast<uint32_t*>(&h);
}

// ---------------------------------------------------------------------------
// split_w: W0+W1 -> fp16 (+ stats zero in block 0)
// ---------------------------------------------------------------------------
__global__ __launch_bounds__(256)
void split_w_kernel(const float* __restrict__ w0, const float* __restrict__ w1)
{
    if (blockIdx.x == 0)
        for (int i = threadIdx.x; i < 768; i += 256) d_stats[i] = 0.f;
    int i = blockIdx.x * 256 + threadIdx.x;
    if (i < C0 * CIN) d_W0h[i] = __float2half_rn(w0[i]);
    int j = i - C0 * CIN;
    if (j >= 0 && j < C1 * C0) d_W1h[j] = __float2half_rn(w1[j]);
}

// ---------------------------------------------------------------------------
// prep: blocks [0,128) = 3-NN search (2 pts/thread); blocks [128,640) =
// points2 transpose -> d_P2T [b][s][256].
// ---------------------------------------------------------------------------
__global__ __launch_bounds__(256)
void prep_kernel(const float* __restrict__ xyz1, const float* __restrict__ xyz2,
                 const float* __restrict__ points2)
{
    __shared__ __align__(16) char shmem[33280];

    if (blockIdx.x < 128) {
        float4* sp = (float4*)shmem;
        const int bx = blockIdx.x & 15;
        const int b  = blockIdx.x >> 4;
        const int t  = threadIdx.x;

        const float* x2 = xyz2 + (size_t)b * 3 * SPTS;
        for (int s = t; s < SPTS; s += 256) {
            float x = x2[s], y = x2[SPTS + s], z = x2[2 * SPTS + s];
            sp[s] = make_float4(-2.f * x, -2.f * y, -2.f * z, x * x + y * y + z * z);
        }
        __syncthreads();

        const int nA = bx * 512 + t;
        const int nB = nA + 256;
        const float* x1 = xyz1 + (size_t)b * 3 * NPTS;
        const float ax = x1[nA], ay = x1[NPTS + nA], az = x1[2 * NPTS + nA];
        const float bx2 = x1[nB], by = x1[NPTS + nB], bz = x1[2 * NPTS + nB];

        float a0 = 3.4e38f, a1 = 3.4e38f, a2 = 3.4e38f;
        float b0 = 3.4e38f, b1 = 3.4e38f, b2 = 3.4e38f;
        int ai0 = 0, ai1 = 0, ai2 = 0, bi0 = 0, bi1 = 0, bi2 = 0;

#pragma unroll 4
        for (int s = 0; s < SPTS; ++s) {
            float4 p = sp[s];
            float ka = fmaf(p.x, ax, fmaf(p.y, ay, fmaf(p.z, az, p.w)));
            float kb = fmaf(p.x, bx2, fmaf(p.y, by, fmaf(p.z, bz, p.w)));
            if (ka < a2) {
                if (ka < a1) {
                    a2 = a1; ai2 = ai1;
                    if (ka < a0) { a1 = a0; ai1 = ai0; a0 = ka; ai0 = s; }
                    else         { a1 = ka; ai1 = s; }
                } else { a2 = ka; ai2 = s; }
            }
            if (kb < b2) {
                if (kb < b1) {
                    b2 = b1; bi2 = bi1;
                    if (kb < b0) { b1 = b0; bi1 = bi0; b0 = kb; bi0 = s; }
                    else         { b1 = kb; bi1 = s; }
                } else { b2 = kb; bi2 = s; }
            }
        }

        {
            const float sn = ax * ax + ay * ay + az * az;
            float r0 = 1.f / (a0 + sn + 1e-8f), r1 = 1.f / (a1 + sn + 1e-8f),
                  r2 = 1.f / (a2 + sn + 1e-8f);
            float ws = r0 + r1 + r2;
            uint4 o;
            o.x = (uint32_t)ai0 | ((uint32_t)ai1 << 16);
            o.y = (uint32_t)ai2;
            o.z = __float_as_uint(r0 / ws);
            o.w = __float_as_uint(r1 / ws);
            d_nn[b * NPTS + nA] = o;
        }
        {
            const float sn = bx2 * bx2 + by * by + bz * bz;
            float r0 = 1.f / (b0 + sn + 1e-8f), r1 = 1.f / (b1 + sn + 1e-8f),
                  r2 = 1.f / (b2 + sn + 1e-8f);
            float ws = r0 + r1 + r2;
            uint4 o;
            o.x = (uint32_t)bi0 | ((uint32_t)bi1 << 16);
            o.y = (uint32_t)bi2;
            o.z = __float_as_uint(r0 / ws);
            o.w = __float_as_uint(r1 / ws);
            d_nn[b * NPTS + nB] = o;
        }
    } else {
        float (*tile)[260] = (float(*)[260])shmem;
        const int tb = blockIdx.x - 128;
        const int b  = tb >> 6;
        const int s0 = (tb & 63) * 32;
        const int tx = threadIdx.x & 31;
        const int ty = threadIdx.x >> 5;

        const float* src = points2 + (size_t)b * C0 * SPTS;
#pragma unroll
        for (int k = 0; k < 32; k++) {
            const int ch = ty + k * 8;
            tile[tx][ch] = src[(size_t)ch * SPTS + s0 + tx];
        }
        __syncthreads();

        const int w = threadIdx.x >> 5, lane = threadIdx.x & 31;
#pragma unroll
        for (int k = 0; k < 4; k++) {
            const int s = w + k * 8;
            float* dst = d_P2T + ((size_t)b * SPTS + s0 + s) * C0;
            *(float4*)(dst + lane * 8)     = *(const float4*)(&tile[s][lane * 8]);
            *(float4*)(dst + lane * 8 + 4) = *(const float4*)(&tile[s][lane * 8 + 4]);
        }
    }
}

// ---------------------------------------------------------------------------
// Fused X-builder: warp-per-point, fp16-hi only.
// ---------------------------------------------------------------------------
__global__ __launch_bounds__(256)
void fused_x_kernel(const float* __restrict__ points1)
{
    __shared__ float tile[32][132];
    const int m0 = blockIdx.x * 32;
    const int b  = m0 >> 13;
    const int n0 = m0 & 8191;
    const int tx = threadIdx.x & 31;
    const int ty = threadIdx.x >> 5;

    const float* p1 = points1 + (size_t)b * C1 * NPTS;
#pragma unroll
    for (int k = 0; k < 16; k++) {
        const int ch = ty + k * 8;
        tile[tx][ch] = p1[(size_t)ch * NPTS + n0 + tx];
    }
    __syncthreads();

    const int w = threadIdx.x >> 5, lane = threadIdx.x & 31;
    const float* p2t = d_P2T + (size_t)b * SPTS * C0;

#pragma unroll
    for (int k = 0; k < 4; k++) {
        const int pt = w * 4 + k;
        const int m  = m0 + pt;
        const uint4 nn = d_nn[m];
        const int i0 = nn.x & 0xFFFF, i1 = nn.x >> 16, i2 = nn.y;
        const float w0 = __uint_as_float(nn.z);
        const float w1 = __uint_as_float(nn.w);
        const float w2 = 1.f - w0 - w1;

        const float4* r0 = (const float4*)(p2t + (size_t)i0 * C0);
        const float4* r1 = (const float4*)(p2t + (size_t)i1 * C0);
        const float4* r2 = (const float4*)(p2t + (size_t)i2 * C0);

        uint4 H;
        {
            float4 a0 = r0[lane * 2],     c0 = r1[lane * 2],     e0 = r2[lane * 2];
            float4 a1 = r0[lane * 2 + 1], c1 = r1[lane * 2 + 1], e1 = r2[lane * 2 + 1];
            float v0 = fmaf(a0.x, w0, fmaf(c0.x, w1, e0.x * w2));
            float v1 = fmaf(a0.y, w0, fmaf(c0.y, w1, e0.y * w2));
            float v2 = fmaf(a0.z, w0, fmaf(c0.z, w1, e0.z * w2));
            float v3 = fmaf(a0.w, w0, fmaf(c0.w, w1, e0.w * w2));
            float v4 = fmaf(a1.x, w0, fmaf(c1.x, w1, e1.x * w2));
            float v5 = fmaf(a1.y, w0, fmaf(c1.y, w1, e1.y * w2));
            float v6 = fmaf(a1.z, w0, fmaf(c1.z, w1, e1.z * w2));
            float v7 = fmaf(a1.w, w0, fmaf(c1.w, w1, e1.w * w2));
            H.x = pack_h2(v0, v1);
            H.y = pack_h2(v2, v3);
            H.z = pack_h2(v4, v5);
            H.w = pack_h2(v6, v7);
        }
        __half* xh = d_Xh + (size_t)m * CIN;
        *(uint4*)(xh + lane * 8) = H;

        {
            float4 v = *(const float4*)(&tile[pt][lane * 4]);
            uint2 h;
            h.x = pack_h2(v.x, v.y);
            h.y = pack_h2(v.z, v.w);
            *(uint2*)(xh + C0 + lane * 4) = h;
        }
    }
}

// ---------------------------------------------------------------------------
// GEMM0 (mma.sync fp16, single-term): Y[m][o] = X[m][:].W0[o][:], K=384.
// CTA: 128 ch x 128 pts. BK=64, 2-stage cp.async (32KB/stage, 2 CTAs/SM).
// Epilogue: fp32 stats (exact) + fp16 Y store (halved traffic).
// ---------------------------------------------------------------------------
#define G0_STG  32768
#define G0_SMEM 69632   // max(2*G0_STG, 128*132*4 epilogue transpose)

__global__ __launch_bounds__(256, 2)
void gemm0_kernel()
{
    extern __shared__ char smem[];
    const uint32_t sb = smem_u32(smem);
    const int tid = threadIdx.x;
    const int m0 = blockIdx.x * 128;
    const int ct = blockIdx.y;
    const int w = tid >> 5, lane = tid & 31;
    const int wm = w >> 2, wn = w & 3;
    const int lrow = lane & 15, lch = lane >> 4;

    float acc[4][4][4];
#pragma unroll
    for (int i = 0; i < 4; i++)
#pragma unroll
        for (int j = 0; j < 4; j++)
#pragma unroll
            for (int q = 0; q < 4; q++) acc[i][j][q] = 0.f;

    auto load_chunk = [&](int c, int stage) {
        const int k0 = c * 64;
        const uint32_t stg = sb + stage * G0_STG;
#pragma unroll
        for (int it = 0; it < 8; it++) {
            int u = it * 256 + tid;
            int arr = u >> 10;                      // 0=W0h 1=Xh
            int v = u & 1023;
            int row = v >> 3, un = v & 7;
            uint32_t dst = stg + arr * 16384 + SW128(row * 128 + un * 16);
            const __half* src;
            if (arr == 0) src = d_W0h + (size_t)(ct * 128 + row) * CIN + k0 + un * 8;
            else          src = d_Xh  + (size_t)(m0 + row) * CIN + k0 + un * 8;
            cp_async16(dst, src);
        }
        CP_COMMIT();
    };

    load_chunk(0, 0);
    load_chunk(1, 1);

    for (int c = 0; c < 6; c++) {
        if (c < 5) asm volatile("cp.async.wait_group 1;" ::: "memory");
        else       asm volatile("cp.async.wait_group 0;" ::: "memory");
        __syncthreads();

        const uint32_t stg = sb + (c & 1) * G0_STG;
        const uint32_t aH = stg, bHb = stg + 16384;
#pragma unroll
        for (int kk = 0; kk < 4; kk++) {
            uint32_t Ah[4][4], Bh[4][2];
#pragma unroll
            for (int mf = 0; mf < 4; mf++) {
                uint32_t off = SW128((wm * 64 + mf * 16 + lrow) * 128 + (kk * 2 + lch) * 16);
                ldsm_x4(Ah[mf], aH + off);
            }
#pragma unroll
            for (int p = 0; p < 2; p++) {
                uint32_t off = SW128((wn * 32 + p * 16 + lrow) * 128 + (kk * 2 + lch) * 16);
                uint32_t r[4];
                ldsm_x4(r, bHb + off);
                Bh[2 * p][0] = r[0]; Bh[2 * p][1] = r[2];
                Bh[2 * p + 1][0] = r[1]; Bh[2 * p + 1][1] = r[3];
            }
#pragma unroll
            for (int mf = 0; mf < 4; mf++)
#pragma unroll
                for (int nf = 0; nf < 4; nf++)
                    mma_f16(acc[mf][nf], Ah[mf], Bh[nf]);
        }
        __syncthreads();
        if (c + 2 < 6) load_chunk(c + 2, c & 1);
    }

    // ---- fused BN0 stats via quad-shuffle + atomics (fp32, exact) ----
    float ssum[4][2] = {}, ssq[4][2] = {};
#pragma unroll
    for (int mf = 0; mf < 4; mf++)
#pragma unroll
        for (int nf = 0; nf < 4; nf++) {
            const float* a = acc[mf][nf];
            ssum[mf][0] += a[0] + a[1];
            ssum[mf][1] += a[2] + a[3];
            ssq[mf][0]  += a[0] * a[0] + a[1] * a[1];
            ssq[mf][1]  += a[2] * a[2] + a[3] * a[3];
        }
#pragma unroll
    for (int mf = 0; mf < 4; mf++)
#pragma unroll
        for (int h = 0; h < 2; h++) {
            float s = ssum[mf][h], q = ssq[mf][h];
            s += __shfl_xor_sync(0xffffffffu, s, 1);
            s += __shfl_xor_sync(0xffffffffu, s, 2);
            q += __shfl_xor_sync(0xffffffffu, q, 1);
            q += __shfl_xor_sync(0xffffffffu, q, 2);
            if ((lane & 3) == 0) {
                int ch = ct * 128 + wm * 64 + mf * 16 + (lane >> 2) + h * 8;
                atomicAdd(&d_stats[ch], s);
                atomicAdd(&d_stats[256 + ch], q);
            }
        }

    // ---- smem transpose -> coalesced fp16 d_Y [m][256] ----
    float* st = (float*)smem;
#pragma unroll
    for (int mf = 0; mf < 4; mf++)
#pragma unroll
        for (int nf = 0; nf < 4; nf++) {
            int ch = wm * 64 + mf * 16 + (lane >> 2);
            int pt = wn * 32 + nf * 8 + (lane & 3) * 2;
            st[pt * 132 + ch]           = acc[mf][nf][0];
            st[(pt + 1) * 132 + ch]     = acc[mf][nf][1];
            st[pt * 132 + ch + 8]       = acc[mf][nf][2];
            st[(pt + 1) * 132 + ch + 8] = acc[mf][nf][3];
        }
    __syncthreads();
    {
        const int row = tid >> 1, half = tid & 1;
        __half* dst = d_Y + (size_t)(m0 + row) * C0 + ct * 128 + half * 64;
        const float* sp = st + row * 132 + half * 64;
#pragma unroll
        for (int j = 0; j < 8; j++) {
            float4 a = *(const float4*)(sp + j * 8);
            float4 b = *(const float4*)(sp + j * 8 + 4);
            uint4 o;
            o.x = pack_h2(a.x, a.y);
            o.y = pack_h2(a.z, a.w);
            o.z = pack_h2(b.x, b.y);
            o.w = pack_h2(b.z, b.w);
            *(uint4*)(dst + j * 8) = o;
        }
    }
}

// ---------------------------------------------------------------------------
// finalize BN constants (conv biases cancel under training-mode BN)
// ---------------------------------------------------------------------------
template<int LAYER>
__global__ void finalize_kernel(const float* __restrict__ g, const float* __restrict__ be)
{
    const int c  = threadIdx.x;
    const int o  = LAYER ? 512 : 0;
    const int cc = LAYER ? C1 : C0;
    const float mean = d_stats[o + c] * (1.f / MTOT);
    const float var  = d_stats[o + cc + c] * (1.f / MTOT) - mean * mean;
    const float sc   = g[c] * rsqrtf(var + 1e-5f);
    d_aff[o + c]      = sc;
    d_aff[o + cc + c] = be[c] - mean * sc;
}

// ---------------------------------------------------------------------------
// GEMM1: Z = relu(aff0(Y)) . W1^T, K=256, single-term fp16, fp16 Y in / Z out.
// ---------------------------------------------------------------------------
#define G1_STG  32768
#define G1_SMEM (2048 + 2 * G1_STG)

__global__ __launch_bounds__(256, 2)
void gemm1_kernel()
{
    extern __shared__ char smem[];
    const uint32_t sb = smem_u32(smem);
    float* s_aff = (float*)smem;                 // 512 floats
    const int tid = threadIdx.x;
    const int m0 = blockIdx.x * 128;
    const int w = tid >> 5, lane = tid & 31;
    const int wm = w >> 2, wn = w & 3;
    const int lrow = lane & 15, lch = lane >> 4;

    for (int i = tid; i < 512; i += 256) s_aff[i] = d_aff[i];
    __syncthreads();

    auto load_chunk = [&](int c, int stage) {
        const int k0 = c * 64;
        const uint32_t stg = sb + 2048 + stage * G1_STG;
#pragma unroll
        for (int it = 0; it < 4; it++) {
            int u = it * 256 + tid;
            int row = u >> 3, un = u & 7;
            uint32_t dst = stg + SW128(row * 128 + un * 16);
            const __half* src = d_W1h + (size_t)row * C0 + k0 + un * 8;
            cp_async16(dst, src);
        }
        CP_COMMIT();
        // B: fp16 Y -> affine+relu -> fp16, stored swizzled
        const uint32_t bB = stg + 16384;
        const int yrow = tid >> 1;
        const int koff = (tid & 1) * 32;
        const __half* yp = d_Y + (size_t)(m0 + yrow) * C0 + c * 64 + koff;
        const float* af  = s_aff + c * 64 + koff;
        const float* af2 = s_aff + 256 + c * 64 + koff;
        uint32_t hi[16];
#pragma unroll
        for (int i = 0; i < 32; i += 8) {
            uint4 raw = *(const uint4*)(yp + i);
            float2 f0 = __half22float2(*reinterpret_cast<__half2*>(&raw.x));
            float2 f1 = __half22float2(*reinterpret_cast<__half2*>(&raw.y));
            float2 f2 = __half22float2(*reinterpret_cast<__half2*>(&raw.z));
            float2 f3 = __half22float2(*reinterpret_cast<__half2*>(&raw.w));
            float x0 = fmaxf(fmaf(f0.x, af[i],     af2[i]),     0.f);
            float x1 = fmaxf(fmaf(f0.y, af[i + 1], af2[i + 1]), 0.f);
            float x2 = fmaxf(fmaf(f1.x, af[i + 2], af2[i + 2]), 0.f);
            float x3 = fmaxf(fmaf(f1.y, af[i + 3], af2[i + 3]), 0.f);
            float x4 = fmaxf(fmaf(f2.x, af[i + 4], af2[i + 4]), 0.f);
            float x5 = fmaxf(fmaf(f2.y, af[i + 5], af2[i + 5]), 0.f);
            float x6 = fmaxf(fmaf(f3.x, af[i + 6], af2[i + 6]), 0.f);
            float x7 = fmaxf(fmaf(f3.y, af[i + 7], af2[i + 7]), 0.f);
            hi[(i >> 1) + 0] = pack_h2(x0, x1);
            hi[(i >> 1) + 1] = pack_h2(x2, x3);
            hi[(i >> 1) + 2] = pack_h2(x4, x5);
            hi[(i >> 1) + 3] = pack_h2(x6, x7);
        }
#pragma unroll
        for (int uu = 0; uu < 4; uu++) {
            uint32_t off = SW128(yrow * 128 + ((tid & 1) * 4 + uu) * 16);
            asm volatile("st.shared.v4.b32 [%0], {%1,%2,%3,%4};"
                         :: "r"(bB + off), "r"(hi[uu * 4]), "r"(hi[uu * 4 + 1]),
                            "r"(hi[uu * 4 + 2]), "r"(hi[uu * 4 + 3]) : "memory");
        }
    };

    float acc[4][4][4];
#pragma unroll
    for (int i = 0; i < 4; i++)
#pragma unroll
        for (int j = 0; j < 4; j++)
#pragma unroll
            for (int q = 0; q < 4; q++) acc[i][j][q] = 0.f;

    load_chunk(0, 0);
    load_chunk(1, 1);

    for (int c = 0; c < 4; c++) {
        if (c < 3) asm volatile("cp.async.wait_group 1;" ::: "memory");
        else       asm volatile("cp.async.wait_group 0;" ::: "memory");
        __syncthreads();

        const uint32_t stg = sb + 2048 + (c & 1) * G1_STG;
        const uint32_t aH = stg, bHb = stg + 16384;
#pragma unroll
        for (int kk = 0; kk < 4; kk++) {
            uint32_t Ah[4][4], Bh[4][2];
#pragma unroll
            for (int mf = 0; mf < 4; mf++) {
                uint32_t off = SW128((wm * 64 + mf * 16 + lrow) * 128 + (kk * 2 + lch) * 16);
                ldsm_x4(Ah[mf], aH + off);
            }
#pragma unroll
            for (int p = 0; p < 2; p++) {
                uint32_t off = SW128((wn * 32 + p * 16 + lrow) * 128 + (kk * 2 + lch) * 16);
                uint32_t r[4];
                ldsm_x4(r, bHb + off);
                Bh[2 * p][0] = r[0]; Bh[2 * p][1] = r[2];
                Bh[2 * p + 1][0] = r[1]; Bh[2 * p + 1][1] = r[3];
            }
#pragma unroll
            for (int mf = 0; mf < 4; mf++)
#pragma unroll
                for (int nf = 0; nf < 4; nf++)
                    mma_f16(acc[mf][nf], Ah[mf], Bh[nf]);
        }
        __syncthreads();
        if (c + 2 < 4) load_chunk(c + 2, c & 1);
    }

    // ---- fused BN1 stats (fp32, exact) ----
    float ssum[4][2] = {}, ssq[4][2] = {};
#pragma unroll
    for (int mf = 0; mf < 4; mf++)
#pragma unroll
        for (int nf = 0; nf < 4; nf++) {
            const float* a = acc[mf][nf];
            ssum[mf][0] += a[0] + a[1];
            ssum[mf][1] += a[2] + a[3];
            ssq[mf][0]  += a[0] * a[0] + a[1] * a[1];
            ssq[mf][1]  += a[2] * a[2] + a[3] * a[3];
        }
#pragma unroll
    for (int mf = 0; mf < 4; mf++)
#pragma unroll
        for (int h = 0; h < 2; h++) {
            float s = ssum[mf][h], q = ssq[mf][h];
            s += __shfl_xor_sync(0xffffffffu, s, 1);
            s += __shfl_xor_sync(0xffffffffu, s, 2);
            q += __shfl_xor_sync(0xffffffffu, q, 1);
            q += __shfl_xor_sync(0xffffffffu, q, 2);
            if ((lane & 3) == 0) {
                int ch = wm * 64 + mf * 16 + (lane >> 2) + h * 8;
                atomicAdd(&d_stats[512 + ch], s);
                atomicAdd(&d_stats[640 + ch], q);
            }
        }

    // ---- store fp16 d_Z [c][m] (pt-pairs => 4B half2 stores) ----
#pragma unroll
    for (int mf = 0; mf < 4; mf++)
#pragma unroll
        for (int nf = 0; nf < 4; nf++) {
            int ch = wm * 64 + mf * 16 + (lane >> 2);
            int pt = m0 + wn * 32 + nf * 8 + (lane & 3) * 2;
            *(uint32_t*)(d_Z + (size_t)ch * MTOT + pt) =
                pack_h2(acc[mf][nf][0], acc[mf][nf][1]);
            *(uint32_t*)(d_Z + (size_t)(ch + 8) * MTOT + pt) =
                pack_h2(acc[mf][nf][2], acc[mf][nf][3]);
        }
}

// ---------------------------------------------------------------------------
// BN1 affine + ReLU + output [B,128,N]; fp16 Z in, fp32 out. 8 elems/thread.
// ---------------------------------------------------------------------------
__global__ __launch_bounds__(256)
void output_kernel(float* __restrict__ out)
{
    const int i = blockIdx.x * 256 + threadIdx.x;
    const int base = i * 8;
    const int o = base >> 16;
    const int m = base & 65535;
    const int b = m >> 13;
    const int n = m & 8191;
    uint4 raw = *(const uint4*)(d_Z + (size_t)o * MTOT + m);
    const float sc = d_aff[512 + o];
    const float sh = d_aff[640 + o];
    float2 f0 = __half22float2(*reinterpret_cast<__half2*>(&raw.x));
    float2 f1 = __half22float2(*reinterpret_cast<__half2*>(&raw.y));
    float2 f2 = __half22float2(*reinterpret_cast<__half2*>(&raw.z));
    float2 f3 = __half22float2(*reinterpret_cast<__half2*>(&raw.w));
    float4 v0, v1;
    v0.x = fmaxf(fmaf(f0.x, sc, sh), 0.f);
    v0.y = fmaxf(fmaf(f0.y, sc, sh), 0.f);
    v0.z = fmaxf(fmaf(f1.x, sc, sh), 0.f);
    v0.w = fmaxf(fmaf(f1.y, sc, sh), 0.f);
    v1.x = fmaxf(fmaf(f2.x, sc, sh), 0.f);
    v1.y = fmaxf(fmaf(f2.y, sc, sh), 0.f);
    v1.z = fmaxf(fmaf(f3.x, sc, sh), 0.f);
    v1.w = fmaxf(fmaf(f3.y, sc, sh), 0.f);
    float* dst = out + ((size_t)b * C1 + o) * NPTS + n;
    *(float4*)(dst)     = v0;
    *(float4*)(dst + 4) = v1;
}

// ---------------------------------------------------------------------------
extern "C" void kernel_launch(void* const* d_in, const int* in_sizes, int n_in,
                              void* d_out, int out_size)
{
    const float* xyz1    = (const float*)d_in[0];
    const float* xyz2    = (const float*)d_in[1];
    const float* points1 = (const float*)d_in[2];
    const float* points2 = (const float*)d_in[3];
    const float* w0      = (const float*)d_in[4];
    const float* g0      = (const float*)d_in[6];
    const float* be0     = (const float*)d_in[7];
    const float* w1      = (const float*)d_in[8];
    const float* g1      = (const float*)d_in[10];
    const float* be1     = (const float*)d_in[11];
    float* out = (float*)d_out;

    cudaFuncSetAttribute(gemm0_kernel, cudaFuncAttributeMaxDynamicSharedMemorySize, G0_SMEM);
    cudaFuncSetAttribute(gemm1_kernel, cudaFuncAttributeMaxDynamicSharedMemorySize, G1_SMEM);

    prep_kernel<<<640, 256>>>(xyz1, xyz2, points2);                      // (1)
    split_w_kernel<<<(C0 * CIN + C1 * C0 + 255) / 256, 256>>>(w0, w1);   // (2)
    fused_x_kernel<<<MTOT / 32, 256>>>(points1);                         // (3)

    gemm0_kernel<<<dim3(MTOT / 128, 2), 256, G0_SMEM>>>();               // (4) <- profiled
    finalize_kernel<0><<<1, C0>>>(g0, be0);                              // (5)

    gemm1_kernel<<<MTOT / 128, 256, G1_SMEM>>>();                        // (6)
    finalize_kernel<1><<<1, C1>>>(g1, be1);                              // (7)

    output_kernel<<<(C1 * MTOT / 8) / 256, 256>>>(out);                  // (8)
}